// round 12
// baseline (speedup 1.0000x reference)
#include <cuda_runtime.h>
#include <cuda_fp16.h>
#include <math.h>
#include <stdint.h>

#define SEQ   4096
#define DIM   2048
#define NH    32
#define NKV   8
#define HD    64
#define ESTQ  64
#define VSZ   300
#define SSZ   800
#define NKEY  1100
#define NKEYP 1152
#define SCALE 0.125f
#define PADKEY 0x3FFFFFFF
#define KVW   1024

// ---------------- device scratch ----------------
__device__ float g_q[SEQ * DIM];
__device__ float g_q64[ESTQ * DIM];
__device__ float g_q64p[8 * ESTQ * DIM];
__device__ float g_kv[SEQ * KVW];
__device__ float g_probs[NH * ESTQ * SEQ];
__device__ float g_vert[NH * SEQ];
__device__ float g_diag[NH * SEQ];
__device__ int   g_keys[NH * NKEYP];
__device__ float g_ksp[NH * NKEYP * HD];
__device__ float g_vsp[NH * NKEYP * HD];
__device__ __half g_xh[SEQ * DIM];      // x hi (fp16)
__device__ __half g_xl[SEQ * DIM];      // x lo (fp16)
__device__ __half g_atth[SEQ * DIM];    // attention output fp16
__device__ __half g_wqt[DIM * DIM];     // wq transposed [n][k] fp16
__device__ __half g_wot[DIM * DIM];     // wo transposed [n][k] fp16
__device__ __half g_wkvtH[KVW * DIM];   // [wk|wv] transposed [n][k] hi fp16
__device__ __half g_wkvtL[KVW * DIM];   // [wk|wv] transposed [n][k] lo fp16

// ---------------- helpers ------------------------------------------------
__device__ __forceinline__ uint32_t f2tf32(float f) {
    uint32_t r;
    asm("cvt.rna.tf32.f32 %0, %1;" : "=r"(r) : "f"(f));
    return r;
}

__device__ __forceinline__ void mma_tf32(float c[4], const uint32_t a[4],
                                         uint32_t b0, uint32_t b1) {
    asm volatile(
        "mma.sync.aligned.m16n8k8.row.col.f32.tf32.tf32.f32 "
        "{%0,%1,%2,%3}, {%4,%5,%6,%7}, {%8,%9}, {%0,%1,%2,%3};\n"
        : "+f"(c[0]), "+f"(c[1]), "+f"(c[2]), "+f"(c[3])
        : "r"(a[0]), "r"(a[1]), "r"(a[2]), "r"(a[3]), "r"(b0), "r"(b1));
}

__device__ __forceinline__ void mma_f16(float c[4], const uint32_t a[4],
                                        uint32_t b0, uint32_t b1) {
    asm volatile(
        "mma.sync.aligned.m16n8k16.row.col.f32.f16.f16.f32 "
        "{%0,%1,%2,%3}, {%4,%5,%6,%7}, {%8,%9}, {%0,%1,%2,%3};\n"
        : "+f"(c[0]), "+f"(c[1]), "+f"(c[2]), "+f"(c[3])
        : "r"(a[0]), "r"(a[1]), "r"(a[2]), "r"(a[3]), "r"(b0), "r"(b1));
}

__device__ __forceinline__ uint32_t smem_u32(const void* p) {
    uint32_t a;
    asm("{ .reg .u64 t; cvta.to.shared.u64 t, %1; cvt.u32.u64 %0, t; }" : "=r"(a) : "l"(p));
    return a;
}

// ================= fp16 k16 GEMM with cp.async double buffering ===========
#define AF_ST 20

__global__ __launch_bounds__(256) void gemm_f16(const __half* __restrict__ A,
                                                const __half* __restrict__ Bt,
                                                float* __restrict__ C,
                                                int M, int N, int K) {
    __shared__ uint32_t As[2][128 * AF_ST];
    __shared__ uint32_t Bs[2][128 * AF_ST];
    int tid = threadIdx.x;
    int lane = tid & 31;
    int warp = tid >> 5;
    int wm = warp & 3;
    int wn = warp >> 2;
    int row0 = blockIdx.y * 128;
    int col0 = blockIdx.x * 128;
    int lr = lane >> 2;
    int lc = lane & 3;

    uint32_t asb[2], bsb[2];
    asb[0] = smem_u32(&As[0][0]);
    asb[1] = smem_u32(&As[1][0]);
    bsb[0] = smem_u32(&Bs[0][0]);
    bsb[1] = smem_u32(&Bs[1][0]);

    float acc[2][8][4];
#pragma unroll
    for (int mi = 0; mi < 2; mi++)
#pragma unroll
        for (int nj = 0; nj < 8; nj++)
#pragma unroll
            for (int e = 0; e < 4; e++) acc[mi][nj][e] = 0.f;

    int r_ld = tid >> 2;
    int j_ld = tid & 3;

    {
#pragma unroll
        for (int i = 0; i < 2; i++) {
            int r = r_ld + i * 64;
            uint32_t da = asb[0] + (uint32_t)(r * AF_ST + j_ld * 4) * 4;
            const __half* sa = A + (size_t)(row0 + r) * K + j_ld * 8;
            asm volatile("cp.async.ca.shared.global [%0], [%1], 16;" :: "r"(da), "l"(sa));
            uint32_t db = bsb[0] + (uint32_t)(r * AF_ST + j_ld * 4) * 4;
            const __half* sb = Bt + (size_t)(col0 + r) * K + j_ld * 8;
            asm volatile("cp.async.ca.shared.global [%0], [%1], 16;" :: "r"(db), "l"(sb));
        }
        asm volatile("cp.async.commit_group;");
    }

    int KC = K >> 5;
    for (int c = 0; c < KC; c++) {
        int buf = c & 1;
        if (c + 1 < KC) {
            int k0 = (c + 1) << 5;
            int nb = buf ^ 1;
#pragma unroll
            for (int i = 0; i < 2; i++) {
                int r = r_ld + i * 64;
                uint32_t da = asb[nb] + (uint32_t)(r * AF_ST + j_ld * 4) * 4;
                const __half* sa = A + (size_t)(row0 + r) * K + k0 + j_ld * 8;
                asm volatile("cp.async.ca.shared.global [%0], [%1], 16;" :: "r"(da), "l"(sa));
                uint32_t db = bsb[nb] + (uint32_t)(r * AF_ST + j_ld * 4) * 4;
                const __half* sb = Bt + (size_t)(col0 + r) * K + k0 + j_ld * 8;
                asm volatile("cp.async.ca.shared.global [%0], [%1], 16;" :: "r"(db), "l"(sb));
            }
            asm volatile("cp.async.commit_group;");
            asm volatile("cp.async.wait_group 1;");
        } else {
            asm volatile("cp.async.wait_group 0;");
        }
        __syncthreads();

        const uint32_t* Ab = As[buf];
        const uint32_t* Bb = Bs[buf];
#pragma unroll
        for (int ks = 0; ks < 2; ks++) {
            int kb = ks * 8;
            uint32_t a[2][4];
#pragma unroll
            for (int mi = 0; mi < 2; mi++) {
                int ra = wm * 32 + mi * 16 + lr;
                a[mi][0] = Ab[ra * AF_ST + kb + lc];
                a[mi][1] = Ab[(ra + 8) * AF_ST + kb + lc];
                a[mi][2] = Ab[ra * AF_ST + kb + lc + 4];
                a[mi][3] = Ab[(ra + 8) * AF_ST + kb + lc + 4];
            }
#pragma unroll
            for (int nj = 0; nj < 8; nj++) {
                int col = wn * 64 + nj * 8 + lr;
                uint32_t b0 = Bb[col * AF_ST + kb + lc];
                uint32_t b1 = Bb[col * AF_ST + kb + lc + 4];
                mma_f16(acc[0][nj], a[0], b0, b1);
                mma_f16(acc[1][nj], a[1], b0, b1);
            }
        }
        __syncthreads();
    }

#pragma unroll
    for (int mi = 0; mi < 2; mi++) {
        int row = row0 + wm * 32 + mi * 16 + lr;
#pragma unroll
        for (int nj = 0; nj < 8; nj++) {
            int col = col0 + wn * 64 + nj * 8 + 2 * lc;
            float* cp0 = C + (size_t)row * N + col;
            cp0[0] = acc[mi][nj][0];
            cp0[1] = acc[mi][nj][1];
            float* cp1 = C + (size_t)(row + 8) * N + col;
            cp1[0] = acc[mi][nj][2];
            cp1[1] = acc[mi][nj][3];
        }
    }
}

// ===== fp16 hi/lo 3-term GEMM (kv projection): ~fp32 accuracy, half the work =====
#define STGW (4 * 128 * AF_ST)   // AH AL BH BL per stage (words)

__global__ __launch_bounds__(256) void gemm_f16x3(const __half* __restrict__ AH,
                                                  const __half* __restrict__ AL,
                                                  const __half* __restrict__ BH,
                                                  const __half* __restrict__ BL,
                                                  float* __restrict__ C,
                                                  int M, int N, int K) {
    extern __shared__ uint32_t sm[];
    uint32_t base = smem_u32(sm);
    int tid = threadIdx.x;
    int lane = tid & 31;
    int warp = tid >> 5;
    int wm = warp & 3;
    int wn = warp >> 2;
    int row0 = blockIdx.y * 128;
    int col0 = blockIdx.x * 128;
    int lr = lane >> 2;
    int lc = lane & 3;

    float acc[2][8][4];
#pragma unroll
    for (int mi = 0; mi < 2; mi++)
#pragma unroll
        for (int nj = 0; nj < 8; nj++)
#pragma unroll
            for (int e = 0; e < 4; e++) acc[mi][nj][e] = 0.f;

    int r_ld = tid >> 2;
    int j_ld = tid & 3;

    auto issue = [&](int stage, int k0) {
        uint32_t sb = base + (uint32_t)stage * STGW * 4;
#pragma unroll
        for (int i = 0; i < 2; i++) {
            int r = r_ld + i * 64;
            uint32_t off = (uint32_t)(r * AF_ST + j_ld * 4) * 4;
            const __half* pa = AH + (size_t)(row0 + r) * K + k0 + j_ld * 8;
            asm volatile("cp.async.ca.shared.global [%0], [%1], 16;" :: "r"(sb + off), "l"(pa));
            const __half* pl = AL + (size_t)(row0 + r) * K + k0 + j_ld * 8;
            asm volatile("cp.async.ca.shared.global [%0], [%1], 16;"
                         :: "r"(sb + (uint32_t)(128 * AF_ST) * 4 + off), "l"(pl));
            const __half* pb = BH + (size_t)(col0 + r) * K + k0 + j_ld * 8;
            asm volatile("cp.async.ca.shared.global [%0], [%1], 16;"
                         :: "r"(sb + (uint32_t)(2 * 128 * AF_ST) * 4 + off), "l"(pb));
            const __half* pc = BL + (size_t)(col0 + r) * K + k0 + j_ld * 8;
            asm volatile("cp.async.ca.shared.global [%0], [%1], 16;"
                         :: "r"(sb + (uint32_t)(3 * 128 * AF_ST) * 4 + off), "l"(pc));
        }
        asm volatile("cp.async.commit_group;");
    };

    issue(0, 0);

    int KC = K >> 5;
    for (int c = 0; c < KC; c++) {
        int buf = c & 1;
        if (c + 1 < KC) {
            issue(buf ^ 1, (c + 1) << 5);
            asm volatile("cp.async.wait_group 1;");
        } else {
            asm volatile("cp.async.wait_group 0;");
        }
        __syncthreads();

        const uint32_t* AsH = sm + (size_t)buf * STGW;
        const uint32_t* AsL = AsH + 128 * AF_ST;
        const uint32_t* BsH = AsH + 2 * 128 * AF_ST;
        const uint32_t* BsL = AsH + 3 * 128 * AF_ST;
#pragma unroll
        for (int ks = 0; ks < 2; ks++) {
            int kb = ks * 8;
            uint32_t aH[2][4], aL[2][4];
#pragma unroll
            for (int mi = 0; mi < 2; mi++) {
                int ra = wm * 32 + mi * 16 + lr;
                aH[mi][0] = AsH[ra * AF_ST + kb + lc];
                aH[mi][1] = AsH[(ra + 8) * AF_ST + kb + lc];
                aH[mi][2] = AsH[ra * AF_ST + kb + lc + 4];
                aH[mi][3] = AsH[(ra + 8) * AF_ST + kb + lc + 4];
                aL[mi][0] = AsL[ra * AF_ST + kb + lc];
                aL[mi][1] = AsL[(ra + 8) * AF_ST + kb + lc];
                aL[mi][2] = AsL[ra * AF_ST + kb + lc + 4];
                aL[mi][3] = AsL[(ra + 8) * AF_ST + kb + lc + 4];
            }
#pragma unroll
            for (int nj = 0; nj < 8; nj++) {
                int col = wn * 64 + nj * 8 + lr;
                uint32_t b0h = BsH[col * AF_ST + kb + lc];
                uint32_t b1h = BsH[col * AF_ST + kb + lc + 4];
                uint32_t b0l = BsL[col * AF_ST + kb + lc];
                uint32_t b1l = BsL[col * AF_ST + kb + lc + 4];
#pragma unroll
                for (int mi = 0; mi < 2; mi++) {
                    mma_f16(acc[mi][nj], aH[mi], b0h, b1h);
                    mma_f16(acc[mi][nj], aH[mi], b0l, b1l);
                    mma_f16(acc[mi][nj], aL[mi], b0h, b1h);
                }
            }
        }
        __syncthreads();
    }

#pragma unroll
    for (int mi = 0; mi < 2; mi++) {
        int row = row0 + wm * 32 + mi * 16 + lr;
#pragma unroll
        for (int nj = 0; nj < 8; nj++) {
            int col = col0 + wn * 64 + nj * 8 + 2 * lc;
            float* cp0 = C + (size_t)row * N + col;
            cp0[0] = acc[mi][nj][0];
            cp0[1] = acc[mi][nj][1];
            float* cp1 = C + (size_t)(row + 8) * N + col;
            cp1[0] = acc[mi][nj][2];
            cp1[1] = acc[mi][nj][3];
        }
    }
}

// ---------------- prep kernels ---------------------------------------------
// fp32 -> fp16 hi/lo split (row-major)
__global__ void split_h2(const float* __restrict__ a, __half* __restrict__ h,
                         __half* __restrict__ l, int n4) {
    int i = blockIdx.x * 256 + threadIdx.x;
    if (i >= n4) return;
    float4 v = ((const float4*)a)[i];
    __half hx = __float2half_rn(v.x), hy = __float2half_rn(v.y);
    __half hz = __float2half_rn(v.z), hw = __float2half_rn(v.w);
    __half2 h0 = __halves2half2(hx, hy);
    __half2 h1 = __halves2half2(hz, hw);
    ((uint2*)h)[i] = make_uint2(*(uint32_t*)&h0, *(uint32_t*)&h1);
    __half2 l0 = __halves2half2(__float2half_rn(v.x - __half2float(hx)),
                                __float2half_rn(v.y - __half2float(hy)));
    __half2 l1 = __halves2half2(__float2half_rn(v.z - __half2float(hz)),
                                __float2half_rn(v.w - __half2float(hw)));
    ((uint2*)l)[i] = make_uint2(*(uint32_t*)&l0, *(uint32_t*)&l1);
}

// concat wk|wv, transpose [k][1024] -> [n][k], split to fp16 hi/lo
__global__ void concat_transp_split(const float* __restrict__ wk, const float* __restrict__ wv,
                                    __half* __restrict__ th, __half* __restrict__ tl) {
    __shared__ float tile[32][33];
    int bx = blockIdx.x * 32;  // n in [0,1024)
    int by = blockIdx.y * 32;  // k
    int tx = threadIdx.x, ty = threadIdx.y;  // (32,8)
    for (int i = 0; i < 32; i += 8) {
        int col = bx + tx;
        float v = (col < 512) ? wk[(size_t)(by + ty + i) * 512 + col]
                              : wv[(size_t)(by + ty + i) * 512 + (col - 512)];
        tile[ty + i][tx] = v;
    }
    __syncthreads();
    for (int i = 0; i < 32; i += 8) {
        float v = tile[tx][ty + i];
        __half h = __float2half_rn(v);
        th[(size_t)(bx + ty + i) * DIM + by + tx] = h;
        tl[(size_t)(bx + ty + i) * DIM + by + tx] = __float2half_rn(v - __half2float(h));
    }
}

__global__ void transp_half(const float* __restrict__ w, __half* __restrict__ t) {
    __shared__ float tile[32][33];
    int bx = blockIdx.x * 32;
    int by = blockIdx.y * 32;
    int tx = threadIdx.x, ty = threadIdx.y;
    for (int i = 0; i < 32; i += 8)
        tile[ty + i][tx] = w[(size_t)(by + ty + i) * DIM + bx + tx];
    __syncthreads();
    for (int i = 0; i < 32; i += 8)
        t[(size_t)(bx + ty + i) * DIM + by + tx] = __float2half_rn(tile[tx][ty + i]);
}

// ---------------- exact fp32 q rows 0..63: split-K ---------------------------
__global__ __launch_bounds__(128) void qproj_part(const float* __restrict__ x,
                                                  const float* __restrict__ wq,
                                                  float* __restrict__ part) {
    __shared__ float xs[8][256];
    int tid = threadIdx.x;
    int col = blockIdx.x * 128 + tid;
    int r0 = blockIdx.y * 8;
    int k0 = blockIdx.z * 256;
    float acc[8];
#pragma unroll
    for (int rr = 0; rr < 8; rr++) acc[rr] = 0.f;

    for (int i = tid; i < 8 * 256; i += 128) {
        int rr = i >> 8, kk = i & 255;
        xs[rr][kk] = x[(size_t)(r0 + rr) * DIM + k0 + kk];
    }
    __syncthreads();
    for (int kk = 0; kk < 256; kk++) {
        float w = wq[(size_t)(k0 + kk) * DIM + col];
#pragma unroll
        for (int rr = 0; rr < 8; rr++) acc[rr] += xs[rr][kk] * w;
    }
#pragma unroll
    for (int rr = 0; rr < 8; rr++)
        part[(size_t)blockIdx.z * ESTQ * DIM + (size_t)(r0 + rr) * DIM + col] = acc[rr];
}

__global__ void qproj_red(const float* __restrict__ part, float* __restrict__ q64) {
    int idx = blockIdx.x * 256 + threadIdx.x;
    if (idx >= ESTQ * DIM) return;
    float s = 0.f;
#pragma unroll
    for (int ks = 0; ks < 8; ks++) s += part[(size_t)ks * ESTQ * DIM + idx];
    q64[idx] = s;
}

// ---------------- RoPE -------------------------------------------------------
__global__ void rope_kernel(float* t, const float* __restrict__ cosb,
                            const float* __restrict__ sinb, int H, int stride, int total) {
    int idx = blockIdx.x * blockDim.x + threadIdx.x;
    if (idx >= total) return;
    int d2 = idx & 31;
    int h = (idx >> 5) % H;
    int s = idx / (32 * H);
    float c = cosb[s * 32 + d2];
    float sn = sinb[s * 32 + d2];
    float* p = t + (size_t)s * stride + h * 64 + 2 * d2;
    float xr = p[0], xi = p[1];
    p[0] = xr * c - xi * sn;
    p[1] = xr * sn + xi * c;
}

// ---------------- est phase A -----------------------------------------------
__global__ __launch_bounds__(256) void est_score(const float* __restrict__ q64,
                                                 const float* __restrict__ kv,
                                                 float* __restrict__ probs) {
    __shared__ float qs[64][68];
    __shared__ float ksm[64][68];
    int tid = threadIdx.x;
    int h = blockIdx.y;
    int c0 = blockIdx.x * 64;
    int kvh = h >> 2;
    int qi = tid >> 2;
    int kg = tid & 3;

    for (int l = tid; l < 64 * 64; l += 256) {
        int r = l >> 6, d = l & 63;
        qs[r][d] = q64[(size_t)r * DIM + h * HD + d];
        ksm[r][d] = kv[(size_t)(c0 + r) * KVW + kvh * HD + d];
    }
    __syncthreads();

    float s16[16];
#pragma unroll
    for (int j = 0; j < 16; j++) s16[j] = 0.f;
#pragma unroll
    for (int d4 = 0; d4 < 16; d4++) {
        float4 q4 = *(float4*)&qs[qi][d4 * 4];
#pragma unroll
        for (int j = 0; j < 16; j++) {
            float4 k4 = *(float4*)&ksm[kg * 16 + j][d4 * 4];
            s16[j] += q4.x * k4.x + q4.y * k4.y + q4.z * k4.z + q4.w * k4.w;
        }
    }
    float* pr = probs + ((size_t)h * ESTQ + qi) * SEQ + c0 + kg * 16;
#pragma unroll
    for (int j = 0; j < 16; j++) {
        int kk = c0 + kg * 16 + j;
        float val = s16[j] * SCALE;
        if (kk >= SEQ - ESTQ && qi < kk - (SEQ - ESTQ)) val = -INFINITY;
        pr[j] = val;
    }
}

// ---------------- est phase B -------------------------------------------------
__global__ __launch_bounds__(256) void est_norm(float* __restrict__ probs) {
    int qi = blockIdx.x;
    int h = blockIdx.y;
    __shared__ float sc[SEQ];
    __shared__ float red[8];
    int tid = threadIdx.x;
    float* pr = probs + ((size_t)h * ESTQ + qi) * SEQ;

    for (int l = tid; l < SEQ / 4; l += 256)
        *(float4*)&sc[l * 4] = *(const float4*)&pr[l * 4];
    __syncthreads();

    float m = -INFINITY;
    for (int kk = tid; kk < SEQ; kk += 256) m = fmaxf(m, sc[kk]);
#pragma unroll
    for (int o = 16; o; o >>= 1) m = fmaxf(m, __shfl_xor_sync(0xFFFFFFFFu, m, o));
    if ((tid & 31) == 0) red[tid >> 5] = m;
    __syncthreads();
    if (tid == 0) {
        float mm = red[0];
#pragma unroll
        for (int i = 1; i < 8; i++) mm = fmaxf(mm, red[i]);
        red[0] = mm;
    }
    __syncthreads();
    m = red[0];
    __syncthreads();

    float s = 0.f;
    for (int kk = tid; kk < SEQ; kk += 256) {
        float e = expf(sc[kk] - m);
        sc[kk] = e;
        s += e;
    }
#pragma unroll
    for (int o = 16; o; o >>= 1) s += __shfl_xor_sync(0xFFFFFFFFu, s, o);
    if ((tid & 31) == 0) red[tid >> 5] = s;
    __syncthreads();
    if (tid == 0) {
        float ss = 0.f;
#pragma unroll
        for (int i = 0; i < 8; i++) ss += red[i];
        red[0] = ss;
    }
    __syncthreads();
    float inv = 1.f / red[0];
    for (int kk = tid; kk < SEQ; kk += 256) pr[kk] = sc[kk] * inv;
}

// ---------------- vertical / diagonal ------------------------------------------
__global__ void vertical_kernel(const float* __restrict__ probs, float* __restrict__ vert) {
    int idx = blockIdx.x * 256 + threadIdx.x;
    int h = idx >> 12;
    int kk = idx & (SEQ - 1);
    float s = 0.f;
    const float* base = probs + (size_t)h * ESTQ * SEQ + kk;
    for (int i = 0; i < ESTQ; i++) s += base[(size_t)i * SEQ];
    vert[idx] = s;
}

__global__ void diag_kernel(const float* __restrict__ probs, float* __restrict__ dg) {
    int idx = blockIdx.x * 256 + threadIdx.x;
    int h = idx >> 12;
    int jp = idx & (SEQ - 1);
    float s = 0.f;
    const float* base = probs + (size_t)h * ESTQ * SEQ;
    for (int i = 0; i < ESTQ; i++) {
        int col = i + jp - 63;
        if (col >= 0 && col < SEQ) s += base[(size_t)i * SEQ + col];
    }
    dg[idx] = s;
}

// ---------------- merged top-k ---------------------------------------------------
__global__ void topk2_kernel(const float* __restrict__ vert, const float* __restrict__ dg,
                             int* __restrict__ keys) {
    int b = blockIdx.x;
    int mode = b >> 5;
    int h = b & 31;
    const float* vals = mode ? dg : vert;
    int kcount = mode ? SSZ : VSZ;
    __shared__ unsigned long long a[SEQ];
    int tid = threadIdx.x;
    for (int i = tid; i < SEQ; i += 512) {
        unsigned u = __float_as_uint(vals[h * SEQ + i]);
        u = (u & 0x80000000u) ? ~u : (u | 0x80000000u);
        a[i] = ((unsigned long long)(~u) << 32) | (unsigned)i;
    }
    __syncthreads();
    for (int k = 2; k <= SEQ; k <<= 1) {
        for (int j = k >> 1; j > 0; j >>= 1) {
            for (int i = tid; i < SEQ; i += 512) {
                int ixj = i ^ j;
                if (ixj > i) {
                    bool up = ((i & k) == 0);
                    unsigned long long x = a[i], y = a[ixj];
                    if (up ? (x > y) : (x < y)) { a[i] = y; a[ixj] = x; }
                }
            }
            __syncthreads();
        }
    }
    if (mode == 0) {
        for (int t = tid; t < kcount; t += 512)
            keys[h * NKEYP + t] = (int)(a[t] & 0xFFFFFFFFull);
    } else {
        for (int t = tid; t < kcount; t += 512)
            keys[h * NKEYP + VSZ + t] = (SEQ - 1) - (int)(a[t] & 0xFFFFFFFFull);
        for (int t = NKEY + tid; t < NKEYP; t += 512) keys[h * NKEYP + t] = PADKEY;
    }
}

// ---------------- sort keys ascending per head ----------------------------------
__global__ __launch_bounds__(256) void sortkeys_kernel(int* __restrict__ keys) {
    int h = blockIdx.x;
    __shared__ int a[2048];
    int tid = threadIdx.x;
    for (int i = tid; i < 2048; i += 256)
        a[i] = (i < NKEYP) ? keys[h * NKEYP + i] : PADKEY;
    __syncthreads();
    for (int k = 2; k <= 2048; k <<= 1) {
        for (int j = k >> 1; j > 0; j >>= 1) {
            for (int i = tid; i < 2048; i += 256) {
                int ixj = i ^ j;
                if (ixj > i) {
                    bool up = ((i & k) == 0);
                    int x = a[i], y = a[ixj];
                    if (up ? (x > y) : (x < y)) { a[i] = y; a[ixj] = x; }
                }
            }
            __syncthreads();
        }
    }
    for (int i = tid; i < NKEYP; i += 256) keys[h * NKEYP + i] = a[i];
}

// ---------------- gather ----------------------------------------------------------
__global__ void gather_kernel(const float* __restrict__ kv,
                              const int* __restrict__ keys,
                              float* __restrict__ ksp, float* __restrict__ vsp) {
    int j = blockIdx.x;
    int h = j / NKEYP;
    int d = threadIdx.x;
    int key = keys[j];
    int kvh = h >> 2;
    float kvv = 0.f, vvv = 0.f;
    if (key < SEQ) {
        kvv = kv[(size_t)key * KVW + kvh * HD + d];
        vvv = kv[(size_t)key * KVW + 512 + kvh * HD + d];
    }
    ksp[(size_t)j * HD + d] = kvv;
    vsp[(size_t)j * HD + d] = vvv;
}

// ---------------- sparse attention (TC QK 3xTF32 + SIMT PV, fp16 out) ------------
#define QHL_ST 132
#define SP_WORDS (64 * 132 + 32 * 132 + 32 * 68 + 64 * 36 + 32)

__global__ __launch_bounds__(256) void spattn_kernel(const float* __restrict__ q,
                                                     const float* __restrict__ ksp,
                                                     const float* __restrict__ vsp,
                                                     const int* __restrict__ keys,
                                                     __half* __restrict__ attout) {
    extern __shared__ uint32_t smem[];
    uint32_t* qhl = smem;
    uint32_t* khl = qhl + 64 * 132;
    float* vs = (float*)(khl + 32 * 132);
    float* ss = vs + 32 * 68;
    int* kid = (int*)(ss + 64 * 36);

    int qb = blockIdx.x;
    int h = blockIdx.y;
    int tid = threadIdx.x;
    int lane = tid & 31;
    int warp = tid >> 5;
    int lr = lane >> 2;
    int lc = lane & 3;
    int wm = warp & 3;
    int wn = warp >> 2;
    int qp = tid >> 3;
    int g = tid & 7;
    int qi0 = qp, qi1 = qp + 32;
    int sglob0 = qb * 64 + qi0;
    int sglob1 = qb * 64 + qi1;
    int qbmax = qb * 64 + 63;

    for (int l = tid; l < 64 * 16; l += 256) {
        int r = l >> 4, c4 = (l & 15) * 4;
        float4 v = *(const float4*)&q[(size_t)(qb * 64 + r) * DIM + h * HD + c4];
        uint32_t* dh = &qhl[r * QHL_ST + c4];
        uint32_t h0 = f2tf32(v.x), h1 = f2tf32(v.y), h2 = f2tf32(v.z), h3 = f2tf32(v.w);
        dh[0] = h0; dh[1] = h1; dh[2] = h2; dh[3] = h3;
        dh[64] = f2tf32(v.x - __uint_as_float(h0));
        dh[65] = f2tf32(v.y - __uint_as_float(h1));
        dh[66] = f2tf32(v.z - __uint_as_float(h2));
        dh[67] = f2tf32(v.w - __uint_as_float(h3));
    }

    float m0 = -INFINITY, m1 = -INFINITY, lsum0 = 0.f, lsum1 = 0.f;
    float out0[8], out1[8];
#pragma unroll
    for (int i = 0; i < 8; i++) { out0[i] = 0.f; out1[i] = 0.f; }

    for (int t = 0; t < NKEYP / 32; t++) {
        __syncthreads();
        if (tid < 32) kid[tid] = keys[h * NKEYP + t * 32 + tid];
        __syncthreads();
        if (kid[0] > qbmax) continue;

        for (int l = tid; l < 32 * 16; l += 256) {
            int r = l >> 4, c4 = (l & 15) * 4;
            float4 kv = *(const float4*)&ksp[((size_t)h * NKEYP + t * 32 + r) * HD + c4];
            uint32_t* dh = &khl[r * QHL_ST + c4];
            uint32_t h0 = f2tf32(kv.x), h1 = f2tf32(kv.y), h2 = f2tf32(kv.z), h3 = f2tf32(kv.w);
            dh[0] = h0; dh[1] = h1; dh[2] = h2; dh[3] = h3;
            dh[64] = f2tf32(kv.x - __uint_as_float(h0));
            dh[65] = f2tf32(kv.y - __uint_as_float(h1));
            dh[66] = f2tf32(kv.z - __uint_as_float(h2));
            dh[67] = f2tf32(kv.w - __uint_as_float(h3));
            *(float4*)&vs[r * 68 + c4] =
                *(const float4*)&vsp[((size_t)h * NKEYP + t * 32 + r) * HD + c4];
        }
        __syncthreads();

        {
            float acc[2][4];
#pragma unroll
            for (int nt = 0; nt < 2; nt++)
#pragma unroll
                for (int e = 0; e < 4; e++) acc[nt][e] = 0.f;
#pragma unroll
            for (int ksI = 0; ksI < 8; ksI++) {
                int kb = ksI * 8;
                int ra = wm * 16 + lr;
                uint32_t aH[4], aL[4];
                aH[0] = qhl[ra * QHL_ST + kb + lc];
                aH[1] = qhl[(ra + 8) * QHL_ST + kb + lc];
                aH[2] = qhl[ra * QHL_ST + kb + lc + 4];
                aH[3] = qhl[(ra + 8) * QHL_ST + kb + lc + 4];
                aL[0] = qhl[ra * QHL_ST + 64 + kb + lc];
                aL[1] = qhl[(ra + 8) * QHL_ST + 64 + kb + lc];
                aL[2] = qhl[ra * QHL_ST + 64 + kb + lc + 4];
                aL[3] = qhl[(ra + 8) * QHL_ST + 64 + kb + lc + 4];
#pragma unroll
                for (int nt = 0; nt < 2; nt++) {
                    int n0 = wn * 16 + nt * 8;
                    uint32_t b0h = khl[(n0 + lr) * QHL_ST + kb + lc];
                    uint32_t b1h = khl[(n0 + lr) * QHL_ST + kb + lc + 4];
                    uint32_t b0l = khl[(n0 + lr) * QHL_ST + 64 + kb + lc];
                    uint32_t b1l = khl[(n0 + lr) * QHL_ST + 64 + kb + lc + 4];
                    mma_tf32(acc[nt], aH, b0h, b1h);
                    mma_tf32(acc[nt], aH, b0l, b1l);
                    mma_tf32(acc[nt], aL, b0h, b1h);
                }
            }
#pragma unroll
            for (int nt = 0; nt < 2; nt++) {
                int row = wm * 16 + lr;
                int col = wn * 16 + nt * 8 + 2 * lc;
#pragma unroll
                for (int e = 0; e < 4; e++) {
                    int rr = row + (e >> 1) * 8;
                    int cc = col + (e & 1);
                    int key = kid[cc];
                    int sg = qb * 64 + rr;
                    float val;
                    if (key >= SEQ) val = -INFINITY;
                    else val = (key <= sg) ? acc[nt][e] * SCALE : -1e30f;
                    ss[rr * 36 + cc] = val;
                }
            }
        }
        __syncthreads();

        float tm0 = m0, tm1 = m1;
#pragma unroll
        for (int j = 0; j < 32; j++) {
            tm0 = fmaxf(tm0, ss[qi0 * 36 + j]);
            tm1 = fmaxf(tm1, ss[qi1 * 36 + j]);
        }
        float c0 = expf(m0 - tm0);
        float c1 = expf(m1 - tm1);
        m0 = tm0; m1 = tm1;
        lsum0 *= c0; lsum1 *= c1;
#pragma unroll
        for (int i = 0; i < 8; i++) { out0[i] *= c0; out1[i] *= c1; }
        __syncthreads();

#pragma unroll
        for (int j = 0; j < 4; j++) {
            int jj = g * 4 + j;
            ss[qi0 * 36 + jj] = expf(ss[qi0 * 36 + jj] - m0);
            ss[qi1 * 36 + jj] = expf(ss[qi1 * 36 + jj] - m1);
        }
        __syncthreads();

        float ps0 = 0.f, ps1 = 0.f;
#pragma unroll
        for (int j = 0; j < 32; j++) {
            float p0 = ss[qi0 * 36 + j];
            float p1 = ss[qi1 * 36 + j];
            ps0 += p0; ps1 += p1;
            float4 va = *(float4*)&vs[j * 68 + g * 8];
            float4 vb = *(float4*)&vs[j * 68 + g * 8 + 4];
            out0[0] += p0 * va.x; out0[1] += p0 * va.y; out0[2] += p0 * va.z; out0[3] += p0 * va.w;
            out0[4] += p0 * vb.x; out0[5] += p0 * vb.y; out0[6] += p0 * vb.z; out0[7] += p0 * vb.w;
            out1[0] += p1 * va.x; out1[1] += p1 * va.y; out1[2] += p1 * va.z; out1[3] += p1 * va.w;
            out1[4] += p1 * vb.x; out1[5] += p1 * vb.y; out1[6] += p1 * vb.z; out1[7] += p1 * vb.w;
        }
        lsum0 += ps0;
        lsum1 += ps1;
    }

    if (m0 < -5e29f) {
        lsum0 = (float)NKEY;
#pragma unroll
        for (int i = 0; i < 8; i++) out0[i] = 0.f;
        for (int j = 0; j < NKEYP; j++) {
            if (keys[h * NKEYP + j] < SEQ) {
                const float* vr = &vsp[((size_t)h * NKEYP + j) * HD + g * 8];
#pragma unroll
                for (int i = 0; i < 8; i++) out0[i] += vr[i];
            }
        }
    }
    if (m1 < -5e29f) {
        lsum1 = (float)NKEY;
#pragma unroll
        for (int i = 0; i < 8; i++) out1[i] = 0.f;
        for (int j = 0; j < NKEYP; j++) {
            if (keys[h * NKEYP + j] < SEQ) {
                const float* vr = &vsp[((size_t)h * NKEYP + j) * HD + g * 8];
#pragma unroll
                for (int i = 0; i < 8; i++) out1[i] += vr[i];
            }
        }
    }

    float inv0 = 1.f / lsum0;
    float inv1 = 1.f / lsum1;
#pragma unroll
    for (int i = 0; i < 8; i++) {
        attout[(size_t)sglob0 * DIM + h * HD + g * 8 + i] = __float2half_rn(out0[i] * inv0);
        attout[(size_t)sglob1 * DIM + h * HD + g * 8 + i] = __float2half_rn(out1[i] * inv1);
    }
}

// --------------------------------- launch --------------------------------
extern "C" void kernel_launch(void* const* d_in, const int* in_sizes, int n_in,
                              void* d_out, int out_size) {
    const float* x    = (const float*)d_in[0];
    const float* fcos = (const float*)d_in[1];
    const float* fsin = (const float*)d_in[2];
    const float* wq   = (const float*)d_in[3];
    const float* wk   = (const float*)d_in[4];
    const float* wv   = (const float*)d_in[5];
    const float* wo   = (const float*)d_in[6];
    float* out = (float*)d_out;

    float *q, *q64, *q64p, *kv, *probs, *vert, *dgp, *ksp, *vsp;
    int* keys;
    __half *xh, *xl, *atth, *wqt, *wot, *wkvtH, *wkvtL;
    cudaGetSymbolAddress((void**)&q, g_q);
    cudaGetSymbolAddress((void**)&q64, g_q64);
    cudaGetSymbolAddress((void**)&q64p, g_q64p);
    cudaGetSymbolAddress((void**)&kv, g_kv);
    cudaGetSymbolAddress((void**)&probs, g_probs);
    cudaGetSymbolAddress((void**)&vert, g_vert);
    cudaGetSymbolAddress((void**)&dgp, g_diag);
    cudaGetSymbolAddress((void**)&keys, g_keys);
    cudaGetSymbolAddress((void**)&ksp, g_ksp);
    cudaGetSymbolAddress((void**)&vsp, g_vsp);
    cudaGetSymbolAddress((void**)&xh, g_xh);
    cudaGetSymbolAddress((void**)&xl, g_xl);
    cudaGetSymbolAddress((void**)&atth, g_atth);
    cudaGetSymbolAddress((void**)&wqt, g_wqt);
    cudaGetSymbolAddress((void**)&wot, g_wot);
    cudaGetSymbolAddress((void**)&wkvtH, g_wkvtH);
    cudaGetSymbolAddress((void**)&wkvtL, g_wkvtL);

    // prep
    split_h2<<<(SEQ * DIM / 4 + 255) / 256, 256>>>(x, xh, xl, SEQ * DIM / 4);
    concat_transp_split<<<dim3(KVW / 32, DIM / 32), dim3(32, 8)>>>(wk, wv, wkvtH, wkvtL);
    transp_half<<<dim3(DIM / 32, DIM / 32), dim3(32, 8)>>>(wq, wqt);
    transp_half<<<dim3(DIM / 32, DIM / 32), dim3(32, 8)>>>(wo, wot);

    // projections: q fp16 TC (pipelined), kv fp16x3 TC (pipelined, ~fp32 accuracy)
    gemm_f16<<<dim3(DIM / 128, SEQ / 128), 256>>>(xh, wqt, q, SEQ, DIM, DIM);
    {
        size_t smb = (size_t)(2 * STGW) * 4;
        cudaFuncSetAttribute(gemm_f16x3, cudaFuncAttributeMaxDynamicSharedMemorySize,
                             (int)smb);
        gemm_f16x3<<<dim3(KVW / 128, SEQ / 128), 256, smb>>>(
            xh, xl, wkvtH, wkvtL, kv, SEQ, KVW, DIM);
    }

    // exact fp32 q rows 0..63
    qproj_part<<<dim3(16, 8, 8), 128>>>(x, wq, q64p);
    qproj_red<<<(ESTQ * DIM + 255) / 256, 256>>>(q64p, q64);

    // RoPE
    {
        int tq = SEQ * NH * 32;
        rope_kernel<<<(tq + 255) / 256, 256>>>(q, fcos, fsin, NH, DIM, tq);
        int tk = SEQ * NKV * 32;
        rope_kernel<<<(tk + 255) / 256, 256>>>(kv, fcos, fsin, NKV, KVW, tk);
        int tq64 = ESTQ * NH * 32;
        rope_kernel<<<(tq64 + 255) / 256, 256>>>(q64, fcos, fsin, NH, DIM, tq64);
    }

    // estimation
    est_score<<<dim3(SEQ / 64, NH), 256>>>(q64, kv, probs);
    est_norm<<<dim3(ESTQ, NH), 256>>>(probs);

    vertical_kernel<<<(NH * SEQ) / 256, 256>>>(probs, vert);
    diag_kernel<<<(NH * SEQ) / 256, 256>>>(probs, dgp);

    topk2_kernel<<<64, 512>>>(vert, dgp, keys);
    sortkeys_kernel<<<NH, 256>>>(keys);

    gather_kernel<<<NH * NKEYP, 64>>>(kv, keys, ksp, vsp);

    {
        size_t spbytes = (size_t)SP_WORDS * 4;
        cudaFuncSetAttribute(spattn_kernel,
                             cudaFuncAttributeMaxDynamicSharedMemorySize, (int)spbytes);
        spattn_kernel<<<dim3(SEQ / 64, NH), 256, spbytes>>>(q, ksp, vsp, keys, atth);
    }

    // output projection: fp16 TC (pipelined)
    gemm_f16<<<dim3(DIM / 128, SEQ / 128), 256>>>(atth, wot, out, SEQ, DIM, DIM);
}

// round 13
// speedup vs baseline: 1.5196x; 1.5196x over previous
#include <cuda_runtime.h>
#include <cuda_fp16.h>
#include <math.h>
#include <stdint.h>

#define SEQ   4096
#define DIM   2048
#define NH    32
#define NKV   8
#define HD    64
#define ESTQ  64
#define VSZ   300
#define SSZ   800
#define NKEY  1100
#define NKEYP 1152
#define SCALE 0.125f
#define PADKEY 0x3FFFFFFF
#define KVW   1024

// ---------------- device scratch ----------------
__device__ float g_q[SEQ * DIM];
__device__ float g_q64[ESTQ * DIM];
__device__ float g_q64p[8 * ESTQ * DIM];
__device__ float g_kv[SEQ * KVW];
__device__ float g_probs[NH * ESTQ * SEQ];
__device__ float g_vert[NH * SEQ];
__device__ float g_diag[NH * SEQ];
__device__ int   g_keys[NH * NKEYP];
__device__ float g_ksp[NH * NKEYP * HD];
__device__ float g_vsp[NH * NKEYP * HD];
__device__ __half g_xh[SEQ * DIM];      // x hi (fp16)
__device__ __half g_xl[SEQ * DIM];      // x lo (fp16)
__device__ __half g_atth[SEQ * DIM];    // attention output fp16
__device__ __half g_wqt[DIM * DIM];     // wq transposed [n][k] fp16
__device__ __half g_wot[DIM * DIM];     // wo transposed [n][k] fp16
__device__ __half g_wkvtH[KVW * DIM];   // [wk|wv] transposed [n][k] hi fp16
__device__ __half g_wkvtL[KVW * DIM];   // [wk|wv] transposed [n][k] lo fp16

// ---------------- helpers ------------------------------------------------
__device__ __forceinline__ uint32_t f2tf32(float f) {
    uint32_t r;
    asm("cvt.rna.tf32.f32 %0, %1;" : "=r"(r) : "f"(f));
    return r;
}

__device__ __forceinline__ void mma_tf32(float c[4], const uint32_t a[4],
                                         uint32_t b0, uint32_t b1) {
    asm volatile(
        "mma.sync.aligned.m16n8k8.row.col.f32.tf32.tf32.f32 "
        "{%0,%1,%2,%3}, {%4,%5,%6,%7}, {%8,%9}, {%0,%1,%2,%3};\n"
        : "+f"(c[0]), "+f"(c[1]), "+f"(c[2]), "+f"(c[3])
        : "r"(a[0]), "r"(a[1]), "r"(a[2]), "r"(a[3]), "r"(b0), "r"(b1));
}

__device__ __forceinline__ void mma_f16(float c[4], const uint32_t a[4],
                                        uint32_t b0, uint32_t b1) {
    asm volatile(
        "mma.sync.aligned.m16n8k16.row.col.f32.f16.f16.f32 "
        "{%0,%1,%2,%3}, {%4,%5,%6,%7}, {%8,%9}, {%0,%1,%2,%3};\n"
        : "+f"(c[0]), "+f"(c[1]), "+f"(c[2]), "+f"(c[3])
        : "r"(a[0]), "r"(a[1]), "r"(a[2]), "r"(a[3]), "r"(b0), "r"(b1));
}

__device__ __forceinline__ uint32_t smem_u32(const void* p) {
    uint32_t a;
    asm("{ .reg .u64 t; cvta.to.shared.u64 t, %1; cvt.u32.u64 %0, t; }" : "=r"(a) : "l"(p));
    return a;
}

// ================= fp16 k16 GEMM with cp.async double buffering ===========
#define AF_ST 20

__global__ __launch_bounds__(256) void gemm_f16(const __half* __restrict__ A,
                                                const __half* __restrict__ Bt,
                                                float* __restrict__ C,
                                                int M, int N, int K) {
    __shared__ uint32_t As[2][128 * AF_ST];
    __shared__ uint32_t Bs[2][128 * AF_ST];
    int tid = threadIdx.x;
    int lane = tid & 31;
    int warp = tid >> 5;
    int wm = warp & 3;
    int wn = warp >> 2;
    int row0 = blockIdx.y * 128;
    int col0 = blockIdx.x * 128;
    int lr = lane >> 2;
    int lc = lane & 3;

    uint32_t asb[2], bsb[2];
    asb[0] = smem_u32(&As[0][0]);
    asb[1] = smem_u32(&As[1][0]);
    bsb[0] = smem_u32(&Bs[0][0]);
    bsb[1] = smem_u32(&Bs[1][0]);

    float acc[2][8][4];
#pragma unroll
    for (int mi = 0; mi < 2; mi++)
#pragma unroll
        for (int nj = 0; nj < 8; nj++)
#pragma unroll
            for (int e = 0; e < 4; e++) acc[mi][nj][e] = 0.f;

    int r_ld = tid >> 2;
    int j_ld = tid & 3;

    {
#pragma unroll
        for (int i = 0; i < 2; i++) {
            int r = r_ld + i * 64;
            uint32_t da = asb[0] + (uint32_t)(r * AF_ST + j_ld * 4) * 4;
            const __half* sa = A + (size_t)(row0 + r) * K + j_ld * 8;
            asm volatile("cp.async.ca.shared.global [%0], [%1], 16;" :: "r"(da), "l"(sa));
            uint32_t db = bsb[0] + (uint32_t)(r * AF_ST + j_ld * 4) * 4;
            const __half* sb = Bt + (size_t)(col0 + r) * K + j_ld * 8;
            asm volatile("cp.async.ca.shared.global [%0], [%1], 16;" :: "r"(db), "l"(sb));
        }
        asm volatile("cp.async.commit_group;");
    }

    int KC = K >> 5;
    for (int c = 0; c < KC; c++) {
        int buf = c & 1;
        if (c + 1 < KC) {
            int k0 = (c + 1) << 5;
            int nb = buf ^ 1;
#pragma unroll
            for (int i = 0; i < 2; i++) {
                int r = r_ld + i * 64;
                uint32_t da = asb[nb] + (uint32_t)(r * AF_ST + j_ld * 4) * 4;
                const __half* sa = A + (size_t)(row0 + r) * K + k0 + j_ld * 8;
                asm volatile("cp.async.ca.shared.global [%0], [%1], 16;" :: "r"(da), "l"(sa));
                uint32_t db = bsb[nb] + (uint32_t)(r * AF_ST + j_ld * 4) * 4;
                const __half* sb = Bt + (size_t)(col0 + r) * K + k0 + j_ld * 8;
                asm volatile("cp.async.ca.shared.global [%0], [%1], 16;" :: "r"(db), "l"(sb));
            }
            asm volatile("cp.async.commit_group;");
            asm volatile("cp.async.wait_group 1;");
        } else {
            asm volatile("cp.async.wait_group 0;");
        }
        __syncthreads();

        const uint32_t* Ab = As[buf];
        const uint32_t* Bb = Bs[buf];
#pragma unroll
        for (int ks = 0; ks < 2; ks++) {
            int kb = ks * 8;
            uint32_t a[2][4];
#pragma unroll
            for (int mi = 0; mi < 2; mi++) {
                int ra = wm * 32 + mi * 16 + lr;
                a[mi][0] = Ab[ra * AF_ST + kb + lc];
                a[mi][1] = Ab[(ra + 8) * AF_ST + kb + lc];
                a[mi][2] = Ab[ra * AF_ST + kb + lc + 4];
                a[mi][3] = Ab[(ra + 8) * AF_ST + kb + lc + 4];
            }
#pragma unroll
            for (int nj = 0; nj < 8; nj++) {
                int col = wn * 64 + nj * 8 + lr;
                uint32_t b0 = Bb[col * AF_ST + kb + lc];
                uint32_t b1 = Bb[col * AF_ST + kb + lc + 4];
                mma_f16(acc[0][nj], a[0], b0, b1);
                mma_f16(acc[1][nj], a[1], b0, b1);
            }
        }
        __syncthreads();
    }

#pragma unroll
    for (int mi = 0; mi < 2; mi++) {
        int row = row0 + wm * 32 + mi * 16 + lr;
#pragma unroll
        for (int nj = 0; nj < 8; nj++) {
            int col = col0 + wn * 64 + nj * 8 + 2 * lc;
            float* cp0 = C + (size_t)row * N + col;
            cp0[0] = acc[mi][nj][0];
            cp0[1] = acc[mi][nj][1];
            float* cp1 = C + (size_t)(row + 8) * N + col;
            cp1[0] = acc[mi][nj][2];
            cp1[1] = acc[mi][nj][3];
        }
    }
}

// ===== fp16 hi/lo 3-term GEMM, BK=16 (kv projection): low smem, 2+ CTAs/SM =====
#define AK_ST 12                       // 8 words (16 halves) + 4 pad
#define STG2W (4 * 128 * AK_ST)        // AH AL BH BL per stage (words) = 24KB

__global__ __launch_bounds__(256) void gemm_f16x3(const __half* __restrict__ AH,
                                                  const __half* __restrict__ AL,
                                                  const __half* __restrict__ BH,
                                                  const __half* __restrict__ BL,
                                                  float* __restrict__ C,
                                                  int M, int N, int K) {
    extern __shared__ uint32_t sm[];
    uint32_t base = smem_u32(sm);
    int tid = threadIdx.x;
    int lane = tid & 31;
    int warp = tid >> 5;
    int wm = warp & 3;
    int wn = warp >> 2;
    int row0 = blockIdx.y * 128;
    int col0 = blockIdx.x * 128;
    int lr = lane >> 2;
    int lc = lane & 3;

    float acc[2][8][4];
#pragma unroll
    for (int mi = 0; mi < 2; mi++)
#pragma unroll
        for (int nj = 0; nj < 8; nj++)
#pragma unroll
            for (int e = 0; e < 4; e++) acc[mi][nj][e] = 0.f;

    int r_ld = tid >> 1;   // row 0..127
    int j_ld = tid & 1;    // 16B chunk within 32B row

    auto issue = [&](int stage, int k0) {
        uint32_t sb = base + (uint32_t)stage * STG2W * 4;
        uint32_t off = (uint32_t)(r_ld * AK_ST + j_ld * 4) * 4;
        const __half* pa = AH + (size_t)(row0 + r_ld) * K + k0 + j_ld * 8;
        asm volatile("cp.async.ca.shared.global [%0], [%1], 16;" :: "r"(sb + off), "l"(pa));
        const __half* pl = AL + (size_t)(row0 + r_ld) * K + k0 + j_ld * 8;
        asm volatile("cp.async.ca.shared.global [%0], [%1], 16;"
                     :: "r"(sb + (uint32_t)(128 * AK_ST) * 4 + off), "l"(pl));
        const __half* pb = BH + (size_t)(col0 + r_ld) * K + k0 + j_ld * 8;
        asm volatile("cp.async.ca.shared.global [%0], [%1], 16;"
                     :: "r"(sb + (uint32_t)(2 * 128 * AK_ST) * 4 + off), "l"(pb));
        const __half* pc = BL + (size_t)(col0 + r_ld) * K + k0 + j_ld * 8;
        asm volatile("cp.async.ca.shared.global [%0], [%1], 16;"
                     :: "r"(sb + (uint32_t)(3 * 128 * AK_ST) * 4 + off), "l"(pc));
        asm volatile("cp.async.commit_group;");
    };

    issue(0, 0);

    int KC = K >> 4;
    for (int c = 0; c < KC; c++) {
        int buf = c & 1;
        if (c + 1 < KC) {
            issue(buf ^ 1, (c + 1) << 4);
            asm volatile("cp.async.wait_group 1;");
        } else {
            asm volatile("cp.async.wait_group 0;");
        }
        __syncthreads();

        const uint32_t* AsH = sm + (size_t)buf * STG2W;
        const uint32_t* AsL = AsH + 128 * AK_ST;
        const uint32_t* BsH = AsH + 2 * 128 * AK_ST;
        const uint32_t* BsL = AsH + 3 * 128 * AK_ST;
        uint32_t aH[2][4], aL[2][4];
#pragma unroll
        for (int mi = 0; mi < 2; mi++) {
            int ra = wm * 32 + mi * 16 + lr;
            aH[mi][0] = AsH[ra * AK_ST + lc];
            aH[mi][1] = AsH[(ra + 8) * AK_ST + lc];
            aH[mi][2] = AsH[ra * AK_ST + lc + 4];
            aH[mi][3] = AsH[(ra + 8) * AK_ST + lc + 4];
            aL[mi][0] = AsL[ra * AK_ST + lc];
            aL[mi][1] = AsL[(ra + 8) * AK_ST + lc];
            aL[mi][2] = AsL[ra * AK_ST + lc + 4];
            aL[mi][3] = AsL[(ra + 8) * AK_ST + lc + 4];
        }
#pragma unroll
        for (int nj = 0; nj < 8; nj++) {
            int col = wn * 64 + nj * 8 + lr;
            uint32_t b0h = BsH[col * AK_ST + lc];
            uint32_t b1h = BsH[col * AK_ST + lc + 4];
            uint32_t b0l = BsL[col * AK_ST + lc];
            uint32_t b1l = BsL[col * AK_ST + lc + 4];
#pragma unroll
            for (int mi = 0; mi < 2; mi++) {
                mma_f16(acc[mi][nj], aH[mi], b0h, b1h);
                mma_f16(acc[mi][nj], aH[mi], b0l, b1l);
                mma_f16(acc[mi][nj], aL[mi], b0h, b1h);
            }
        }
        __syncthreads();
    }

#pragma unroll
    for (int mi = 0; mi < 2; mi++) {
        int row = row0 + wm * 32 + mi * 16 + lr;
#pragma unroll
        for (int nj = 0; nj < 8; nj++) {
            int col = col0 + wn * 64 + nj * 8 + 2 * lc;
            float* cp0 = C + (size_t)row * N + col;
            cp0[0] = acc[mi][nj][0];
            cp0[1] = acc[mi][nj][1];
            float* cp1 = C + (size_t)(row + 8) * N + col;
            cp1[0] = acc[mi][nj][2];
            cp1[1] = acc[mi][nj][3];
        }
    }
}

// ---------------- prep kernels ---------------------------------------------
__global__ void split_h2(const float* __restrict__ a, __half* __restrict__ h,
                         __half* __restrict__ l, int n4) {
    int i = blockIdx.x * 256 + threadIdx.x;
    if (i >= n4) return;
    float4 v = ((const float4*)a)[i];
    __half hx = __float2half_rn(v.x), hy = __float2half_rn(v.y);
    __half hz = __float2half_rn(v.z), hw = __float2half_rn(v.w);
    __half2 h0 = __halves2half2(hx, hy);
    __half2 h1 = __halves2half2(hz, hw);
    ((uint2*)h)[i] = make_uint2(*(uint32_t*)&h0, *(uint32_t*)&h1);
    __half2 l0 = __halves2half2(__float2half_rn(v.x - __half2float(hx)),
                                __float2half_rn(v.y - __half2float(hy)));
    __half2 l1 = __halves2half2(__float2half_rn(v.z - __half2float(hz)),
                                __float2half_rn(v.w - __half2float(hw)));
    ((uint2*)l)[i] = make_uint2(*(uint32_t*)&l0, *(uint32_t*)&l1);
}

__global__ void concat_transp_split(const float* __restrict__ wk, const float* __restrict__ wv,
                                    __half* __restrict__ th, __half* __restrict__ tl) {
    __shared__ float tile[32][33];
    int bx = blockIdx.x * 32;  // n in [0,1024)
    int by = blockIdx.y * 32;  // k
    int tx = threadIdx.x, ty = threadIdx.y;  // (32,8)
    for (int i = 0; i < 32; i += 8) {
        int col = bx + tx;
        float v = (col < 512) ? wk[(size_t)(by + ty + i) * 512 + col]
                              : wv[(size_t)(by + ty + i) * 512 + (col - 512)];
        tile[ty + i][tx] = v;
    }
    __syncthreads();
    for (int i = 0; i < 32; i += 8) {
        float v = tile[tx][ty + i];
        __half h = __float2half_rn(v);
        th[(size_t)(bx + ty + i) * DIM + by + tx] = h;
        tl[(size_t)(bx + ty + i) * DIM + by + tx] = __float2half_rn(v - __half2float(h));
    }
}

__global__ void transp_half(const float* __restrict__ w, __half* __restrict__ t) {
    __shared__ float tile[32][33];
    int bx = blockIdx.x * 32;
    int by = blockIdx.y * 32;
    int tx = threadIdx.x, ty = threadIdx.y;
    for (int i = 0; i < 32; i += 8)
        tile[ty + i][tx] = w[(size_t)(by + ty + i) * DIM + bx + tx];
    __syncthreads();
    for (int i = 0; i < 32; i += 8)
        t[(size_t)(bx + ty + i) * DIM + by + tx] = __float2half_rn(tile[tx][ty + i]);
}

// ---------------- exact fp32 q rows 0..63: split-K ---------------------------
__global__ __launch_bounds__(128) void qproj_part(const float* __restrict__ x,
                                                  const float* __restrict__ wq,
                                                  float* __restrict__ part) {
    __shared__ float xs[8][256];
    int tid = threadIdx.x;
    int col = blockIdx.x * 128 + tid;
    int r0 = blockIdx.y * 8;
    int k0 = blockIdx.z * 256;
    float acc[8];
#pragma unroll
    for (int rr = 0; rr < 8; rr++) acc[rr] = 0.f;

    for (int i = tid; i < 8 * 256; i += 128) {
        int rr = i >> 8, kk = i & 255;
        xs[rr][kk] = x[(size_t)(r0 + rr) * DIM + k0 + kk];
    }
    __syncthreads();
    for (int kk = 0; kk < 256; kk++) {
        float w = wq[(size_t)(k0 + kk) * DIM + col];
#pragma unroll
        for (int rr = 0; rr < 8; rr++) acc[rr] += xs[rr][kk] * w;
    }
#pragma unroll
    for (int rr = 0; rr < 8; rr++)
        part[(size_t)blockIdx.z * ESTQ * DIM + (size_t)(r0 + rr) * DIM + col] = acc[rr];
}

__global__ void qproj_red(const float* __restrict__ part, float* __restrict__ q64) {
    int idx = blockIdx.x * 256 + threadIdx.x;
    if (idx >= ESTQ * DIM) return;
    float s = 0.f;
#pragma unroll
    for (int ks = 0; ks < 8; ks++) s += part[(size_t)ks * ESTQ * DIM + idx];
    q64[idx] = s;
}

// ---------------- RoPE -------------------------------------------------------
__global__ void rope_kernel(float* t, const float* __restrict__ cosb,
                            const float* __restrict__ sinb, int H, int stride, int total) {
    int idx = blockIdx.x * blockDim.x + threadIdx.x;
    if (idx >= total) return;
    int d2 = idx & 31;
    int h = (idx >> 5) % H;
    int s = idx / (32 * H);
    float c = cosb[s * 32 + d2];
    float sn = sinb[s * 32 + d2];
    float* p = t + (size_t)s * stride + h * 64 + 2 * d2;
    float xr = p[0], xi = p[1];
    p[0] = xr * c - xi * sn;
    p[1] = xr * sn + xi * c;
}

// ---------------- est phase A -----------------------------------------------
__global__ __launch_bounds__(256) void est_score(const float* __restrict__ q64,
                                                 const float* __restrict__ kv,
                                                 float* __restrict__ probs) {
    __shared__ float qs[64][68];
    __shared__ float ksm[64][68];
    int tid = threadIdx.x;
    int h = blockIdx.y;
    int c0 = blockIdx.x * 64;
    int kvh = h >> 2;
    int qi = tid >> 2;
    int kg = tid & 3;

    for (int l = tid; l < 64 * 64; l += 256) {
        int r = l >> 6, d = l & 63;
        qs[r][d] = q64[(size_t)r * DIM + h * HD + d];
        ksm[r][d] = kv[(size_t)(c0 + r) * KVW + kvh * HD + d];
    }
    __syncthreads();

    float s16[16];
#pragma unroll
    for (int j = 0; j < 16; j++) s16[j] = 0.f;
#pragma unroll
    for (int d4 = 0; d4 < 16; d4++) {
        float4 q4 = *(float4*)&qs[qi][d4 * 4];
#pragma unroll
        for (int j = 0; j < 16; j++) {
            float4 k4 = *(float4*)&ksm[kg * 16 + j][d4 * 4];
            s16[j] += q4.x * k4.x + q4.y * k4.y + q4.z * k4.z + q4.w * k4.w;
        }
    }
    float* pr = probs + ((size_t)h * ESTQ + qi) * SEQ + c0 + kg * 16;
#pragma unroll
    for (int j = 0; j < 16; j++) {
        int kk = c0 + kg * 16 + j;
        float val = s16[j] * SCALE;
        if (kk >= SEQ - ESTQ && qi < kk - (SEQ - ESTQ)) val = -INFINITY;
        pr[j] = val;
    }
}

// ---------------- est phase B -------------------------------------------------
__global__ __launch_bounds__(256) void est_norm(float* __restrict__ probs) {
    int qi = blockIdx.x;
    int h = blockIdx.y;
    __shared__ float sc[SEQ];
    __shared__ float red[8];
    int tid = threadIdx.x;
    float* pr = probs + ((size_t)h * ESTQ + qi) * SEQ;

    for (int l = tid; l < SEQ / 4; l += 256)
        *(float4*)&sc[l * 4] = *(const float4*)&pr[l * 4];
    __syncthreads();

    float m = -INFINITY;
    for (int kk = tid; kk < SEQ; kk += 256) m = fmaxf(m, sc[kk]);
#pragma unroll
    for (int o = 16; o; o >>= 1) m = fmaxf(m, __shfl_xor_sync(0xFFFFFFFFu, m, o));
    if ((tid & 31) == 0) red[tid >> 5] = m;
    __syncthreads();
    if (tid == 0) {
        float mm = red[0];
#pragma unroll
        for (int i = 1; i < 8; i++) mm = fmaxf(mm, red[i]);
        red[0] = mm;
    }
    __syncthreads();
    m = red[0];
    __syncthreads();

    float s = 0.f;
    for (int kk = tid; kk < SEQ; kk += 256) {
        float e = expf(sc[kk] - m);
        sc[kk] = e;
        s += e;
    }
#pragma unroll
    for (int o = 16; o; o >>= 1) s += __shfl_xor_sync(0xFFFFFFFFu, s, o);
    if ((tid & 31) == 0) red[tid >> 5] = s;
    __syncthreads();
    if (tid == 0) {
        float ss = 0.f;
#pragma unroll
        for (int i = 0; i < 8; i++) ss += red[i];
        red[0] = ss;
    }
    __syncthreads();
    float inv = 1.f / red[0];
    for (int kk = tid; kk < SEQ; kk += 256) pr[kk] = sc[kk] * inv;
}

// ---------------- vertical / diagonal ------------------------------------------
__global__ void vertical_kernel(const float* __restrict__ probs, float* __restrict__ vert) {
    int idx = blockIdx.x * 256 + threadIdx.x;
    int h = idx >> 12;
    int kk = idx & (SEQ - 1);
    float s = 0.f;
    const float* base = probs + (size_t)h * ESTQ * SEQ + kk;
    for (int i = 0; i < ESTQ; i++) s += base[(size_t)i * SEQ];
    vert[idx] = s;
}

__global__ void diag_kernel(const float* __restrict__ probs, float* __restrict__ dg) {
    int idx = blockIdx.x * 256 + threadIdx.x;
    int h = idx >> 12;
    int jp = idx & (SEQ - 1);
    float s = 0.f;
    const float* base = probs + (size_t)h * ESTQ * SEQ;
    for (int i = 0; i < ESTQ; i++) {
        int col = i + jp - 63;
        if (col >= 0 && col < SEQ) s += base[(size_t)i * SEQ + col];
    }
    dg[idx] = s;
}

// ---------------- merged top-k ---------------------------------------------------
__global__ void topk2_kernel(const float* __restrict__ vert, const float* __restrict__ dg,
                             int* __restrict__ keys) {
    int b = blockIdx.x;
    int mode = b >> 5;
    int h = b & 31;
    const float* vals = mode ? dg : vert;
    int kcount = mode ? SSZ : VSZ;
    __shared__ unsigned long long a[SEQ];
    int tid = threadIdx.x;
    for (int i = tid; i < SEQ; i += 512) {
        unsigned u = __float_as_uint(vals[h * SEQ + i]);
        u = (u & 0x80000000u) ? ~u : (u | 0x80000000u);
        a[i] = ((unsigned long long)(~u) << 32) | (unsigned)i;
    }
    __syncthreads();
    for (int k = 2; k <= SEQ; k <<= 1) {
        for (int j = k >> 1; j > 0; j >>= 1) {
            for (int i = tid; i < SEQ; i += 512) {
                int ixj = i ^ j;
                if (ixj > i) {
                    bool up = ((i & k) == 0);
                    unsigned long long x = a[i], y = a[ixj];
                    if (up ? (x > y) : (x < y)) { a[i] = y; a[ixj] = x; }
                }
            }
            __syncthreads();
        }
    }
    if (mode == 0) {
        for (int t = tid; t < kcount; t += 512)
            keys[h * NKEYP + t] = (int)(a[t] & 0xFFFFFFFFull);
    } else {
        for (int t = tid; t < kcount; t += 512)
            keys[h * NKEYP + VSZ + t] = (SEQ - 1) - (int)(a[t] & 0xFFFFFFFFull);
        for (int t = NKEY + tid; t < NKEYP; t += 512) keys[h * NKEYP + t] = PADKEY;
    }
}

// ---------------- sort keys ascending per head ----------------------------------
__global__ __launch_bounds__(256) void sortkeys_kernel(int* __restrict__ keys) {
    int h = blockIdx.x;
    __shared__ int a[2048];
    int tid = threadIdx.x;
    for (int i = tid; i < 2048; i += 256)
        a[i] = (i < NKEYP) ? keys[h * NKEYP + i] : PADKEY;
    __syncthreads();
    for (int k = 2; k <= 2048; k <<= 1) {
        for (int j = k >> 1; j > 0; j >>= 1) {
            for (int i = tid; i < 2048; i += 256) {
                int ixj = i ^ j;
                if (ixj > i) {
                    bool up = ((i & k) == 0);
                    int x = a[i], y = a[ixj];
                    if (up ? (x > y) : (x < y)) { a[i] = y; a[ixj] = x; }
                }
            }
            __syncthreads();
        }
    }
    for (int i = tid; i < NKEYP; i += 256) keys[h * NKEYP + i] = a[i];
}

// ---------------- gather ----------------------------------------------------------
__global__ void gather_kernel(const float* __restrict__ kv,
                              const int* __restrict__ keys,
                              float* __restrict__ ksp, float* __restrict__ vsp) {
    int j = blockIdx.x;
    int h = j / NKEYP;
    int d = threadIdx.x;
    int key = keys[j];
    int kvh = h >> 2;
    float kvv = 0.f, vvv = 0.f;
    if (key < SEQ) {
        kvv = kv[(size_t)key * KVW + kvh * HD + d];
        vvv = kv[(size_t)key * KVW + 512 + kvh * HD + d];
    }
    ksp[(size_t)j * HD + d] = kvv;
    vsp[(size_t)j * HD + d] = vvv;
}

// ---------------- sparse attention (TC QK 3xTF32 + SIMT PV, fp16 out) ------------
#define QHL_ST 132
#define SP_WORDS (64 * 132 + 32 * 132 + 32 * 68 + 64 * 36 + 32)

__global__ __launch_bounds__(256) void spattn_kernel(const float* __restrict__ q,
                                                     const float* __restrict__ ksp,
                                                     const float* __restrict__ vsp,
                                                     const int* __restrict__ keys,
                                                     __half* __restrict__ attout) {
    extern __shared__ uint32_t smem[];
    uint32_t* qhl = smem;
    uint32_t* khl = qhl + 64 * 132;
    float* vs = (float*)(khl + 32 * 132);
    float* ss = vs + 32 * 68;
    int* kid = (int*)(ss + 64 * 36);

    int qb = blockIdx.x;
    int h = blockIdx.y;
    int tid = threadIdx.x;
    int lane = tid & 31;
    int warp = tid >> 5;
    int lr = lane >> 2;
    int lc = lane & 3;
    int wm = warp & 3;
    int wn = warp >> 2;
    int qp = tid >> 3;
    int g = tid & 7;
    int qi0 = qp, qi1 = qp + 32;
    int sglob0 = qb * 64 + qi0;
    int sglob1 = qb * 64 + qi1;
    int qbmax = qb * 64 + 63;

    for (int l = tid; l < 64 * 16; l += 256) {
        int r = l >> 4, c4 = (l & 15) * 4;
        float4 v = *(const float4*)&q[(size_t)(qb * 64 + r) * DIM + h * HD + c4];
        uint32_t* dh = &qhl[r * QHL_ST + c4];
        uint32_t h0 = f2tf32(v.x), h1 = f2tf32(v.y), h2 = f2tf32(v.z), h3 = f2tf32(v.w);
        dh[0] = h0; dh[1] = h1; dh[2] = h2; dh[3] = h3;
        dh[64] = f2tf32(v.x - __uint_as_float(h0));
        dh[65] = f2tf32(v.y - __uint_as_float(h1));
        dh[66] = f2tf32(v.z - __uint_as_float(h2));
        dh[67] = f2tf32(v.w - __uint_as_float(h3));
    }

    float m0 = -INFINITY, m1 = -INFINITY, lsum0 = 0.f, lsum1 = 0.f;
    float out0[8], out1[8];
#pragma unroll
    for (int i = 0; i < 8; i++) { out0[i] = 0.f; out1[i] = 0.f; }

    for (int t = 0; t < NKEYP / 32; t++) {
        __syncthreads();
        if (tid < 32) kid[tid] = keys[h * NKEYP + t * 32 + tid];
        __syncthreads();
        if (kid[0] > qbmax) continue;

        for (int l = tid; l < 32 * 16; l += 256) {
            int r = l >> 4, c4 = (l & 15) * 4;
            float4 kv = *(const float4*)&ksp[((size_t)h * NKEYP + t * 32 + r) * HD + c4];
            uint32_t* dh = &khl[r * QHL_ST + c4];
            uint32_t h0 = f2tf32(kv.x), h1 = f2tf32(kv.y), h2 = f2tf32(kv.z), h3 = f2tf32(kv.w);
            dh[0] = h0; dh[1] = h1; dh[2] = h2; dh[3] = h3;
            dh[64] = f2tf32(kv.x - __uint_as_float(h0));
            dh[65] = f2tf32(kv.y - __uint_as_float(h1));
            dh[66] = f2tf32(kv.z - __uint_as_float(h2));
            dh[67] = f2tf32(kv.w - __uint_as_float(h3));
            *(float4*)&vs[r * 68 + c4] =
                *(const float4*)&vsp[((size_t)h * NKEYP + t * 32 + r) * HD + c4];
        }
        __syncthreads();

        {
            float acc[2][4];
#pragma unroll
            for (int nt = 0; nt < 2; nt++)
#pragma unroll
                for (int e = 0; e < 4; e++) acc[nt][e] = 0.f;
#pragma unroll
            for (int ksI = 0; ksI < 8; ksI++) {
                int kb = ksI * 8;
                int ra = wm * 16 + lr;
                uint32_t aH[4], aL[4];
                aH[0] = qhl[ra * QHL_ST + kb + lc];
                aH[1] = qhl[(ra + 8) * QHL_ST + kb + lc];
                aH[2] = qhl[ra * QHL_ST + kb + lc + 4];
                aH[3] = qhl[(ra + 8) * QHL_ST + kb + lc + 4];
                aL[0] = qhl[ra * QHL_ST + 64 + kb + lc];
                aL[1] = qhl[(ra + 8) * QHL_ST + 64 + kb + lc];
                aL[2] = qhl[ra * QHL_ST + 64 + kb + lc + 4];
                aL[3] = qhl[(ra + 8) * QHL_ST + 64 + kb + lc + 4];
#pragma unroll
                for (int nt = 0; nt < 2; nt++) {
                    int n0 = wn * 16 + nt * 8;
                    uint32_t b0h = khl[(n0 + lr) * QHL_ST + kb + lc];
                    uint32_t b1h = khl[(n0 + lr) * QHL_ST + kb + lc + 4];
                    uint32_t b0l = khl[(n0 + lr) * QHL_ST + 64 + kb + lc];
                    uint32_t b1l = khl[(n0 + lr) * QHL_ST + 64 + kb + lc + 4];
                    mma_tf32(acc[nt], aH, b0h, b1h);
                    mma_tf32(acc[nt], aH, b0l, b1l);
                    mma_tf32(acc[nt], aL, b0h, b1h);
                }
            }
#pragma unroll
            for (int nt = 0; nt < 2; nt++) {
                int row = wm * 16 + lr;
                int col = wn * 16 + nt * 8 + 2 * lc;
#pragma unroll
                for (int e = 0; e < 4; e++) {
                    int rr = row + (e >> 1) * 8;
                    int cc = col + (e & 1);
                    int key = kid[cc];
                    int sg = qb * 64 + rr;
                    float val;
                    if (key >= SEQ) val = -INFINITY;
                    else val = (key <= sg) ? acc[nt][e] * SCALE : -1e30f;
                    ss[rr * 36 + cc] = val;
                }
            }
        }
        __syncthreads();

        float tm0 = m0, tm1 = m1;
#pragma unroll
        for (int j = 0; j < 32; j++) {
            tm0 = fmaxf(tm0, ss[qi0 * 36 + j]);
            tm1 = fmaxf(tm1, ss[qi1 * 36 + j]);
        }
        float c0 = expf(m0 - tm0);
        float c1 = expf(m1 - tm1);
        m0 = tm0; m1 = tm1;
        lsum0 *= c0; lsum1 *= c1;
#pragma unroll
        for (int i = 0; i < 8; i++) { out0[i] *= c0; out1[i] *= c1; }
        __syncthreads();

#pragma unroll
        for (int j = 0; j < 4; j++) {
            int jj = g * 4 + j;
            ss[qi0 * 36 + jj] = expf(ss[qi0 * 36 + jj] - m0);
            ss[qi1 * 36 + jj] = expf(ss[qi1 * 36 + jj] - m1);
        }
        __syncthreads();

        float ps0 = 0.f, ps1 = 0.f;
#pragma unroll
        for (int j = 0; j < 32; j++) {
            float p0 = ss[qi0 * 36 + j];
            float p1 = ss[qi1 * 36 + j];
            ps0 += p0; ps1 += p1;
            float4 va = *(float4*)&vs[j * 68 + g * 8];
            float4 vb = *(float4*)&vs[j * 68 + g * 8 + 4];
            out0[0] += p0 * va.x; out0[1] += p0 * va.y; out0[2] += p0 * va.z; out0[3] += p0 * va.w;
            out0[4] += p0 * vb.x; out0[5] += p0 * vb.y; out0[6] += p0 * vb.z; out0[7] += p0 * vb.w;
            out1[0] += p1 * va.x; out1[1] += p1 * va.y; out1[2] += p1 * va.z; out1[3] += p1 * va.w;
            out1[4] += p1 * vb.x; out1[5] += p1 * vb.y; out1[6] += p1 * vb.z; out1[7] += p1 * vb.w;
        }
        lsum0 += ps0;
        lsum1 += ps1;
    }

    if (m0 < -5e29f) {
        lsum0 = (float)NKEY;
#pragma unroll
        for (int i = 0; i < 8; i++) out0[i] = 0.f;
        for (int j = 0; j < NKEYP; j++) {
            if (keys[h * NKEYP + j] < SEQ) {
                const float* vr = &vsp[((size_t)h * NKEYP + j) * HD + g * 8];
#pragma unroll
                for (int i = 0; i < 8; i++) out0[i] += vr[i];
            }
        }
    }
    if (m1 < -5e29f) {
        lsum1 = (float)NKEY;
#pragma unroll
        for (int i = 0; i < 8; i++) out1[i] = 0.f;
        for (int j = 0; j < NKEYP; j++) {
            if (keys[h * NKEYP + j] < SEQ) {
                const float* vr = &vsp[((size_t)h * NKEYP + j) * HD + g * 8];
#pragma unroll
                for (int i = 0; i < 8; i++) out1[i] += vr[i];
            }
        }
    }

    float inv0 = 1.f / lsum0;
    float inv1 = 1.f / lsum1;
#pragma unroll
    for (int i = 0; i < 8; i++) {
        attout[(size_t)sglob0 * DIM + h * HD + g * 8 + i] = __float2half_rn(out0[i] * inv0);
        attout[(size_t)sglob1 * DIM + h * HD + g * 8 + i] = __float2half_rn(out1[i] * inv1);
    }
}

// --------------------------------- launch --------------------------------
extern "C" void kernel_launch(void* const* d_in, const int* in_sizes, int n_in,
                              void* d_out, int out_size) {
    const float* x    = (const float*)d_in[0];
    const float* fcos = (const float*)d_in[1];
    const float* fsin = (const float*)d_in[2];
    const float* wq   = (const float*)d_in[3];
    const float* wk   = (const float*)d_in[4];
    const float* wv   = (const float*)d_in[5];
    const float* wo   = (const float*)d_in[6];
    float* out = (float*)d_out;

    float *q, *q64, *q64p, *kv, *probs, *vert, *dgp, *ksp, *vsp;
    int* keys;
    __half *xh, *xl, *atth, *wqt, *wot, *wkvtH, *wkvtL;
    cudaGetSymbolAddress((void**)&q, g_q);
    cudaGetSymbolAddress((void**)&q64, g_q64);
    cudaGetSymbolAddress((void**)&q64p, g_q64p);
    cudaGetSymbolAddress((void**)&kv, g_kv);
    cudaGetSymbolAddress((void**)&probs, g_probs);
    cudaGetSymbolAddress((void**)&vert, g_vert);
    cudaGetSymbolAddress((void**)&dgp, g_diag);
    cudaGetSymbolAddress((void**)&keys, g_keys);
    cudaGetSymbolAddress((void**)&ksp, g_ksp);
    cudaGetSymbolAddress((void**)&vsp, g_vsp);
    cudaGetSymbolAddress((void**)&xh, g_xh);
    cudaGetSymbolAddress((void**)&xl, g_xl);
    cudaGetSymbolAddress((void**)&atth, g_atth);
    cudaGetSymbolAddress((void**)&wqt, g_wqt);
    cudaGetSymbolAddress((void**)&wot, g_wot);
    cudaGetSymbolAddress((void**)&wkvtH, g_wkvtH);
    cudaGetSymbolAddress((void**)&wkvtL, g_wkvtL);

    // prep
    split_h2<<<(SEQ * DIM / 4 + 255) / 256, 256>>>(x, xh, xl, SEQ * DIM / 4);
    concat_transp_split<<<dim3(KVW / 32, DIM / 32), dim3(32, 8)>>>(wk, wv, wkvtH, wkvtL);
    transp_half<<<dim3(DIM / 32, DIM / 32), dim3(32, 8)>>>(wq, wqt);
    transp_half<<<dim3(DIM / 32, DIM / 32), dim3(32, 8)>>>(wo, wot);

    // projections: q fp16 TC (pipelined), kv fp16x3 BK=16 (2+ CTAs/SM)
    gemm_f16<<<dim3(DIM / 128, SEQ / 128), 256>>>(xh, wqt, q, SEQ, DIM, DIM);
    {
        size_t smb = (size_t)(2 * STG2W) * 4;   // 48KB
        cudaFuncSetAttribute(gemm_f16x3, cudaFuncAttributeMaxDynamicSharedMemorySize,
                             (int)smb);
        gemm_f16x3<<<dim3(KVW / 128, SEQ / 128), 256, smb>>>(
            xh, xl, wkvtH, wkvtL, kv, SEQ, KVW, DIM);
    }

    // exact fp32 q rows 0..63
    qproj_part<<<dim3(16, 8, 8), 128>>>(x, wq, q64p);
    qproj_red<<<(ESTQ * DIM + 255) / 256, 256>>>(q64p, q64);

    // RoPE
    {
        int tq = SEQ * NH * 32;
        rope_kernel<<<(tq + 255) / 256, 256>>>(q, fcos, fsin, NH, DIM, tq);
        int tk = SEQ * NKV * 32;
        rope_kernel<<<(tk + 255) / 256, 256>>>(kv, fcos, fsin, NKV, KVW, tk);
        int tq64 = ESTQ * NH * 32;
        rope_kernel<<<(tq64 + 255) / 256, 256>>>(q64, fcos, fsin, NH, DIM, tq64);
    }

    // estimation
    est_score<<<dim3(SEQ / 64, NH), 256>>>(q64, kv, probs);
    est_norm<<<dim3(ESTQ, NH), 256>>>(probs);

    vertical_kernel<<<(NH * SEQ) / 256, 256>>>(probs, vert);
    diag_kernel<<<(NH * SEQ) / 256, 256>>>(probs, dgp);

    topk2_kernel<<<64, 512>>>(vert, dgp, keys);
    sortkeys_kernel<<<NH, 256>>>(keys);

    gather_kernel<<<NH * NKEYP, 64>>>(kv, keys, ksp, vsp);

    {
        size_t spbytes = (size_t)SP_WORDS * 4;
        cudaFuncSetAttribute(spattn_kernel,
                             cudaFuncAttributeMaxDynamicSharedMemorySize, (int)spbytes);
        spattn_kernel<<<dim3(SEQ / 64, NH), 256, spbytes>>>(q, ksp, vsp, keys, atth);
    }

    // output projection: fp16 TC (pipelined)
    gemm_f16<<<dim3(DIM / 128, SEQ / 128), 256>>>(atth, wot, out, SEQ, DIM, DIM);
}

// round 14
// speedup vs baseline: 1.9877x; 1.3081x over previous
#include <cuda_runtime.h>
#include <cuda_fp16.h>
#include <math.h>
#include <stdint.h>

#define SEQ   4096
#define DIM   2048
#define NH    32
#define NKV   8
#define HD    64
#define ESTQ  64
#define VSZ   300
#define SSZ   800
#define NKEY  1100
#define NKEYP 1152
#define SCALE 0.125f
#define PADKEY 0x3FFFFFFF
#define KVW   1024

// ---------------- device scratch ----------------
__device__ float g_q[SEQ * DIM];
__device__ float g_q64[ESTQ * DIM];
__device__ float g_q64p[8 * ESTQ * DIM];
__device__ float g_kv[SEQ * KVW];
__device__ float g_probs[NH * ESTQ * SEQ];
__device__ float g_vert[NH * SEQ];
__device__ float g_diag[NH * SEQ];
__device__ int   g_keys[NH * NKEYP];
__device__ float g_ksp[NH * NKEYP * HD];
__device__ float g_vsp[NH * NKEYP * HD];
__device__ __half g_xh[SEQ * DIM];
__device__ __half g_xl[SEQ * DIM];
__device__ __half g_atth[SEQ * DIM];
__device__ __half g_wqt[DIM * DIM];
__device__ __half g_wot[DIM * DIM];
__device__ __half g_wkvtH[KVW * DIM];
__device__ __half g_wkvtL[KVW * DIM];

// ---------------- helpers ------------------------------------------------
__device__ __forceinline__ uint32_t f2tf32(float f) {
    uint32_t r;
    asm("cvt.rna.tf32.f32 %0, %1;" : "=r"(r) : "f"(f));
    return r;
}

__device__ __forceinline__ void mma_tf32(float c[4], const uint32_t a[4],
                                         uint32_t b0, uint32_t b1) {
    asm volatile(
        "mma.sync.aligned.m16n8k8.row.col.f32.tf32.tf32.f32 "
        "{%0,%1,%2,%3}, {%4,%5,%6,%7}, {%8,%9}, {%0,%1,%2,%3};\n"
        : "+f"(c[0]), "+f"(c[1]), "+f"(c[2]), "+f"(c[3])
        : "r"(a[0]), "r"(a[1]), "r"(a[2]), "r"(a[3]), "r"(b0), "r"(b1));
}

__device__ __forceinline__ void mma_f16(float c[4], const uint32_t a[4],
                                        uint32_t b0, uint32_t b1) {
    asm volatile(
        "mma.sync.aligned.m16n8k16.row.col.f32.f16.f16.f32 "
        "{%0,%1,%2,%3}, {%4,%5,%6,%7}, {%8,%9}, {%0,%1,%2,%3};\n"
        : "+f"(c[0]), "+f"(c[1]), "+f"(c[2]), "+f"(c[3])
        : "r"(a[0]), "r"(a[1]), "r"(a[2]), "r"(a[3]), "r"(b0), "r"(b1));
}

__device__ __forceinline__ uint32_t smem_u32(const void* p) {
    uint32_t a;
    asm("{ .reg .u64 t; cvta.to.shared.u64 t, %1; cvt.u32.u64 %0, t; }" : "=r"(a) : "l"(p));
    return a;
}

// ================= fp16 k16 GEMM with cp.async double buffering ===========
#define AF_ST 20

__global__ __launch_bounds__(256) void gemm_f16(const __half* __restrict__ A,
                                                const __half* __restrict__ Bt,
                                                float* __restrict__ C,
                                                int M, int N, int K) {
    __shared__ uint32_t As[2][128 * AF_ST];
    __shared__ uint32_t Bs[2][128 * AF_ST];
    int tid = threadIdx.x;
    int lane = tid & 31;
    int warp = tid >> 5;
    int wm = warp & 3;
    int wn = warp >> 2;
    int row0 = blockIdx.y * 128;
    int col0 = blockIdx.x * 128;
    int lr = lane >> 2;
    int lc = lane & 3;

    uint32_t asb[2], bsb[2];
    asb[0] = smem_u32(&As[0][0]);
    asb[1] = smem_u32(&As[1][0]);
    bsb[0] = smem_u32(&Bs[0][0]);
    bsb[1] = smem_u32(&Bs[1][0]);

    float acc[2][8][4];
#pragma unroll
    for (int mi = 0; mi < 2; mi++)
#pragma unroll
        for (int nj = 0; nj < 8; nj++)
#pragma unroll
            for (int e = 0; e < 4; e++) acc[mi][nj][e] = 0.f;

    int r_ld = tid >> 2;
    int j_ld = tid & 3;

    {
#pragma unroll
        for (int i = 0; i < 2; i++) {
            int r = r_ld + i * 64;
            uint32_t da = asb[0] + (uint32_t)(r * AF_ST + j_ld * 4) * 4;
            const __half* sa = A + (size_t)(row0 + r) * K + j_ld * 8;
            asm volatile("cp.async.ca.shared.global [%0], [%1], 16;" :: "r"(da), "l"(sa));
            uint32_t db = bsb[0] + (uint32_t)(r * AF_ST + j_ld * 4) * 4;
            const __half* sb = Bt + (size_t)(col0 + r) * K + j_ld * 8;
            asm volatile("cp.async.ca.shared.global [%0], [%1], 16;" :: "r"(db), "l"(sb));
        }
        asm volatile("cp.async.commit_group;");
    }

    int KC = K >> 5;
    for (int c = 0; c < KC; c++) {
        int buf = c & 1;
        if (c + 1 < KC) {
            int k0 = (c + 1) << 5;
            int nb = buf ^ 1;
#pragma unroll
            for (int i = 0; i < 2; i++) {
                int r = r_ld + i * 64;
                uint32_t da = asb[nb] + (uint32_t)(r * AF_ST + j_ld * 4) * 4;
                const __half* sa = A + (size_t)(row0 + r) * K + k0 + j_ld * 8;
                asm volatile("cp.async.ca.shared.global [%0], [%1], 16;" :: "r"(da), "l"(sa));
                uint32_t db = bsb[nb] + (uint32_t)(r * AF_ST + j_ld * 4) * 4;
                const __half* sb = Bt + (size_t)(col0 + r) * K + k0 + j_ld * 8;
                asm volatile("cp.async.ca.shared.global [%0], [%1], 16;" :: "r"(db), "l"(sb));
            }
            asm volatile("cp.async.commit_group;");
            asm volatile("cp.async.wait_group 1;");
        } else {
            asm volatile("cp.async.wait_group 0;");
        }
        __syncthreads();

        const uint32_t* Ab = As[buf];
        const uint32_t* Bb = Bs[buf];
#pragma unroll
        for (int ks = 0; ks < 2; ks++) {
            int kb = ks * 8;
            uint32_t a[2][4];
#pragma unroll
            for (int mi = 0; mi < 2; mi++) {
                int ra = wm * 32 + mi * 16 + lr;
                a[mi][0] = Ab[ra * AF_ST + kb + lc];
                a[mi][1] = Ab[(ra + 8) * AF_ST + kb + lc];
                a[mi][2] = Ab[ra * AF_ST + kb + lc + 4];
                a[mi][3] = Ab[(ra + 8) * AF_ST + kb + lc + 4];
            }
#pragma unroll
            for (int nj = 0; nj < 8; nj++) {
                int col = wn * 64 + nj * 8 + lr;
                uint32_t b0 = Bb[col * AF_ST + kb + lc];
                uint32_t b1 = Bb[col * AF_ST + kb + lc + 4];
                mma_f16(acc[0][nj], a[0], b0, b1);
                mma_f16(acc[1][nj], a[1], b0, b1);
            }
        }
        __syncthreads();
    }

#pragma unroll
    for (int mi = 0; mi < 2; mi++) {
        int row = row0 + wm * 32 + mi * 16 + lr;
#pragma unroll
        for (int nj = 0; nj < 8; nj++) {
            int col = col0 + wn * 64 + nj * 8 + 2 * lc;
            float* cp0 = C + (size_t)row * N + col;
            cp0[0] = acc[mi][nj][0];
            cp0[1] = acc[mi][nj][1];
            float* cp1 = C + (size_t)(row + 8) * N + col;
            cp1[0] = acc[mi][nj][2];
            cp1[1] = acc[mi][nj][3];
        }
    }
}

// ===== fp16 hi/lo 3-term GEMM, BK=16 (kv projection) =====
#define AK_ST 12
#define STG2W (4 * 128 * AK_ST)

__global__ __launch_bounds__(256) void gemm_f16x3(const __half* __restrict__ AH,
                                                  const __half* __restrict__ AL,
                                                  const __half* __restrict__ BH,
                                                  const __half* __restrict__ BL,
                                                  float* __restrict__ C,
                                                  int M, int N, int K) {
    extern __shared__ uint32_t sm[];
    uint32_t base = smem_u32(sm);
    int tid = threadIdx.x;
    int lane = tid & 31;
    int warp = tid >> 5;
    int wm = warp & 3;
    int wn = warp >> 2;
    int row0 = blockIdx.y * 128;
    int col0 = blockIdx.x * 128;
    int lr = lane >> 2;
    int lc = lane & 3;

    float acc[2][8][4];
#pragma unroll
    for (int mi = 0; mi < 2; mi++)
#pragma unroll
        for (int nj = 0; nj < 8; nj++)
#pragma unroll
            for (int e = 0; e < 4; e++) acc[mi][nj][e] = 0.f;

    int r_ld = tid >> 1;
    int j_ld = tid & 1;

    auto issue = [&](int stage, int k0) {
        uint32_t sb = base + (uint32_t)stage * STG2W * 4;
        uint32_t off = (uint32_t)(r_ld * AK_ST + j_ld * 4) * 4;
        const __half* pa = AH + (size_t)(row0 + r_ld) * K + k0 + j_ld * 8;
        asm volatile("cp.async.ca.shared.global [%0], [%1], 16;" :: "r"(sb + off), "l"(pa));
        const __half* pl = AL + (size_t)(row0 + r_ld) * K + k0 + j_ld * 8;
        asm volatile("cp.async.ca.shared.global [%0], [%1], 16;"
                     :: "r"(sb + (uint32_t)(128 * AK_ST) * 4 + off), "l"(pl));
        const __half* pb = BH + (size_t)(col0 + r_ld) * K + k0 + j_ld * 8;
        asm volatile("cp.async.ca.shared.global [%0], [%1], 16;"
                     :: "r"(sb + (uint32_t)(2 * 128 * AK_ST) * 4 + off), "l"(pb));
        const __half* pc = BL + (size_t)(col0 + r_ld) * K + k0 + j_ld * 8;
        asm volatile("cp.async.ca.shared.global [%0], [%1], 16;"
                     :: "r"(sb + (uint32_t)(3 * 128 * AK_ST) * 4 + off), "l"(pc));
        asm volatile("cp.async.commit_group;");
    };

    issue(0, 0);

    int KC = K >> 4;
    for (int c = 0; c < KC; c++) {
        int buf = c & 1;
        if (c + 1 < KC) {
            issue(buf ^ 1, (c + 1) << 4);
            asm volatile("cp.async.wait_group 1;");
        } else {
            asm volatile("cp.async.wait_group 0;");
        }
        __syncthreads();

        const uint32_t* AsH = sm + (size_t)buf * STG2W;
        const uint32_t* AsL = AsH + 128 * AK_ST;
        const uint32_t* BsH = AsH + 2 * 128 * AK_ST;
        const uint32_t* BsL = AsH + 3 * 128 * AK_ST;
        uint32_t aH[2][4], aL[2][4];
#pragma unroll
        for (int mi = 0; mi < 2; mi++) {
            int ra = wm * 32 + mi * 16 + lr;
            aH[mi][0] = AsH[ra * AK_ST + lc];
            aH[mi][1] = AsH[(ra + 8) * AK_ST + lc];
            aH[mi][2] = AsH[ra * AK_ST + lc + 4];
            aH[mi][3] = AsH[(ra + 8) * AK_ST + lc + 4];
            aL[mi][0] = AsL[ra * AK_ST + lc];
            aL[mi][1] = AsL[(ra + 8) * AK_ST + lc];
            aL[mi][2] = AsL[ra * AK_ST + lc + 4];
            aL[mi][3] = AsL[(ra + 8) * AK_ST + lc + 4];
        }
#pragma unroll
        for (int nj = 0; nj < 8; nj++) {
            int col = wn * 64 + nj * 8 + lr;
            uint32_t b0h = BsH[col * AK_ST + lc];
            uint32_t b1h = BsH[col * AK_ST + lc + 4];
            uint32_t b0l = BsL[col * AK_ST + lc];
            uint32_t b1l = BsL[col * AK_ST + lc + 4];
#pragma unroll
            for (int mi = 0; mi < 2; mi++) {
                mma_f16(acc[mi][nj], aH[mi], b0h, b1h);
                mma_f16(acc[mi][nj], aH[mi], b0l, b1l);
                mma_f16(acc[mi][nj], aL[mi], b0h, b1h);
            }
        }
        __syncthreads();
    }

#pragma unroll
    for (int mi = 0; mi < 2; mi++) {
        int row = row0 + wm * 32 + mi * 16 + lr;
#pragma unroll
        for (int nj = 0; nj < 8; nj++) {
            int col = col0 + wn * 64 + nj * 8 + 2 * lc;
            float* cp0 = C + (size_t)row * N + col;
            cp0[0] = acc[mi][nj][0];
            cp0[1] = acc[mi][nj][1];
            float* cp1 = C + (size_t)(row + 8) * N + col;
            cp1[0] = acc[mi][nj][2];
            cp1[1] = acc[mi][nj][3];
        }
    }
}

// ---------------- prep kernels ---------------------------------------------
__global__ void split_h2(const float* __restrict__ a, __half* __restrict__ h,
                         __half* __restrict__ l, int n4) {
    int i = blockIdx.x * 256 + threadIdx.x;
    if (i >= n4) return;
    float4 v = ((const float4*)a)[i];
    __half hx = __float2half_rn(v.x), hy = __float2half_rn(v.y);
    __half hz = __float2half_rn(v.z), hw = __float2half_rn(v.w);
    __half2 h0 = __halves2half2(hx, hy);
    __half2 h1 = __halves2half2(hz, hw);
    ((uint2*)h)[i] = make_uint2(*(uint32_t*)&h0, *(uint32_t*)&h1);
    __half2 l0 = __halves2half2(__float2half_rn(v.x - __half2float(hx)),
                                __float2half_rn(v.y - __half2float(hy)));
    __half2 l1 = __halves2half2(__float2half_rn(v.z - __half2float(hz)),
                                __float2half_rn(v.w - __half2float(hw)));
    ((uint2*)l)[i] = make_uint2(*(uint32_t*)&l0, *(uint32_t*)&l1);
}

__global__ void concat_transp_split(const float* __restrict__ wk, const float* __restrict__ wv,
                                    __half* __restrict__ th, __half* __restrict__ tl) {
    __shared__ float tile[32][33];
    int bx = blockIdx.x * 32;
    int by = blockIdx.y * 32;
    int tx = threadIdx.x, ty = threadIdx.y;
    for (int i = 0; i < 32; i += 8) {
        int col = bx + tx;
        float v = (col < 512) ? wk[(size_t)(by + ty + i) * 512 + col]
                              : wv[(size_t)(by + ty + i) * 512 + (col - 512)];
        tile[ty + i][tx] = v;
    }
    __syncthreads();
    for (int i = 0; i < 32; i += 8) {
        float v = tile[tx][ty + i];
        __half h = __float2half_rn(v);
        th[(size_t)(bx + ty + i) * DIM + by + tx] = h;
        tl[(size_t)(bx + ty + i) * DIM + by + tx] = __float2half_rn(v - __half2float(h));
    }
}

__global__ void transp_half(const float* __restrict__ w, __half* __restrict__ t) {
    __shared__ float tile[32][33];
    int bx = blockIdx.x * 32;
    int by = blockIdx.y * 32;
    int tx = threadIdx.x, ty = threadIdx.y;
    for (int i = 0; i < 32; i += 8)
        tile[ty + i][tx] = w[(size_t)(by + ty + i) * DIM + bx + tx];
    __syncthreads();
    for (int i = 0; i < 32; i += 8)
        t[(size_t)(bx + ty + i) * DIM + by + tx] = __float2half_rn(tile[tx][ty + i]);
}

// ---------------- exact fp32 q rows 0..63: split-K ---------------------------
__global__ __launch_bounds__(128) void qproj_part(const float* __restrict__ x,
                                                  const float* __restrict__ wq,
                                                  float* __restrict__ part) {
    __shared__ float xs[8][256];
    int tid = threadIdx.x;
    int col = blockIdx.x * 128 + tid;
    int r0 = blockIdx.y * 8;
    int k0 = blockIdx.z * 256;
    float acc[8];
#pragma unroll
    for (int rr = 0; rr < 8; rr++) acc[rr] = 0.f;

    for (int i = tid; i < 8 * 256; i += 128) {
        int rr = i >> 8, kk = i & 255;
        xs[rr][kk] = x[(size_t)(r0 + rr) * DIM + k0 + kk];
    }
    __syncthreads();
    for (int kk = 0; kk < 256; kk++) {
        float w = wq[(size_t)(k0 + kk) * DIM + col];
#pragma unroll
        for (int rr = 0; rr < 8; rr++) acc[rr] += xs[rr][kk] * w;
    }
#pragma unroll
    for (int rr = 0; rr < 8; rr++)
        part[(size_t)blockIdx.z * ESTQ * DIM + (size_t)(r0 + rr) * DIM + col] = acc[rr];
}

__global__ void qproj_red(const float* __restrict__ part, float* __restrict__ q64) {
    int idx = blockIdx.x * 256 + threadIdx.x;
    if (idx >= ESTQ * DIM) return;
    float s = 0.f;
#pragma unroll
    for (int ks = 0; ks < 8; ks++) s += part[(size_t)ks * ESTQ * DIM + idx];
    q64[idx] = s;
}

// ---------------- RoPE -------------------------------------------------------
__global__ void rope_kernel(float* t, const float* __restrict__ cosb,
                            const float* __restrict__ sinb, int H, int stride, int total) {
    int idx = blockIdx.x * blockDim.x + threadIdx.x;
    if (idx >= total) return;
    int d2 = idx & 31;
    int h = (idx >> 5) % H;
    int s = idx / (32 * H);
    float c = cosb[s * 32 + d2];
    float sn = sinb[s * 32 + d2];
    float* p = t + (size_t)s * stride + h * 64 + 2 * d2;
    float xr = p[0], xi = p[1];
    p[0] = xr * c - xi * sn;
    p[1] = xr * sn + xi * c;
}

// ---------------- est phase A -----------------------------------------------
__global__ __launch_bounds__(256) void est_score(const float* __restrict__ q64,
                                                 const float* __restrict__ kv,
                                                 float* __restrict__ probs) {
    __shared__ float qs[64][68];
    __shared__ float ksm[64][68];
    int tid = threadIdx.x;
    int h = blockIdx.y;
    int c0 = blockIdx.x * 64;
    int kvh = h >> 2;
    int qi = tid >> 2;
    int kg = tid & 3;

    for (int l = tid; l < 64 * 64; l += 256) {
        int r = l >> 6, d = l & 63;
        qs[r][d] = q64[(size_t)r * DIM + h * HD + d];
        ksm[r][d] = kv[(size_t)(c0 + r) * KVW + kvh * HD + d];
    }
    __syncthreads();

    float s16[16];
#pragma unroll
    for (int j = 0; j < 16; j++) s16[j] = 0.f;
#pragma unroll
    for (int d4 = 0; d4 < 16; d4++) {
        float4 q4 = *(float4*)&qs[qi][d4 * 4];
#pragma unroll
        for (int j = 0; j < 16; j++) {
            float4 k4 = *(float4*)&ksm[kg * 16 + j][d4 * 4];
            s16[j] += q4.x * k4.x + q4.y * k4.y + q4.z * k4.z + q4.w * k4.w;
        }
    }
    float* pr = probs + ((size_t)h * ESTQ + qi) * SEQ + c0 + kg * 16;
#pragma unroll
    for (int j = 0; j < 16; j++) {
        int kk = c0 + kg * 16 + j;
        float val = s16[j] * SCALE;
        if (kk >= SEQ - ESTQ && qi < kk - (SEQ - ESTQ)) val = -INFINITY;
        pr[j] = val;
    }
}

// ---------------- est phase B -------------------------------------------------
__global__ __launch_bounds__(256) void est_norm(float* __restrict__ probs) {
    int qi = blockIdx.x;
    int h = blockIdx.y;
    __shared__ float sc[SEQ];
    __shared__ float red[8];
    int tid = threadIdx.x;
    float* pr = probs + ((size_t)h * ESTQ + qi) * SEQ;

    for (int l = tid; l < SEQ / 4; l += 256)
        *(float4*)&sc[l * 4] = *(const float4*)&pr[l * 4];
    __syncthreads();

    float m = -INFINITY;
    for (int kk = tid; kk < SEQ; kk += 256) m = fmaxf(m, sc[kk]);
#pragma unroll
    for (int o = 16; o; o >>= 1) m = fmaxf(m, __shfl_xor_sync(0xFFFFFFFFu, m, o));
    if ((tid & 31) == 0) red[tid >> 5] = m;
    __syncthreads();
    if (tid == 0) {
        float mm = red[0];
#pragma unroll
        for (int i = 1; i < 8; i++) mm = fmaxf(mm, red[i]);
        red[0] = mm;
    }
    __syncthreads();
    m = red[0];
    __syncthreads();

    float s = 0.f;
    for (int kk = tid; kk < SEQ; kk += 256) {
        float e = expf(sc[kk] - m);
        sc[kk] = e;
        s += e;
    }
#pragma unroll
    for (int o = 16; o; o >>= 1) s += __shfl_xor_sync(0xFFFFFFFFu, s, o);
    if ((tid & 31) == 0) red[tid >> 5] = s;
    __syncthreads();
    if (tid == 0) {
        float ss = 0.f;
#pragma unroll
        for (int i = 0; i < 8; i++) ss += red[i];
        red[0] = ss;
    }
    __syncthreads();
    float inv = 1.f / red[0];
    for (int kk = tid; kk < SEQ; kk += 256) pr[kk] = sc[kk] * inv;
}

// ---------------- vertical / diagonal ------------------------------------------
__global__ void vertical_kernel(const float* __restrict__ probs, float* __restrict__ vert) {
    int idx = blockIdx.x * 256 + threadIdx.x;
    int h = idx >> 12;
    int kk = idx & (SEQ - 1);
    float s = 0.f;
    const float* base = probs + (size_t)h * ESTQ * SEQ + kk;
    for (int i = 0; i < ESTQ; i++) s += base[(size_t)i * SEQ];
    vert[idx] = s;
}

__global__ void diag_kernel(const float* __restrict__ probs, float* __restrict__ dg) {
    int idx = blockIdx.x * 256 + threadIdx.x;
    int h = idx >> 12;
    int jp = idx & (SEQ - 1);
    float s = 0.f;
    const float* base = probs + (size_t)h * ESTQ * SEQ;
    for (int i = 0; i < ESTQ; i++) {
        int col = i + jp - 63;
        if (col >= 0 && col < SEQ) s += base[(size_t)i * SEQ + col];
    }
    dg[idx] = s;
}

// ---------------- merged top-k ---------------------------------------------------
__global__ void topk2_kernel(const float* __restrict__ vert, const float* __restrict__ dg,
                             int* __restrict__ keys) {
    int b = blockIdx.x;
    int mode = b >> 5;
    int h = b & 31;
    const float* vals = mode ? dg : vert;
    int kcount = mode ? SSZ : VSZ;
    __shared__ unsigned long long a[SEQ];
    int tid = threadIdx.x;
    for (int i = tid; i < SEQ; i += 512) {
        unsigned u = __float_as_uint(vals[h * SEQ + i]);
        u = (u & 0x80000000u) ? ~u : (u | 0x80000000u);
        a[i] = ((unsigned long long)(~u) << 32) | (unsigned)i;
    }
    __syncthreads();
    for (int k = 2; k <= SEQ; k <<= 1) {
        for (int j = k >> 1; j > 0; j >>= 1) {
            for (int i = tid; i < SEQ; i += 512) {
                int ixj = i ^ j;
                if (ixj > i) {
                    bool up = ((i & k) == 0);
                    unsigned long long x = a[i], y = a[ixj];
                    if (up ? (x > y) : (x < y)) { a[i] = y; a[ixj] = x; }
                }
            }
            __syncthreads();
        }
    }
    if (mode == 0) {
        for (int t = tid; t < kcount; t += 512)
            keys[h * NKEYP + t] = (int)(a[t] & 0xFFFFFFFFull);
    } else {
        for (int t = tid; t < kcount; t += 512)
            keys[h * NKEYP + VSZ + t] = (SEQ - 1) - (int)(a[t] & 0xFFFFFFFFull);
        for (int t = NKEY + tid; t < NKEYP; t += 512) keys[h * NKEYP + t] = PADKEY;
    }
}

// ---------------- sort keys ascending per head ----------------------------------
__global__ __launch_bounds__(256) void sortkeys_kernel(int* __restrict__ keys) {
    int h = blockIdx.x;
    __shared__ int a[2048];
    int tid = threadIdx.x;
    for (int i = tid; i < 2048; i += 256)
        a[i] = (i < NKEYP) ? keys[h * NKEYP + i] : PADKEY;
    __syncthreads();
    for (int k = 2; k <= 2048; k <<= 1) {
        for (int j = k >> 1; j > 0; j >>= 1) {
            for (int i = tid; i < 2048; i += 256) {
                int ixj = i ^ j;
                if (ixj > i) {
                    bool up = ((i & k) == 0);
                    int x = a[i], y = a[ixj];
                    if (up ? (x > y) : (x < y)) { a[i] = y; a[ixj] = x; }
                }
            }
            __syncthreads();
        }
    }
    for (int i = tid; i < NKEYP; i += 256) keys[h * NKEYP + i] = a[i];
}

// ---------------- gather ----------------------------------------------------------
__global__ void gather_kernel(const float* __restrict__ kv,
                              const int* __restrict__ keys,
                              float* __restrict__ ksp, float* __restrict__ vsp) {
    int j = blockIdx.x;
    int h = j / NKEYP;
    int d = threadIdx.x;
    int key = keys[j];
    int kvh = h >> 2;
    float kvv = 0.f, vvv = 0.f;
    if (key < SEQ) {
        kvv = kv[(size_t)key * KVW + kvh * HD + d];
        vvv = kv[(size_t)key * KVW + 512 + kvh * HD + d];
    }
    ksp[(size_t)j * HD + d] = kvv;
    vsp[(size_t)j * HD + d] = vvv;
}

// ---------------- sparse attention v4: TC QK (3xTF32) + TC PV (fp16) -------------
// smem layout (u32 words):
//  qhl: 64*132   khl: 32*132   ss(f32): 64*36
//  psh(fp16): 64*20 words      vst(fp16): 64*20 words
//  keys_all: 1152   m_arr,l_arr,crow,vbar: 64 each   vbar4: 4*64   flag: 1
#define QHL_ST 132
#define SS_ST 36
#define PH_W 20
#define SPV_WORDS (64*132 + 32*132 + 64*36 + 64*20 + 64*20 + 1152 + 4*64 + 4*64 + 8)

__global__ __launch_bounds__(256) void spattn_kernel(const float* __restrict__ q,
                                                     const float* __restrict__ ksp,
                                                     const float* __restrict__ vsp,
                                                     const int* __restrict__ keys,
                                                     __half* __restrict__ attout) {
    extern __shared__ uint32_t smem[];
    uint32_t* qhl = smem;                         // 64*132
    uint32_t* khl = qhl + 64 * 132;               // 32*132
    float* ss = (float*)(khl + 32 * 132);         // 64*36
    uint32_t* psh = (uint32_t*)(ss + 64 * 36);    // 64*20 words
    uint32_t* vst = psh + 64 * PH_W;              // 64*20 words
    int* keys_all = (int*)(vst + 64 * PH_W);      // 1152
    float* m_arr = (float*)(keys_all + 1152);     // 64
    float* l_arr = m_arr + 64;                    // 64
    float* crow = l_arr + 64;                     // 64
    float* vbar = crow + 64;                      // 64
    float* vbar4 = vbar + 64;                     // 4*64
    int* anyflag = (int*)(vbar4 + 4 * 64);

    int qb = blockIdx.x;
    int h = blockIdx.y;
    int tid = threadIdx.x;
    int lane = tid & 31;
    int warp = tid >> 5;
    int lr = lane >> 2;
    int lc = lane & 3;
    int wm = warp & 3;
    int wn = warp >> 2;
    int qp = tid >> 3;
    int g = tid & 7;
    int qbmax = qb * 64 + 63;

    // preload all keys, init row state, load q tile (hi/lo tf32)
    for (int i = tid; i < NKEYP; i += 256) keys_all[i] = keys[h * NKEYP + i];
    if (tid < 64) { m_arr[tid] = -INFINITY; l_arr[tid] = 0.f; }
    if (tid == 0) *anyflag = 0;
    for (int l = tid; l < 64 * 16; l += 256) {
        int r = l >> 4, c4 = (l & 15) * 4;
        float4 v = *(const float4*)&q[(size_t)(qb * 64 + r) * DIM + h * HD + c4];
        uint32_t* dh = &qhl[r * QHL_ST + c4];
        uint32_t h0 = f2tf32(v.x), h1 = f2tf32(v.y), h2 = f2tf32(v.z), h3 = f2tf32(v.w);
        dh[0] = h0; dh[1] = h1; dh[2] = h2; dh[3] = h3;
        dh[64] = f2tf32(v.x - __uint_as_float(h0));
        dh[65] = f2tf32(v.y - __uint_as_float(h1));
        dh[66] = f2tf32(v.z - __uint_as_float(h2));
        dh[67] = f2tf32(v.w - __uint_as_float(h3));
    }
    __syncthreads();

    // PV accumulators (warp tile: rows wm*16..+15, cols wn*32..+31 -> 4 x m16n8)
    float pacc[4][4];
#pragma unroll
    for (int nt = 0; nt < 4; nt++)
#pragma unroll
        for (int e = 0; e < 4; e++) pacc[nt][e] = 0.f;

    for (int t = 0; t < NKEYP / 32; t++) {
        if (keys_all[t * 32] > qbmax) continue;  // block-uniform condition
        __syncthreads();  // protect prev tile's psh/vst/khl/ss from overwrite

        // load k tile (hi/lo tf32) and V^T tile (fp16)
        for (int l = tid; l < 32 * 16; l += 256) {
            int r = l >> 4, c4 = (l & 15) * 4;
            float4 kv = *(const float4*)&ksp[((size_t)h * NKEYP + t * 32 + r) * HD + c4];
            uint32_t* dh = &khl[r * QHL_ST + c4];
            uint32_t h0 = f2tf32(kv.x), h1 = f2tf32(kv.y), h2 = f2tf32(kv.z), h3 = f2tf32(kv.w);
            dh[0] = h0; dh[1] = h1; dh[2] = h2; dh[3] = h3;
            dh[64] = f2tf32(kv.x - __uint_as_float(h0));
            dh[65] = f2tf32(kv.y - __uint_as_float(h1));
            dh[66] = f2tf32(kv.z - __uint_as_float(h2));
            dh[67] = f2tf32(kv.w - __uint_as_float(h3));
        }
        {
            // V^T: vst[d][j] fp16; thread: j = tid>>3, d8 = (tid&7)*8
            int j = tid >> 3;
            int d8 = (tid & 7) * 8;
            const float* vr = &vsp[((size_t)h * NKEYP + t * 32 + j) * HD + d8];
            float4 v0 = *(const float4*)vr;
            float4 v1 = *(const float4*)(vr + 4);
            __half* vh = (__half*)vst;
#pragma unroll
            for (int i = 0; i < 4; i++)
                vh[(d8 + i) * (PH_W * 2) + j] = __float2half_rn(((const float*)&v0)[i]);
#pragma unroll
            for (int i = 0; i < 4; i++)
                vh[(d8 + 4 + i) * (PH_W * 2) + j] = __float2half_rn(((const float*)&v1)[i]);
        }
        __syncthreads();

        // QK MMA (3xTF32) -> masked scaled ss fp32
        {
            float acc[2][4];
#pragma unroll
            for (int nt = 0; nt < 2; nt++)
#pragma unroll
                for (int e = 0; e < 4; e++) acc[nt][e] = 0.f;
#pragma unroll
            for (int ksI = 0; ksI < 8; ksI++) {
                int kb = ksI * 8;
                int ra = wm * 16 + lr;
                uint32_t aH[4], aL[4];
                aH[0] = qhl[ra * QHL_ST + kb + lc];
                aH[1] = qhl[(ra + 8) * QHL_ST + kb + lc];
                aH[2] = qhl[ra * QHL_ST + kb + lc + 4];
                aH[3] = qhl[(ra + 8) * QHL_ST + kb + lc + 4];
                aL[0] = qhl[ra * QHL_ST + 64 + kb + lc];
                aL[1] = qhl[(ra + 8) * QHL_ST + 64 + kb + lc];
                aL[2] = qhl[ra * QHL_ST + 64 + kb + lc + 4];
                aL[3] = qhl[(ra + 8) * QHL_ST + 64 + kb + lc + 4];
#pragma unroll
                for (int nt = 0; nt < 2; nt++) {
                    int n0 = wn * 16 + nt * 8;
                    uint32_t b0h = khl[(n0 + lr) * QHL_ST + kb + lc];
                    uint32_t b1h = khl[(n0 + lr) * QHL_ST + kb + lc + 4];
                    uint32_t b0l = khl[(n0 + lr) * QHL_ST + 64 + kb + lc];
                    uint32_t b1l = khl[(n0 + lr) * QHL_ST + 64 + kb + lc + 4];
                    mma_tf32(acc[nt], aH, b0h, b1h);
                    mma_tf32(acc[nt], aH, b0l, b1l);
                    mma_tf32(acc[nt], aL, b0h, b1h);
                }
            }
#pragma unroll
            for (int nt = 0; nt < 2; nt++) {
                int row = wm * 16 + lr;
                int col = wn * 16 + nt * 8 + 2 * lc;
#pragma unroll
                for (int e = 0; e < 4; e++) {
                    int rr = row + (e >> 1) * 8;
                    int cc = col + (e & 1);
                    int key = keys_all[t * 32 + cc];
                    int sg = qb * 64 + rr;
                    float val;
                    if (key >= SEQ) val = -INFINITY;
                    else val = (key <= sg) ? acc[nt][e] * SCALE : -1e30f;
                    ss[rr * SS_ST + cc] = val;
                }
            }
        }
        __syncthreads();

        // row owners update m, crow, scale l
        if (tid < 64) {
            int r = tid;
            float tm = m_arr[r];
#pragma unroll
            for (int j = 0; j < 32; j++) tm = fmaxf(tm, ss[r * SS_ST + j]);
            float c = expf(m_arr[r] - tm);
            crow[r] = c;
            m_arr[r] = tm;
            l_arr[r] *= c;
        }
        __syncthreads();

        // all threads: exp -> psh fp16, row-sum via 8-lane shuffle, rescale pacc
        {
            int r0 = qp, r1 = qp + 32;
            float m0 = m_arr[r0], m1 = m_arr[r1];
            float ps0 = 0.f, ps1 = 0.f;
            __half* ph = (__half*)psh;
#pragma unroll
            for (int j = 0; j < 4; j++) {
                int cc = g * 4 + j;
                float e0 = expf(ss[r0 * SS_ST + cc] - m0);
                float e1 = expf(ss[r1 * SS_ST + cc] - m1);
                ph[r0 * (PH_W * 2) + cc] = __float2half_rn(e0);
                ph[r1 * (PH_W * 2) + cc] = __float2half_rn(e1);
                ps0 += e0; ps1 += e1;
            }
#pragma unroll
            for (int o = 4; o; o >>= 1) {
                ps0 += __shfl_down_sync(0xFFFFFFFFu, ps0, o, 8);
                ps1 += __shfl_down_sync(0xFFFFFFFFu, ps1, o, 8);
            }
            if (g == 0) { l_arr[r0] += ps0; l_arr[r1] += ps1; }
            // rescale PV accumulators by crow of fragment rows
            float c0 = crow[wm * 16 + lr];
            float c1 = crow[wm * 16 + lr + 8];
#pragma unroll
            for (int nt = 0; nt < 4; nt++) {
                pacc[nt][0] *= c0; pacc[nt][1] *= c0;
                pacc[nt][2] *= c1; pacc[nt][3] *= c1;
            }
        }
        __syncthreads();

        // PV MMA: D[16x32 per warp] += P[16x32] @ V^T[32x32cols]
        {
#pragma unroll
            for (int kb = 0; kb < 2; kb++) {
                int kw = kb * 8;
                int ra = wm * 16 + lr;
                uint32_t a[4];
                a[0] = psh[ra * PH_W + kw + lc];
                a[1] = psh[(ra + 8) * PH_W + kw + lc];
                a[2] = psh[ra * PH_W + kw + lc + 4];
                a[3] = psh[(ra + 8) * PH_W + kw + lc + 4];
#pragma unroll
                for (int nt = 0; nt < 4; nt++) {
                    int n0 = wn * 32 + nt * 8;
                    uint32_t b0 = vst[(n0 + lr) * PH_W + kw + lc];
                    uint32_t b1 = vst[(n0 + lr) * PH_W + kw + lc + 4];
                    mma_f16(pacc[nt], a, b0, b1);
                }
            }
        }
    }
    __syncthreads();  // l_arr final

    // fallback vbar for fully-masked rows (uniform over real keys)
    if (tid < 64 && m_arr[tid] < -5e29f) *anyflag = 1;
    __syncthreads();
    if (*anyflag) {
        int d = tid & 63, part = tid >> 6;
        float s = 0.f;
        for (int j = part; j < NKEYP; j += 4)
            if (keys_all[j] < SEQ) s += vsp[((size_t)h * NKEYP + j) * HD + d];
        vbar4[part * 64 + d] = s;
        __syncthreads();
        if (tid < 64)
            vbar[tid] = (vbar4[tid] + vbar4[64 + tid] + vbar4[128 + tid] + vbar4[192 + tid])
                        * (1.f / NKEY);
        __syncthreads();
    }

    // normalize + write fp16
    {
        int r0 = wm * 16 + lr, r1 = r0 + 8;
        float i0 = 1.f / l_arr[r0], i1 = 1.f / l_arr[r1];
        bool f0 = m_arr[r0] < -5e29f, f1 = m_arr[r1] < -5e29f;
        __half* o0 = &attout[(size_t)(qb * 64 + r0) * DIM + h * HD];
        __half* o1 = &attout[(size_t)(qb * 64 + r1) * DIM + h * HD];
#pragma unroll
        for (int nt = 0; nt < 4; nt++) {
            int col = wn * 32 + nt * 8 + 2 * lc;
            o0[col]     = __float2half_rn(f0 ? vbar[col]     : pacc[nt][0] * i0);
            o0[col + 1] = __float2half_rn(f0 ? vbar[col + 1] : pacc[nt][1] * i0);
            o1[col]     = __float2half_rn(f1 ? vbar[col]     : pacc[nt][2] * i1);
            o1[col + 1] = __float2half_rn(f1 ? vbar[col + 1] : pacc[nt][3] * i1);
        }
    }
}

// --------------------------------- launch --------------------------------
extern "C" void kernel_launch(void* const* d_in, const int* in_sizes, int n_in,
                              void* d_out, int out_size) {
    const float* x    = (const float*)d_in[0];
    const float* fcos = (const float*)d_in[1];
    const float* fsin = (const float*)d_in[2];
    const float* wq   = (const float*)d_in[3];
    const float* wk   = (const float*)d_in[4];
    const float* wv   = (const float*)d_in[5];
    const float* wo   = (const float*)d_in[6];
    float* out = (float*)d_out;

    float *q, *q64, *q64p, *kv, *probs, *vert, *dgp, *ksp, *vsp;
    int* keys;
    __half *xh, *xl, *atth, *wqt, *wot, *wkvtH, *wkvtL;
    cudaGetSymbolAddress((void**)&q, g_q);
    cudaGetSymbolAddress((void**)&q64, g_q64);
    cudaGetSymbolAddress((void**)&q64p, g_q64p);
    cudaGetSymbolAddress((void**)&kv, g_kv);
    cudaGetSymbolAddress((void**)&probs, g_probs);
    cudaGetSymbolAddress((void**)&vert, g_vert);
    cudaGetSymbolAddress((void**)&dgp, g_diag);
    cudaGetSymbolAddress((void**)&keys, g_keys);
    cudaGetSymbolAddress((void**)&ksp, g_ksp);
    cudaGetSymbolAddress((void**)&vsp, g_vsp);
    cudaGetSymbolAddress((void**)&xh, g_xh);
    cudaGetSymbolAddress((void**)&xl, g_xl);
    cudaGetSymbolAddress((void**)&atth, g_atth);
    cudaGetSymbolAddress((void**)&wqt, g_wqt);
    cudaGetSymbolAddress((void**)&wot, g_wot);
    cudaGetSymbolAddress((void**)&wkvtH, g_wkvtH);
    cudaGetSymbolAddress((void**)&wkvtL, g_wkvtL);

    // prep
    split_h2<<<(SEQ * DIM / 4 + 255) / 256, 256>>>(x, xh, xl, SEQ * DIM / 4);
    concat_transp_split<<<dim3(KVW / 32, DIM / 32), dim3(32, 8)>>>(wk, wv, wkvtH, wkvtL);
    transp_half<<<dim3(DIM / 32, DIM / 32), dim3(32, 8)>>>(wq, wqt);
    transp_half<<<dim3(DIM / 32, DIM / 32), dim3(32, 8)>>>(wo, wot);

    // projections
    gemm_f16<<<dim3(DIM / 128, SEQ / 128), 256>>>(xh, wqt, q, SEQ, DIM, DIM);
    {
        size_t smb = (size_t)(2 * STG2W) * 4;
        cudaFuncSetAttribute(gemm_f16x3, cudaFuncAttributeMaxDynamicSharedMemorySize,
                             (int)smb);
        gemm_f16x3<<<dim3(KVW / 128, SEQ / 128), 256, smb>>>(
            xh, xl, wkvtH, wkvtL, kv, SEQ, KVW, DIM);
    }

    // exact fp32 q rows 0..63
    qproj_part<<<dim3(16, 8, 8), 128>>>(x, wq, q64p);
    qproj_red<<<(ESTQ * DIM + 255) / 256, 256>>>(q64p, q64);

    // RoPE
    {
        int tq = SEQ * NH * 32;
        rope_kernel<<<(tq + 255) / 256, 256>>>(q, fcos, fsin, NH, DIM, tq);
        int tk = SEQ * NKV * 32;
        rope_kernel<<<(tk + 255) / 256, 256>>>(kv, fcos, fsin, NKV, KVW, tk);
        int tq64 = ESTQ * NH * 32;
        rope_kernel<<<(tq64 + 255) / 256, 256>>>(q64, fcos, fsin, NH, DIM, tq64);
    }

    // estimation
    est_score<<<dim3(SEQ / 64, NH), 256>>>(q64, kv, probs);
    est_norm<<<dim3(ESTQ, NH), 256>>>(probs);

    vertical_kernel<<<(NH * SEQ) / 256, 256>>>(probs, vert);
    diag_kernel<<<(NH * SEQ) / 256, 256>>>(probs, dgp);

    topk2_kernel<<<64, 512>>>(vert, dgp, keys);
    sortkeys_kernel<<<NH, 256>>>(keys);

    gather_kernel<<<NH * NKEYP, 64>>>(kv, keys, ksp, vsp);

    {
        size_t spbytes = (size_t)SPV_WORDS * 4;
        cudaFuncSetAttribute(spattn_kernel,
                             cudaFuncAttributeMaxDynamicSharedMemorySize, (int)spbytes);
        spattn_kernel<<<dim3(SEQ / 64, NH), 256, spbytes>>>(q, ksp, vsp, keys, atth);
    }

    // output projection
    gemm_f16<<<dim3(DIM / 128, SEQ / 128), 256>>>(atth, wot, out, SEQ, DIM, DIM);
}

// round 15
// speedup vs baseline: 2.3307x; 1.1726x over previous
#include <cuda_runtime.h>
#include <cuda_fp16.h>
#include <math.h>
#include <stdint.h>

#define SEQ   4096
#define DIM   2048
#define NH    32
#define NKV   8
#define HD    64
#define ESTQ  64
#define VSZ   300
#define SSZ   800
#define NKEY  1100
#define NKEYP 1152
#define SCALE 0.125f
#define PADKEY 0x3FFFFFFF
#define KVW   1024

// ---------------- device scratch ----------------
__device__ float g_q[SEQ * DIM];
__device__ float g_q64[ESTQ * DIM];
__device__ float g_q64p[8 * ESTQ * DIM];
__device__ float g_kv[SEQ * KVW];
__device__ float g_probs[NH * ESTQ * SEQ];
__device__ float g_vert[NH * SEQ];
__device__ float g_diag[NH * SEQ];
__device__ int   g_keys[NH * NKEYP];
__device__ float g_ksp[NH * NKEYP * HD];
__device__ float g_vsp[NH * NKEYP * HD];
__device__ __half g_xh[SEQ * DIM];
__device__ __half g_xl[SEQ * DIM];
__device__ __half g_atth[SEQ * DIM];
__device__ __half g_wqt[DIM * DIM];
__device__ __half g_wot[DIM * DIM];
__device__ __half g_wkvtH[KVW * DIM];
__device__ __half g_wkvtL[KVW * DIM];

// ---------------- helpers ------------------------------------------------
__device__ __forceinline__ uint32_t f2tf32(float f) {
    uint32_t r;
    asm("cvt.rna.tf32.f32 %0, %1;" : "=r"(r) : "f"(f));
    return r;
}

__device__ __forceinline__ void mma_tf32(float c[4], const uint32_t a[4],
                                         uint32_t b0, uint32_t b1) {
    asm volatile(
        "mma.sync.aligned.m16n8k8.row.col.f32.tf32.tf32.f32 "
        "{%0,%1,%2,%3}, {%4,%5,%6,%7}, {%8,%9}, {%0,%1,%2,%3};\n"
        : "+f"(c[0]), "+f"(c[1]), "+f"(c[2]), "+f"(c[3])
        : "r"(a[0]), "r"(a[1]), "r"(a[2]), "r"(a[3]), "r"(b0), "r"(b1));
}

__device__ __forceinline__ void mma_f16(float c[4], const uint32_t a[4],
                                        uint32_t b0, uint32_t b1) {
    asm volatile(
        "mma.sync.aligned.m16n8k16.row.col.f32.f16.f16.f32 "
        "{%0,%1,%2,%3}, {%4,%5,%6,%7}, {%8,%9}, {%0,%1,%2,%3};\n"
        : "+f"(c[0]), "+f"(c[1]), "+f"(c[2]), "+f"(c[3])
        : "r"(a[0]), "r"(a[1]), "r"(a[2]), "r"(a[3]), "r"(b0), "r"(b1));
}

__device__ __forceinline__ uint32_t smem_u32(const void* p) {
    uint32_t a;
    asm("{ .reg .u64 t; cvta.to.shared.u64 t, %1; cvt.u32.u64 %0, t; }" : "=r"(a) : "l"(p));
    return a;
}

// ================= fp16 k16 GEMM with cp.async double buffering ===========
#define AF_ST 20

__global__ __launch_bounds__(256) void gemm_f16(const __half* __restrict__ A,
                                                const __half* __restrict__ Bt,
                                                float* __restrict__ C,
                                                int M, int N, int K) {
    __shared__ uint32_t As[2][128 * AF_ST];
    __shared__ uint32_t Bs[2][128 * AF_ST];
    int tid = threadIdx.x;
    int lane = tid & 31;
    int warp = tid >> 5;
    int wm = warp & 3;
    int wn = warp >> 2;
    int row0 = blockIdx.y * 128;
    int col0 = blockIdx.x * 128;
    int lr = lane >> 2;
    int lc = lane & 3;

    uint32_t asb[2], bsb[2];
    asb[0] = smem_u32(&As[0][0]);
    asb[1] = smem_u32(&As[1][0]);
    bsb[0] = smem_u32(&Bs[0][0]);
    bsb[1] = smem_u32(&Bs[1][0]);

    float acc[2][8][4];
#pragma unroll
    for (int mi = 0; mi < 2; mi++)
#pragma unroll
        for (int nj = 0; nj < 8; nj++)
#pragma unroll
            for (int e = 0; e < 4; e++) acc[mi][nj][e] = 0.f;

    int r_ld = tid >> 2;
    int j_ld = tid & 3;

    {
#pragma unroll
        for (int i = 0; i < 2; i++) {
            int r = r_ld + i * 64;
            uint32_t da = asb[0] + (uint32_t)(r * AF_ST + j_ld * 4) * 4;
            const __half* sa = A + (size_t)(row0 + r) * K + j_ld * 8;
            asm volatile("cp.async.ca.shared.global [%0], [%1], 16;" :: "r"(da), "l"(sa));
            uint32_t db = bsb[0] + (uint32_t)(r * AF_ST + j_ld * 4) * 4;
            const __half* sb = Bt + (size_t)(col0 + r) * K + j_ld * 8;
            asm volatile("cp.async.ca.shared.global [%0], [%1], 16;" :: "r"(db), "l"(sb));
        }
        asm volatile("cp.async.commit_group;");
    }

    int KC = K >> 5;
    for (int c = 0; c < KC; c++) {
        int buf = c & 1;
        if (c + 1 < KC) {
            int k0 = (c + 1) << 5;
            int nb = buf ^ 1;
#pragma unroll
            for (int i = 0; i < 2; i++) {
                int r = r_ld + i * 64;
                uint32_t da = asb[nb] + (uint32_t)(r * AF_ST + j_ld * 4) * 4;
                const __half* sa = A + (size_t)(row0 + r) * K + k0 + j_ld * 8;
                asm volatile("cp.async.ca.shared.global [%0], [%1], 16;" :: "r"(da), "l"(sa));
                uint32_t db = bsb[nb] + (uint32_t)(r * AF_ST + j_ld * 4) * 4;
                const __half* sb = Bt + (size_t)(col0 + r) * K + k0 + j_ld * 8;
                asm volatile("cp.async.ca.shared.global [%0], [%1], 16;" :: "r"(db), "l"(sb));
            }
            asm volatile("cp.async.commit_group;");
            asm volatile("cp.async.wait_group 1;");
        } else {
            asm volatile("cp.async.wait_group 0;");
        }
        __syncthreads();

        const uint32_t* Ab = As[buf];
        const uint32_t* Bb = Bs[buf];
#pragma unroll
        for (int ks = 0; ks < 2; ks++) {
            int kb = ks * 8;
            uint32_t a[2][4];
#pragma unroll
            for (int mi = 0; mi < 2; mi++) {
                int ra = wm * 32 + mi * 16 + lr;
                a[mi][0] = Ab[ra * AF_ST + kb + lc];
                a[mi][1] = Ab[(ra + 8) * AF_ST + kb + lc];
                a[mi][2] = Ab[ra * AF_ST + kb + lc + 4];
                a[mi][3] = Ab[(ra + 8) * AF_ST + kb + lc + 4];
            }
#pragma unroll
            for (int nj = 0; nj < 8; nj++) {
                int col = wn * 64 + nj * 8 + lr;
                uint32_t b0 = Bb[col * AF_ST + kb + lc];
                uint32_t b1 = Bb[col * AF_ST + kb + lc + 4];
                mma_f16(acc[0][nj], a[0], b0, b1);
                mma_f16(acc[1][nj], a[1], b0, b1);
            }
        }
        __syncthreads();
    }

#pragma unroll
    for (int mi = 0; mi < 2; mi++) {
        int row = row0 + wm * 32 + mi * 16 + lr;
#pragma unroll
        for (int nj = 0; nj < 8; nj++) {
            int col = col0 + wn * 64 + nj * 8 + 2 * lc;
            float* cp0 = C + (size_t)row * N + col;
            cp0[0] = acc[mi][nj][0];
            cp0[1] = acc[mi][nj][1];
            float* cp1 = C + (size_t)(row + 8) * N + col;
            cp1[0] = acc[mi][nj][2];
            cp1[1] = acc[mi][nj][3];
        }
    }
}

// ===== fp16 hi/lo 3-term GEMM, BK=16 (kv projection) =====
#define AK_ST 12
#define STG2W (4 * 128 * AK_ST)

__global__ __launch_bounds__(256) void gemm_f16x3(const __half* __restrict__ AH,
                                                  const __half* __restrict__ AL,
                                                  const __half* __restrict__ BH,
                                                  const __half* __restrict__ BL,
                                                  float* __restrict__ C,
                                                  int M, int N, int K) {
    extern __shared__ uint32_t sm[];
    uint32_t base = smem_u32(sm);
    int tid = threadIdx.x;
    int lane = tid & 31;
    int warp = tid >> 5;
    int wm = warp & 3;
    int wn = warp >> 2;
    int row0 = blockIdx.y * 128;
    int col0 = blockIdx.x * 128;
    int lr = lane >> 2;
    int lc = lane & 3;

    float acc[2][8][4];
#pragma unroll
    for (int mi = 0; mi < 2; mi++)
#pragma unroll
        for (int nj = 0; nj < 8; nj++)
#pragma unroll
            for (int e = 0; e < 4; e++) acc[mi][nj][e] = 0.f;

    int r_ld = tid >> 1;
    int j_ld = tid & 1;

    auto issue = [&](int stage, int k0) {
        uint32_t sb = base + (uint32_t)stage * STG2W * 4;
        uint32_t off = (uint32_t)(r_ld * AK_ST + j_ld * 4) * 4;
        const __half* pa = AH + (size_t)(row0 + r_ld) * K + k0 + j_ld * 8;
        asm volatile("cp.async.ca.shared.global [%0], [%1], 16;" :: "r"(sb + off), "l"(pa));
        const __half* pl = AL + (size_t)(row0 + r_ld) * K + k0 + j_ld * 8;
        asm volatile("cp.async.ca.shared.global [%0], [%1], 16;"
                     :: "r"(sb + (uint32_t)(128 * AK_ST) * 4 + off), "l"(pl));
        const __half* pb = BH + (size_t)(col0 + r_ld) * K + k0 + j_ld * 8;
        asm volatile("cp.async.ca.shared.global [%0], [%1], 16;"
                     :: "r"(sb + (uint32_t)(2 * 128 * AK_ST) * 4 + off), "l"(pb));
        const __half* pc = BL + (size_t)(col0 + r_ld) * K + k0 + j_ld * 8;
        asm volatile("cp.async.ca.shared.global [%0], [%1], 16;"
                     :: "r"(sb + (uint32_t)(3 * 128 * AK_ST) * 4 + off), "l"(pc));
        asm volatile("cp.async.commit_group;");
    };

    issue(0, 0);

    int KC = K >> 4;
    for (int c = 0; c < KC; c++) {
        int buf = c & 1;
        if (c + 1 < KC) {
            issue(buf ^ 1, (c + 1) << 4);
            asm volatile("cp.async.wait_group 1;");
        } else {
            asm volatile("cp.async.wait_group 0;");
        }
        __syncthreads();

        const uint32_t* AsH = sm + (size_t)buf * STG2W;
        const uint32_t* AsL = AsH + 128 * AK_ST;
        const uint32_t* BsH = AsH + 2 * 128 * AK_ST;
        const uint32_t* BsL = AsH + 3 * 128 * AK_ST;
        uint32_t aH[2][4], aL[2][4];
#pragma unroll
        for (int mi = 0; mi < 2; mi++) {
            int ra = wm * 32 + mi * 16 + lr;
            aH[mi][0] = AsH[ra * AK_ST + lc];
            aH[mi][1] = AsH[(ra + 8) * AK_ST + lc];
            aH[mi][2] = AsH[ra * AK_ST + lc + 4];
            aH[mi][3] = AsH[(ra + 8) * AK_ST + lc + 4];
            aL[mi][0] = AsL[ra * AK_ST + lc];
            aL[mi][1] = AsL[(ra + 8) * AK_ST + lc];
            aL[mi][2] = AsL[ra * AK_ST + lc + 4];
            aL[mi][3] = AsL[(ra + 8) * AK_ST + lc + 4];
        }
#pragma unroll
        for (int nj = 0; nj < 8; nj++) {
            int col = wn * 64 + nj * 8 + lr;
            uint32_t b0h = BsH[col * AK_ST + lc];
            uint32_t b1h = BsH[col * AK_ST + lc + 4];
            uint32_t b0l = BsL[col * AK_ST + lc];
            uint32_t b1l = BsL[col * AK_ST + lc + 4];
#pragma unroll
            for (int mi = 0; mi < 2; mi++) {
                mma_f16(acc[mi][nj], aH[mi], b0h, b1h);
                mma_f16(acc[mi][nj], aH[mi], b0l, b1l);
                mma_f16(acc[mi][nj], aL[mi], b0h, b1h);
            }
        }
        __syncthreads();
    }

#pragma unroll
    for (int mi = 0; mi < 2; mi++) {
        int row = row0 + wm * 32 + mi * 16 + lr;
#pragma unroll
        for (int nj = 0; nj < 8; nj++) {
            int col = col0 + wn * 64 + nj * 8 + 2 * lc;
            float* cp0 = C + (size_t)row * N + col;
            cp0[0] = acc[mi][nj][0];
            cp0[1] = acc[mi][nj][1];
            float* cp1 = C + (size_t)(row + 8) * N + col;
            cp1[0] = acc[mi][nj][2];
            cp1[1] = acc[mi][nj][3];
        }
    }
}

// ---------------- prep kernels ---------------------------------------------
__global__ void split_h2(const float* __restrict__ a, __half* __restrict__ h,
                         __half* __restrict__ l, int n4) {
    int i = blockIdx.x * 256 + threadIdx.x;
    if (i >= n4) return;
    float4 v = ((const float4*)a)[i];
    __half hx = __float2half_rn(v.x), hy = __float2half_rn(v.y);
    __half hz = __float2half_rn(v.z), hw = __float2half_rn(v.w);
    __half2 h0 = __halves2half2(hx, hy);
    __half2 h1 = __halves2half2(hz, hw);
    ((uint2*)h)[i] = make_uint2(*(uint32_t*)&h0, *(uint32_t*)&h1);
    __half2 l0 = __halves2half2(__float2half_rn(v.x - __half2float(hx)),
                                __float2half_rn(v.y - __half2float(hy)));
    __half2 l1 = __halves2half2(__float2half_rn(v.z - __half2float(hz)),
                                __float2half_rn(v.w - __half2float(hw)));
    ((uint2*)l)[i] = make_uint2(*(uint32_t*)&l0, *(uint32_t*)&l1);
}

__global__ void concat_transp_split(const float* __restrict__ wk, const float* __restrict__ wv,
                                    __half* __restrict__ th, __half* __restrict__ tl) {
    __shared__ float tile[32][33];
    int bx = blockIdx.x * 32;
    int by = blockIdx.y * 32;
    int tx = threadIdx.x, ty = threadIdx.y;
    for (int i = 0; i < 32; i += 8) {
        int col = bx + tx;
        float v = (col < 512) ? wk[(size_t)(by + ty + i) * 512 + col]
                              : wv[(size_t)(by + ty + i) * 512 + (col - 512)];
        tile[ty + i][tx] = v;
    }
    __syncthreads();
    for (int i = 0; i < 32; i += 8) {
        float v = tile[tx][ty + i];
        __half h = __float2half_rn(v);
        th[(size_t)(bx + ty + i) * DIM + by + tx] = h;
        tl[(size_t)(bx + ty + i) * DIM + by + tx] = __float2half_rn(v - __half2float(h));
    }
}

__global__ void transp_half(const float* __restrict__ w, __half* __restrict__ t) {
    __shared__ float tile[32][33];
    int bx = blockIdx.x * 32;
    int by = blockIdx.y * 32;
    int tx = threadIdx.x, ty = threadIdx.y;
    for (int i = 0; i < 32; i += 8)
        tile[ty + i][tx] = w[(size_t)(by + ty + i) * DIM + bx + tx];
    __syncthreads();
    for (int i = 0; i < 32; i += 8)
        t[(size_t)(bx + ty + i) * DIM + by + tx] = __float2half_rn(tile[tx][ty + i]);
}

// ---------------- exact fp32 q rows 0..63: split-K ---------------------------
__global__ __launch_bounds__(128) void qproj_part(const float* __restrict__ x,
                                                  const float* __restrict__ wq,
                                                  float* __restrict__ part) {
    __shared__ float xs[8][256];
    int tid = threadIdx.x;
    int col = blockIdx.x * 128 + tid;
    int r0 = blockIdx.y * 8;
    int k0 = blockIdx.z * 256;
    float acc[8];
#pragma unroll
    for (int rr = 0; rr < 8; rr++) acc[rr] = 0.f;

    for (int i = tid; i < 8 * 256; i += 128) {
        int rr = i >> 8, kk = i & 255;
        xs[rr][kk] = x[(size_t)(r0 + rr) * DIM + k0 + kk];
    }
    __syncthreads();
    for (int kk = 0; kk < 256; kk++) {
        float w = wq[(size_t)(k0 + kk) * DIM + col];
#pragma unroll
        for (int rr = 0; rr < 8; rr++) acc[rr] += xs[rr][kk] * w;
    }
#pragma unroll
    for (int rr = 0; rr < 8; rr++)
        part[(size_t)blockIdx.z * ESTQ * DIM + (size_t)(r0 + rr) * DIM + col] = acc[rr];
}

__global__ void qproj_red(const float* __restrict__ part, float* __restrict__ q64) {
    int idx = blockIdx.x * 256 + threadIdx.x;
    if (idx >= ESTQ * DIM) return;
    float s = 0.f;
#pragma unroll
    for (int ks = 0; ks < 8; ks++) s += part[(size_t)ks * ESTQ * DIM + idx];
    q64[idx] = s;
}

// ---------------- RoPE -------------------------------------------------------
__global__ void rope_kernel(float* t, const float* __restrict__ cosb,
                            const float* __restrict__ sinb, int H, int stride, int total) {
    int idx = blockIdx.x * blockDim.x + threadIdx.x;
    if (idx >= total) return;
    int d2 = idx & 31;
    int h = (idx >> 5) % H;
    int s = idx / (32 * H);
    float c = cosb[s * 32 + d2];
    float sn = sinb[s * 32 + d2];
    float* p = t + (size_t)s * stride + h * 64 + 2 * d2;
    float xr = p[0], xi = p[1];
    p[0] = xr * c - xi * sn;
    p[1] = xr * sn + xi * c;
}

// ---------------- est phase A: TC scores (fp16 hi/lo 3-term) ------------------
// grid (SEQ/64, NH), 256 thr. S[64q][64k] per block, K=64.
#define ES_ST 36

__global__ __launch_bounds__(256) void est_score(const float* __restrict__ q64,
                                                 const float* __restrict__ kv,
                                                 float* __restrict__ probs) {
    __shared__ uint32_t qh[64 * ES_ST];
    __shared__ uint32_t ql[64 * ES_ST];
    __shared__ uint32_t kh[64 * ES_ST];
    __shared__ uint32_t kl[64 * ES_ST];
    int tid = threadIdx.x;
    int lane = tid & 31;
    int warp = tid >> 5;
    int lr = lane >> 2;
    int lc = lane & 3;
    int wm = warp & 3;   // 16-row slab
    int wn = warp >> 2;  // 32-col slab
    int h = blockIdx.y;
    int c0 = blockIdx.x * 64;
    int kvh = h >> 2;

    // load + split q (64x64) and k (64x64) to fp16 hi/lo
    for (int l = tid; l < 64 * 16; l += 256) {
        int r = l >> 4, c4 = (l & 15) * 4;
        float4 v = *(const float4*)&q64[(size_t)r * DIM + h * HD + c4];
        __half hx = __float2half_rn(v.x), hy = __float2half_rn(v.y);
        __half hz = __float2half_rn(v.z), hw = __float2half_rn(v.w);
        __half2 p0 = __halves2half2(hx, hy);
        __half2 p1 = __halves2half2(hz, hw);
        qh[r * ES_ST + c4 / 2] = *(uint32_t*)&p0;
        qh[r * ES_ST + c4 / 2 + 1] = *(uint32_t*)&p1;
        __half2 q0 = __halves2half2(__float2half_rn(v.x - __half2float(hx)),
                                    __float2half_rn(v.y - __half2float(hy)));
        __half2 q1 = __halves2half2(__float2half_rn(v.z - __half2float(hz)),
                                    __float2half_rn(v.w - __half2float(hw)));
        ql[r * ES_ST + c4 / 2] = *(uint32_t*)&q0;
        ql[r * ES_ST + c4 / 2 + 1] = *(uint32_t*)&q1;

        float4 kvv = *(const float4*)&kv[(size_t)(c0 + r) * KVW + kvh * HD + c4];
        __half kx = __float2half_rn(kvv.x), ky = __float2half_rn(kvv.y);
        __half kz = __float2half_rn(kvv.z), kw = __float2half_rn(kvv.w);
        __half2 r0 = __halves2half2(kx, ky);
        __half2 r1 = __halves2half2(kz, kw);
        kh[r * ES_ST + c4 / 2] = *(uint32_t*)&r0;
        kh[r * ES_ST + c4 / 2 + 1] = *(uint32_t*)&r1;
        __half2 s0 = __halves2half2(__float2half_rn(kvv.x - __half2float(kx)),
                                    __float2half_rn(kvv.y - __half2float(ky)));
        __half2 s1 = __halves2half2(__float2half_rn(kvv.z - __half2float(kz)),
                                    __float2half_rn(kvv.w - __half2float(kw)));
        kl[r * ES_ST + c4 / 2] = *(uint32_t*)&s0;
        kl[r * ES_ST + c4 / 2 + 1] = *(uint32_t*)&s1;
    }
    __syncthreads();

    // warp tile: rows wm*16..+15, cols wn*32..+31 (4 x m16n8), K=64 = 4 k16 chunks
    float acc[4][4];
#pragma unroll
    for (int nt = 0; nt < 4; nt++)
#pragma unroll
        for (int e = 0; e < 4; e++) acc[nt][e] = 0.f;

#pragma unroll
    for (int kc = 0; kc < 4; kc++) {
        int kw = kc * 8;
        int ra = wm * 16 + lr;
        uint32_t aH[4], aL[4];
        aH[0] = qh[ra * ES_ST + kw + lc];
        aH[1] = qh[(ra + 8) * ES_ST + kw + lc];
        aH[2] = qh[ra * ES_ST + kw + lc + 4];
        aH[3] = qh[(ra + 8) * ES_ST + kw + lc + 4];
        aL[0] = ql[ra * ES_ST + kw + lc];
        aL[1] = ql[(ra + 8) * ES_ST + kw + lc];
        aL[2] = ql[ra * ES_ST + kw + lc + 4];
        aL[3] = ql[(ra + 8) * ES_ST + kw + lc + 4];
#pragma unroll
        for (int nt = 0; nt < 4; nt++) {
            int n0 = wn * 32 + nt * 8;
            uint32_t b0h = kh[(n0 + lr) * ES_ST + kw + lc];
            uint32_t b1h = kh[(n0 + lr) * ES_ST + kw + lc + 4];
            uint32_t b0l = kl[(n0 + lr) * ES_ST + kw + lc];
            uint32_t b1l = kl[(n0 + lr) * ES_ST + kw + lc + 4];
            mma_f16(acc[nt], aH, b0h, b1h);
            mma_f16(acc[nt], aH, b0l, b1l);
            mma_f16(acc[nt], aL, b0h, b1h);
        }
    }

    // epilogue: scale + tail mask, write probs
#pragma unroll
    for (int nt = 0; nt < 4; nt++) {
        int row = wm * 16 + lr;
        int col = wn * 32 + nt * 8 + 2 * lc;
#pragma unroll
        for (int e = 0; e < 4; e++) {
            int rr = row + (e >> 1) * 8;
            int cc = col + (e & 1);
            int kk = c0 + cc;
            float val = acc[nt][e] * SCALE;
            if (kk >= SEQ - ESTQ && rr < kk - (SEQ - ESTQ)) val = -INFINITY;
            probs[((size_t)h * ESTQ + rr) * SEQ + kk] = val;
        }
    }
}

// ---------------- est phase B -------------------------------------------------
__global__ __launch_bounds__(256) void est_norm(float* __restrict__ probs) {
    int qi = blockIdx.x;
    int h = blockIdx.y;
    __shared__ float sc[SEQ];
    __shared__ float red[8];
    int tid = threadIdx.x;
    float* pr = probs + ((size_t)h * ESTQ + qi) * SEQ;

    for (int l = tid; l < SEQ / 4; l += 256)
        *(float4*)&sc[l * 4] = *(const float4*)&pr[l * 4];
    __syncthreads();

    float m = -INFINITY;
    for (int kk = tid; kk < SEQ; kk += 256) m = fmaxf(m, sc[kk]);
#pragma unroll
    for (int o = 16; o; o >>= 1) m = fmaxf(m, __shfl_xor_sync(0xFFFFFFFFu, m, o));
    if ((tid & 31) == 0) red[tid >> 5] = m;
    __syncthreads();
    if (tid == 0) {
        float mm = red[0];
#pragma unroll
        for (int i = 1; i < 8; i++) mm = fmaxf(mm, red[i]);
        red[0] = mm;
    }
    __syncthreads();
    m = red[0];
    __syncthreads();

    float s = 0.f;
    for (int kk = tid; kk < SEQ; kk += 256) {
        float e = expf(sc[kk] - m);
        sc[kk] = e;
        s += e;
    }
#pragma unroll
    for (int o = 16; o; o >>= 1) s += __shfl_xor_sync(0xFFFFFFFFu, s, o);
    if ((tid & 31) == 0) red[tid >> 5] = s;
    __syncthreads();
    if (tid == 0) {
        float ss = 0.f;
#pragma unroll
        for (int i = 0; i < 8; i++) ss += red[i];
        red[0] = ss;
    }
    __syncthreads();
    float inv = 1.f / red[0];
    for (int kk = tid; kk < SEQ; kk += 256) pr[kk] = sc[kk] * inv;
}

// ---------------- vertical / diagonal ------------------------------------------
__global__ void vertical_kernel(const float* __restrict__ probs, float* __restrict__ vert) {
    int idx = blockIdx.x * 256 + threadIdx.x;
    int h = idx >> 12;
    int kk = idx & (SEQ - 1);
    float s = 0.f;
    const float* base = probs + (size_t)h * ESTQ * SEQ + kk;
    for (int i = 0; i < ESTQ; i++) s += base[(size_t)i * SEQ];
    vert[idx] = s;
}

__global__ void diag_kernel(const float* __restrict__ probs, float* __restrict__ dg) {
    int idx = blockIdx.x * 256 + threadIdx.x;
    int h = idx >> 12;
    int jp = idx & (SEQ - 1);
    float s = 0.f;
    const float* base = probs + (size_t)h * ESTQ * SEQ;
    for (int i = 0; i < ESTQ; i++) {
        int col = i + jp - 63;
        if (col >= 0 && col < SEQ) s += base[(size_t)i * SEQ + col];
    }
    dg[idx] = s;
}

// ---------------- merged top-k ---------------------------------------------------
__global__ void topk2_kernel(const float* __restrict__ vert, const float* __restrict__ dg,
                             int* __restrict__ keys) {
    int b = blockIdx.x;
    int mode = b >> 5;
    int h = b & 31;
    const float* vals = mode ? dg : vert;
    int kcount = mode ? SSZ : VSZ;
    __shared__ unsigned long long a[SEQ];
    int tid = threadIdx.x;
    for (int i = tid; i < SEQ; i += 512) {
        unsigned u = __float_as_uint(vals[h * SEQ + i]);
        u = (u & 0x80000000u) ? ~u : (u | 0x80000000u);
        a[i] = ((unsigned long long)(~u) << 32) | (unsigned)i;
    }
    __syncthreads();
    for (int k = 2; k <= SEQ; k <<= 1) {
        for (int j = k >> 1; j > 0; j >>= 1) {
            for (int i = tid; i < SEQ; i += 512) {
                int ixj = i ^ j;
                if (ixj > i) {
                    bool up = ((i & k) == 0);
                    unsigned long long x = a[i], y = a[ixj];
                    if (up ? (x > y) : (x < y)) { a[i] = y; a[ixj] = x; }
                }
            }
            __syncthreads();
        }
    }
    if (mode == 0) {
        for (int t = tid; t < kcount; t += 512)
            keys[h * NKEYP + t] = (int)(a[t] & 0xFFFFFFFFull);
    } else {
        for (int t = tid; t < kcount; t += 512)
            keys[h * NKEYP + VSZ + t] = (SEQ - 1) - (int)(a[t] & 0xFFFFFFFFull);
        for (int t = NKEY + tid; t < NKEYP; t += 512) keys[h * NKEYP + t] = PADKEY;
    }
}

// ---------------- sort keys ascending per head ----------------------------------
__global__ __launch_bounds__(256) void sortkeys_kernel(int* __restrict__ keys) {
    int h = blockIdx.x;
    __shared__ int a[2048];
    int tid = threadIdx.x;
    for (int i = tid; i < 2048; i += 256)
        a[i] = (i < NKEYP) ? keys[h * NKEYP + i] : PADKEY;
    __syncthreads();
    for (int k = 2; k <= 2048; k <<= 1) {
        for (int j = k >> 1; j > 0; j >>= 1) {
            for (int i = tid; i < 2048; i += 256) {
                int ixj = i ^ j;
                if (ixj > i) {
                    bool up = ((i & k) == 0);
                    int x = a[i], y = a[ixj];
                    if (up ? (x > y) : (x < y)) { a[i] = y; a[ixj] = x; }
                }
            }
            __syncthreads();
        }
    }
    for (int i = tid; i < NKEYP; i += 256) keys[h * NKEYP + i] = a[i];
}

// ---------------- gather ----------------------------------------------------------
__global__ void gather_kernel(const float* __restrict__ kv,
                              const int* __restrict__ keys,
                              float* __restrict__ ksp, float* __restrict__ vsp) {
    int j = blockIdx.x;
    int h = j / NKEYP;
    int d = threadIdx.x;
    int key = keys[j];
    int kvh = h >> 2;
    float kvv = 0.f, vvv = 0.f;
    if (key < SEQ) {
        kvv = kv[(size_t)key * KVW + kvh * HD + d];
        vvv = kv[(size_t)key * KVW + 512 + kvh * HD + d];
    }
    ksp[(size_t)j * HD + d] = kvv;
    vsp[(size_t)j * HD + d] = vvv;
}

// ---------------- sparse attention v4: TC QK (3xTF32) + TC PV (fp16) -------------
#define QHL_ST 132
#define SS_ST 36
#define PH_W 20
#define SPV_WORDS (64*132 + 32*132 + 64*36 + 64*20 + 64*20 + 1152 + 4*64 + 4*64 + 8)

__global__ __launch_bounds__(256) void spattn_kernel(const float* __restrict__ q,
                                                     const float* __restrict__ ksp,
                                                     const float* __restrict__ vsp,
                                                     const int* __restrict__ keys,
                                                     __half* __restrict__ attout) {
    extern __shared__ uint32_t smem[];
    uint32_t* qhl = smem;
    uint32_t* khl = qhl + 64 * 132;
    float* ss = (float*)(khl + 32 * 132);
    uint32_t* psh = (uint32_t*)(ss + 64 * 36);
    uint32_t* vst = psh + 64 * PH_W;
    int* keys_all = (int*)(vst + 64 * PH_W);
    float* m_arr = (float*)(keys_all + 1152);
    float* l_arr = m_arr + 64;
    float* crow = l_arr + 64;
    float* vbar = crow + 64;
    float* vbar4 = vbar + 64;
    int* anyflag = (int*)(vbar4 + 4 * 64);

    int qb = blockIdx.x;
    int h = blockIdx.y;
    int tid = threadIdx.x;
    int lane = tid & 31;
    int warp = tid >> 5;
    int lr = lane >> 2;
    int lc = lane & 3;
    int wm = warp & 3;
    int wn = warp >> 2;
    int qp = tid >> 3;
    int g = tid & 7;
    int qbmax = qb * 64 + 63;

    for (int i = tid; i < NKEYP; i += 256) keys_all[i] = keys[h * NKEYP + i];
    if (tid < 64) { m_arr[tid] = -INFINITY; l_arr[tid] = 0.f; }
    if (tid == 0) *anyflag = 0;
    for (int l = tid; l < 64 * 16; l += 256) {
        int r = l >> 4, c4 = (l & 15) * 4;
        float4 v = *(const float4*)&q[(size_t)(qb * 64 + r) * DIM + h * HD + c4];
        uint32_t* dh = &qhl[r * QHL_ST + c4];
        uint32_t h0 = f2tf32(v.x), h1 = f2tf32(v.y), h2 = f2tf32(v.z), h3 = f2tf32(v.w);
        dh[0] = h0; dh[1] = h1; dh[2] = h2; dh[3] = h3;
        dh[64] = f2tf32(v.x - __uint_as_float(h0));
        dh[65] = f2tf32(v.y - __uint_as_float(h1));
        dh[66] = f2tf32(v.z - __uint_as_float(h2));
        dh[67] = f2tf32(v.w - __uint_as_float(h3));
    }
    __syncthreads();

    float pacc[4][4];
#pragma unroll
    for (int nt = 0; nt < 4; nt++)
#pragma unroll
        for (int e = 0; e < 4; e++) pacc[nt][e] = 0.f;

    for (int t = 0; t < NKEYP / 32; t++) {
        if (keys_all[t * 32] > qbmax) continue;
        __syncthreads();

        for (int l = tid; l < 32 * 16; l += 256) {
            int r = l >> 4, c4 = (l & 15) * 4;
            float4 kv = *(const float4*)&ksp[((size_t)h * NKEYP + t * 32 + r) * HD + c4];
            uint32_t* dh = &khl[r * QHL_ST + c4];
            uint32_t h0 = f2tf32(kv.x), h1 = f2tf32(kv.y), h2 = f2tf32(kv.z), h3 = f2tf32(kv.w);
            dh[0] = h0; dh[1] = h1; dh[2] = h2; dh[3] = h3;
            dh[64] = f2tf32(kv.x - __uint_as_float(h0));
            dh[65] = f2tf32(kv.y - __uint_as_float(h1));
            dh[66] = f2tf32(kv.z - __uint_as_float(h2));
            dh[67] = f2tf32(kv.w - __uint_as_float(h3));
        }
        {
            int j = tid >> 3;
            int d8 = (tid & 7) * 8;
            const float* vr = &vsp[((size_t)h * NKEYP + t * 32 + j) * HD + d8];
            float4 v0 = *(const float4*)vr;
            float4 v1 = *(const float4*)(vr + 4);
            __half* vh = (__half*)vst;
#pragma unroll
            for (int i = 0; i < 4; i++)
                vh[(d8 + i) * (PH_W * 2) + j] = __float2half_rn(((const float*)&v0)[i]);
#pragma unroll
            for (int i = 0; i < 4; i++)
                vh[(d8 + 4 + i) * (PH_W * 2) + j] = __float2half_rn(((const float*)&v1)[i]);
        }
        __syncthreads();

        {
            float acc[2][4];
#pragma unroll
            for (int nt = 0; nt < 2; nt++)
#pragma unroll
                for (int e = 0; e < 4; e++) acc[nt][e] = 0.f;
#pragma unroll
            for (int ksI = 0; ksI < 8; ksI++) {
                int kb = ksI * 8;
                int ra = wm * 16 + lr;
                uint32_t aH[4], aL[4];
                aH[0] = qhl[ra * QHL_ST + kb + lc];
                aH[1] = qhl[(ra + 8) * QHL_ST + kb + lc];
                aH[2] = qhl[ra * QHL_ST + kb + lc + 4];
                aH[3] = qhl[(ra + 8) * QHL_ST + kb + lc + 4];
                aL[0] = qhl[ra * QHL_ST + 64 + kb + lc];
                aL[1] = qhl[(ra + 8) * QHL_ST + 64 + kb + lc];
                aL[2] = qhl[ra * QHL_ST + 64 + kb + lc + 4];
                aL[3] = qhl[(ra + 8) * QHL_ST + 64 + kb + lc + 4];
#pragma unroll
                for (int nt = 0; nt < 2; nt++) {
                    int n0 = wn * 16 + nt * 8;
                    uint32_t b0h = khl[(n0 + lr) * QHL_ST + kb + lc];
                    uint32_t b1h = khl[(n0 + lr) * QHL_ST + kb + lc + 4];
                    uint32_t b0l = khl[(n0 + lr) * QHL_ST + 64 + kb + lc];
                    uint32_t b1l = khl[(n0 + lr) * QHL_ST + 64 + kb + lc + 4];
                    mma_tf32(acc[nt], aH, b0h, b1h);
                    mma_tf32(acc[nt], aH, b0l, b1l);
                    mma_tf32(acc[nt], aL, b0h, b1h);
                }
            }
#pragma unroll
            for (int nt = 0; nt < 2; nt++) {
                int row = wm * 16 + lr;
                int col = wn * 16 + nt * 8 + 2 * lc;
#pragma unroll
                for (int e = 0; e < 4; e++) {
                    int rr = row + (e >> 1) * 8;
                    int cc = col + (e & 1);
                    int key = keys_all[t * 32 + cc];
                    int sg = qb * 64 + rr;
                    float val;
                    if (key >= SEQ) val = -INFINITY;
                    else val = (key <= sg) ? acc[nt][e] * SCALE : -1e30f;
                    ss[rr * SS_ST + cc] = val;
                }
            }
        }
        __syncthreads();

        if (tid < 64) {
            int r = tid;
            float tm = m_arr[r];
#pragma unroll
            for (int j = 0; j < 32; j++) tm = fmaxf(tm, ss[r * SS_ST + j]);
            float c = expf(m_arr[r] - tm);
            crow[r] = c;
            m_arr[r] = tm;
            l_arr[r] *= c;
        }
        __syncthreads();

        {
            int r0 = qp, r1 = qp + 32;
            float m0 = m_arr[r0], m1 = m_arr[r1];
            float ps0 = 0.f, ps1 = 0.f;
            __half* ph = (__half*)psh;
#pragma unroll
            for (int j = 0; j < 4; j++) {
                int cc = g * 4 + j;
                float e0 = expf(ss[r0 * SS_ST + cc] - m0);
                float e1 = expf(ss[r1 * SS_ST + cc] - m1);
                ph[r0 * (PH_W * 2) + cc] = __float2half_rn(e0);
                ph[r1 * (PH_W * 2) + cc] = __float2half_rn(e1);
                ps0 += e0; ps1 += e1;
            }
#pragma unroll
            for (int o = 4; o; o >>= 1) {
                ps0 += __shfl_down_sync(0xFFFFFFFFu, ps0, o, 8);
                ps1 += __shfl_down_sync(0xFFFFFFFFu, ps1, o, 8);
            }
            if (g == 0) { l_arr[r0] += ps0; l_arr[r1] += ps1; }
            float c0 = crow[wm * 16 + lr];
            float c1 = crow[wm * 16 + lr + 8];
#pragma unroll
            for (int nt = 0; nt < 4; nt++) {
                pacc[nt][0] *= c0; pacc[nt][1] *= c0;
                pacc[nt][2] *= c1; pacc[nt][3] *= c1;
            }
        }
        __syncthreads();

        {
#pragma unroll
            for (int kb = 0; kb < 2; kb++) {
                int kw = kb * 8;
                int ra = wm * 16 + lr;
                uint32_t a[4];
                a[0] = psh[ra * PH_W + kw + lc];
                a[1] = psh[(ra + 8) * PH_W + kw + lc];
                a[2] = psh[ra * PH_W + kw + lc + 4];
                a[3] = psh[(ra + 8) * PH_W + kw + lc + 4];
#pragma unroll
                for (int nt = 0; nt < 4; nt++) {
                    int n0 = wn * 32 + nt * 8;
                    uint32_t b0 = vst[(n0 + lr) * PH_W + kw + lc];
                    uint32_t b1 = vst[(n0 + lr) * PH_W + kw + lc + 4];
                    mma_f16(pacc[nt], a, b0, b1);
                }
            }
        }
    }
    __syncthreads();

    if (tid < 64 && m_arr[tid] < -5e29f) *anyflag = 1;
    __syncthreads();
    if (*anyflag) {
        int d = tid & 63, part = tid >> 6;
        float s = 0.f;
        for (int j = part; j < NKEYP; j += 4)
            if (keys_all[j] < SEQ) s += vsp[((size_t)h * NKEYP + j) * HD + d];
        vbar4[part * 64 + d] = s;
        __syncthreads();
        if (tid < 64)
            vbar[tid] = (vbar4[tid] + vbar4[64 + tid] + vbar4[128 + tid] + vbar4[192 + tid])
                        * (1.f / NKEY);
        __syncthreads();
    }

    {
        int r0 = wm * 16 + lr, r1 = r0 + 8;
        float i0 = 1.f / l_arr[r0], i1 = 1.f / l_arr[r1];
        bool f0 = m_arr[r0] < -5e29f, f1 = m_arr[r1] < -5e29f;
        __half* o0 = &attout[(size_t)(qb * 64 + r0) * DIM + h * HD];
        __half* o1 = &attout[(size_t)(qb * 64 + r1) * DIM + h * HD];
#pragma unroll
        for (int nt = 0; nt < 4; nt++) {
            int col = wn * 32 + nt * 8 + 2 * lc;
            o0[col]     = __float2half_rn(f0 ? vbar[col]     : pacc[nt][0] * i0);
            o0[col + 1] = __float2half_rn(f0 ? vbar[col + 1] : pacc[nt][1] * i0);
            o1[col]     = __float2half_rn(f1 ? vbar[col]     : pacc[nt][2] * i1);
            o1[col + 1] = __float2half_rn(f1 ? vbar[col + 1] : pacc[nt][3] * i1);
        }
    }
}

// --------------------------------- launch --------------------------------
extern "C" void kernel_launch(void* const* d_in, const int* in_sizes, int n_in,
                              void* d_out, int out_size) {
    const float* x    = (const float*)d_in[0];
    const float* fcos = (const float*)d_in[1];
    const float* fsin = (const float*)d_in[2];
    const float* wq   = (const float*)d_in[3];
    const float* wk   = (const float*)d_in[4];
    const float* wv   = (const float*)d_in[5];
    const float* wo   = (const float*)d_in[6];
    float* out = (float*)d_out;

    float *q, *q64, *q64p, *kv, *probs, *vert, *dgp, *ksp, *vsp;
    int* keys;
    __half *xh, *xl, *atth, *wqt, *wot, *wkvtH, *wkvtL;
    cudaGetSymbolAddress((void**)&q, g_q);
    cudaGetSymbolAddress((void**)&q64, g_q64);
    cudaGetSymbolAddress((void**)&q64p, g_q64p);
    cudaGetSymbolAddress((void**)&kv, g_kv);
    cudaGetSymbolAddress((void**)&probs, g_probs);
    cudaGetSymbolAddress((void**)&vert, g_vert);
    cudaGetSymbolAddress((void**)&dgp, g_diag);
    cudaGetSymbolAddress((void**)&keys, g_keys);
    cudaGetSymbolAddress((void**)&ksp, g_ksp);
    cudaGetSymbolAddress((void**)&vsp, g_vsp);
    cudaGetSymbolAddress((void**)&xh, g_xh);
    cudaGetSymbolAddress((void**)&xl, g_xl);
    cudaGetSymbolAddress((void**)&atth, g_atth);
    cudaGetSymbolAddress((void**)&wqt, g_wqt);
    cudaGetSymbolAddress((void**)&wot, g_wot);
    cudaGetSymbolAddress((void**)&wkvtH, g_wkvtH);
    cudaGetSymbolAddress((void**)&wkvtL, g_wkvtL);

    // prep
    split_h2<<<(SEQ * DIM / 4 + 255) / 256, 256>>>(x, xh, xl, SEQ * DIM / 4);
    concat_transp_split<<<dim3(KVW / 32, DIM / 32), dim3(32, 8)>>>(wk, wv, wkvtH, wkvtL);
    transp_half<<<dim3(DIM / 32, DIM / 32), dim3(32, 8)>>>(wq, wqt);
    transp_half<<<dim3(DIM / 32, DIM / 32), dim3(32, 8)>>>(wo, wot);

    // projections
    gemm_f16<<<dim3(DIM / 128, SEQ / 128), 256>>>(xh, wqt, q, SEQ, DIM, DIM);
    {
        size_t smb = (size_t)(2 * STG2W) * 4;
        cudaFuncSetAttribute(gemm_f16x3, cudaFuncAttributeMaxDynamicSharedMemorySize,
                             (int)smb);
        gemm_f16x3<<<dim3(KVW / 128, SEQ / 128), 256, smb>>>(
            xh, xl, wkvtH, wkvtL, kv, SEQ, KVW, DIM);
    }

    // exact fp32 q rows 0..63
    qproj_part<<<dim3(16, 8, 8), 128>>>(x, wq, q64p);
    qproj_red<<<(ESTQ * DIM + 255) / 256, 256>>>(q64p, q64);

    // RoPE
    {
        int tq = SEQ * NH * 32;
        rope_kernel<<<(tq + 255) / 256, 256>>>(q, fcos, fsin, NH, DIM, tq);
        int tk = SEQ * NKV * 32;
        rope_kernel<<<(tk + 255) / 256, 256>>>(kv, fcos, fsin, NKV, KVW, tk);
        int tq64 = ESTQ * NH * 32;
        rope_kernel<<<(tq64 + 255) / 256, 256>>>(q64, fcos, fsin, NH, DIM, tq64);
    }

    // estimation (TC scores)
    est_score<<<dim3(SEQ / 64, NH), 256>>>(q64, kv, probs);
    est_norm<<<dim3(ESTQ, NH), 256>>>(probs);

    vertical_kernel<<<(NH * SEQ) / 256, 256>>>(probs, vert);
    diag_kernel<<<(NH * SEQ) / 256, 256>>>(probs, dgp);

    topk2_kernel<<<64, 512>>>(vert, dgp, keys);
    sortkeys_kernel<<<NH, 256>>>(keys);

    gather_kernel<<<NH * NKEYP, 64>>>(kv, keys, ksp, vsp);

    {
        size_t spbytes = (size_t)SPV_WORDS * 4;
        cudaFuncSetAttribute(spattn_kernel,
                             cudaFuncAttributeMaxDynamicSharedMemorySize, (int)spbytes);
        spattn_kernel<<<dim3(SEQ / 64, NH), 256, spbytes>>>(q, ksp, vsp, keys, atth);
    }

    // output projection
    gemm_f16<<<dim3(DIM / 128, SEQ / 128), 256>>>(atth, wot, out, SEQ, DIM, DIM);
}

// round 16
// speedup vs baseline: 2.4181x; 1.0375x over previous
#include <cuda_runtime.h>
#include <cuda_fp16.h>
#include <math.h>
#include <stdint.h>

#define SEQ   4096
#define DIM   2048
#define NH    32
#define NKV   8
#define HD    64
#define ESTQ  64
#define VSZ   300
#define SSZ   800
#define NKEY  1100
#define NKEYP 1152
#define SCALE 0.125f
#define PADKEY 0x3FFFFFFF
#define KVW   1024

// ---------------- device scratch ----------------
__device__ float g_q[SEQ * DIM];
__device__ float g_q64[ESTQ * DIM];
__device__ float g_q64p[8 * ESTQ * DIM];
__device__ float g_kv[SEQ * KVW];
__device__ float g_probs[NH * ESTQ * SEQ];
__device__ float g_vert[NH * SEQ];
__device__ float g_diag[NH * SEQ];
__device__ int   g_keys[NH * NKEYP];
__device__ float g_ksp[NH * NKEYP * HD];
__device__ float g_vsp[NH * NKEYP * HD];
__device__ __half g_xh[SEQ * DIM];
__device__ __half g_xl[SEQ * DIM];
__device__ __half g_atth[SEQ * DIM];
__device__ __half g_wqt[DIM * DIM];
__device__ __half g_wot[DIM * DIM];
__device__ __half g_wkt_h[512 * DIM];   // wk^T hi
__device__ __half g_wkt_l[512 * DIM];   // wk^T lo
__device__ __half g_wvt[512 * DIM];     // wv^T fp16

// ---------------- helpers ------------------------------------------------
__device__ __forceinline__ uint32_t f2tf32(float f) {
    uint32_t r;
    asm("cvt.rna.tf32.f32 %0, %1;" : "=r"(r) : "f"(f));
    return r;
}

__device__ __forceinline__ void mma_tf32(float c[4], const uint32_t a[4],
                                         uint32_t b0, uint32_t b1) {
    asm volatile(
        "mma.sync.aligned.m16n8k8.row.col.f32.tf32.tf32.f32 "
        "{%0,%1,%2,%3}, {%4,%5,%6,%7}, {%8,%9}, {%0,%1,%2,%3};\n"
        : "+f"(c[0]), "+f"(c[1]), "+f"(c[2]), "+f"(c[3])
        : "r"(a[0]), "r"(a[1]), "r"(a[2]), "r"(a[3]), "r"(b0), "r"(b1));
}

__device__ __forceinline__ void mma_f16(float c[4], const uint32_t a[4],
                                        uint32_t b0, uint32_t b1) {
    asm volatile(
        "mma.sync.aligned.m16n8k16.row.col.f32.f16.f16.f32 "
        "{%0,%1,%2,%3}, {%4,%5,%6,%7}, {%8,%9}, {%0,%1,%2,%3};\n"
        : "+f"(c[0]), "+f"(c[1]), "+f"(c[2]), "+f"(c[3])
        : "r"(a[0]), "r"(a[1]), "r"(a[2]), "r"(a[3]), "r"(b0), "r"(b1));
}

__device__ __forceinline__ uint32_t smem_u32(const void* p) {
    uint32_t a;
    asm("{ .reg .u64 t; cvta.to.shared.u64 t, %1; cvt.u32.u64 %0, t; }" : "=r"(a) : "l"(p));
    return a;
}

// ================= fp16 k16 GEMM with cp.async double buffering ===========
#define AF_ST 20

__global__ __launch_bounds__(256) void gemm_f16(const __half* __restrict__ A,
                                                const __half* __restrict__ Bt,
                                                float* __restrict__ C,
                                                int M, int N, int K, int ldc) {
    __shared__ uint32_t As[2][128 * AF_ST];
    __shared__ uint32_t Bs[2][128 * AF_ST];
    int tid = threadIdx.x;
    int lane = tid & 31;
    int warp = tid >> 5;
    int wm = warp & 3;
    int wn = warp >> 2;
    int row0 = blockIdx.y * 128;
    int col0 = blockIdx.x * 128;
    int lr = lane >> 2;
    int lc = lane & 3;

    uint32_t asb[2], bsb[2];
    asb[0] = smem_u32(&As[0][0]);
    asb[1] = smem_u32(&As[1][0]);
    bsb[0] = smem_u32(&Bs[0][0]);
    bsb[1] = smem_u32(&Bs[1][0]);

    float acc[2][8][4];
#pragma unroll
    for (int mi = 0; mi < 2; mi++)
#pragma unroll
        for (int nj = 0; nj < 8; nj++)
#pragma unroll
            for (int e = 0; e < 4; e++) acc[mi][nj][e] = 0.f;

    int r_ld = tid >> 2;
    int j_ld = tid & 3;

    {
#pragma unroll
        for (int i = 0; i < 2; i++) {
            int r = r_ld + i * 64;
            uint32_t da = asb[0] + (uint32_t)(r * AF_ST + j_ld * 4) * 4;
            const __half* sa = A + (size_t)(row0 + r) * K + j_ld * 8;
            asm volatile("cp.async.ca.shared.global [%0], [%1], 16;" :: "r"(da), "l"(sa));
            uint32_t db = bsb[0] + (uint32_t)(r * AF_ST + j_ld * 4) * 4;
            const __half* sb = Bt + (size_t)(col0 + r) * K + j_ld * 8;
            asm volatile("cp.async.ca.shared.global [%0], [%1], 16;" :: "r"(db), "l"(sb));
        }
        asm volatile("cp.async.commit_group;");
    }

    int KC = K >> 5;
    for (int c = 0; c < KC; c++) {
        int buf = c & 1;
        if (c + 1 < KC) {
            int k0 = (c + 1) << 5;
            int nb = buf ^ 1;
#pragma unroll
            for (int i = 0; i < 2; i++) {
                int r = r_ld + i * 64;
                uint32_t da = asb[nb] + (uint32_t)(r * AF_ST + j_ld * 4) * 4;
                const __half* sa = A + (size_t)(row0 + r) * K + k0 + j_ld * 8;
                asm volatile("cp.async.ca.shared.global [%0], [%1], 16;" :: "r"(da), "l"(sa));
                uint32_t db = bsb[nb] + (uint32_t)(r * AF_ST + j_ld * 4) * 4;
                const __half* sb = Bt + (size_t)(col0 + r) * K + k0 + j_ld * 8;
                asm volatile("cp.async.ca.shared.global [%0], [%1], 16;" :: "r"(db), "l"(sb));
            }
            asm volatile("cp.async.commit_group;");
            asm volatile("cp.async.wait_group 1;");
        } else {
            asm volatile("cp.async.wait_group 0;");
        }
        __syncthreads();

        const uint32_t* Ab = As[buf];
        const uint32_t* Bb = Bs[buf];
#pragma unroll
        for (int ks = 0; ks < 2; ks++) {
            int kb = ks * 8;
            uint32_t a[2][4];
#pragma unroll
            for (int mi = 0; mi < 2; mi++) {
                int ra = wm * 32 + mi * 16 + lr;
                a[mi][0] = Ab[ra * AF_ST + kb + lc];
                a[mi][1] = Ab[(ra + 8) * AF_ST + kb + lc];
                a[mi][2] = Ab[ra * AF_ST + kb + lc + 4];
                a[mi][3] = Ab[(ra + 8) * AF_ST + kb + lc + 4];
            }
#pragma unroll
            for (int nj = 0; nj < 8; nj++) {
                int col = wn * 64 + nj * 8 + lr;
                uint32_t b0 = Bb[col * AF_ST + kb + lc];
                uint32_t b1 = Bb[col * AF_ST + kb + lc + 4];
                mma_f16(acc[0][nj], a[0], b0, b1);
                mma_f16(acc[1][nj], a[1], b0, b1);
            }
        }
        __syncthreads();
    }

#pragma unroll
    for (int mi = 0; mi < 2; mi++) {
        int row = row0 + wm * 32 + mi * 16 + lr;
#pragma unroll
        for (int nj = 0; nj < 8; nj++) {
            int col = col0 + wn * 64 + nj * 8 + 2 * lc;
            float* cp0 = C + (size_t)row * ldc + col;
            cp0[0] = acc[mi][nj][0];
            cp0[1] = acc[mi][nj][1];
            float* cp1 = C + (size_t)(row + 8) * ldc + col;
            cp1[0] = acc[mi][nj][2];
            cp1[1] = acc[mi][nj][3];
        }
    }
}

// ===== fp16 hi/lo 3-term GEMM, BK=16 (k projection) =====
#define AK_ST 12
#define STG2W (4 * 128 * AK_ST)

__global__ __launch_bounds__(256) void gemm_f16x3(const __half* __restrict__ AH,
                                                  const __half* __restrict__ AL,
                                                  const __half* __restrict__ BH,
                                                  const __half* __restrict__ BL,
                                                  float* __restrict__ C,
                                                  int M, int N, int K, int ldc) {
    extern __shared__ uint32_t sm[];
    uint32_t base = smem_u32(sm);
    int tid = threadIdx.x;
    int lane = tid & 31;
    int warp = tid >> 5;
    int wm = warp & 3;
    int wn = warp >> 2;
    int row0 = blockIdx.y * 128;
    int col0 = blockIdx.x * 128;
    int lr = lane >> 2;
    int lc = lane & 3;

    float acc[2][8][4];
#pragma unroll
    for (int mi = 0; mi < 2; mi++)
#pragma unroll
        for (int nj = 0; nj < 8; nj++)
#pragma unroll
            for (int e = 0; e < 4; e++) acc[mi][nj][e] = 0.f;

    int r_ld = tid >> 1;
    int j_ld = tid & 1;

    auto issue = [&](int stage, int k0) {
        uint32_t sb = base + (uint32_t)stage * STG2W * 4;
        uint32_t off = (uint32_t)(r_ld * AK_ST + j_ld * 4) * 4;
        const __half* pa = AH + (size_t)(row0 + r_ld) * K + k0 + j_ld * 8;
        asm volatile("cp.async.ca.shared.global [%0], [%1], 16;" :: "r"(sb + off), "l"(pa));
        const __half* pl = AL + (size_t)(row0 + r_ld) * K + k0 + j_ld * 8;
        asm volatile("cp.async.ca.shared.global [%0], [%1], 16;"
                     :: "r"(sb + (uint32_t)(128 * AK_ST) * 4 + off), "l"(pl));
        const __half* pb = BH + (size_t)(col0 + r_ld) * K + k0 + j_ld * 8;
        asm volatile("cp.async.ca.shared.global [%0], [%1], 16;"
                     :: "r"(sb + (uint32_t)(2 * 128 * AK_ST) * 4 + off), "l"(pb));
        const __half* pc = BL + (size_t)(col0 + r_ld) * K + k0 + j_ld * 8;
        asm volatile("cp.async.ca.shared.global [%0], [%1], 16;"
                     :: "r"(sb + (uint32_t)(3 * 128 * AK_ST) * 4 + off), "l"(pc));
        asm volatile("cp.async.commit_group;");
    };

    issue(0, 0);

    int KC = K >> 4;
    for (int c = 0; c < KC; c++) {
        int buf = c & 1;
        if (c + 1 < KC) {
            issue(buf ^ 1, (c + 1) << 4);
            asm volatile("cp.async.wait_group 1;");
        } else {
            asm volatile("cp.async.wait_group 0;");
        }
        __syncthreads();

        const uint32_t* AsH = sm + (size_t)buf * STG2W;
        const uint32_t* AsL = AsH + 128 * AK_ST;
        const uint32_t* BsH = AsH + 2 * 128 * AK_ST;
        const uint32_t* BsL = AsH + 3 * 128 * AK_ST;
        uint32_t aH[2][4], aL[2][4];
#pragma unroll
        for (int mi = 0; mi < 2; mi++) {
            int ra = wm * 32 + mi * 16 + lr;
            aH[mi][0] = AsH[ra * AK_ST + lc];
            aH[mi][1] = AsH[(ra + 8) * AK_ST + lc];
            aH[mi][2] = AsH[ra * AK_ST + lc + 4];
            aH[mi][3] = AsH[(ra + 8) * AK_ST + lc + 4];
            aL[mi][0] = AsL[ra * AK_ST + lc];
            aL[mi][1] = AsL[(ra + 8) * AK_ST + lc];
            aL[mi][2] = AsL[ra * AK_ST + lc + 4];
            aL[mi][3] = AsL[(ra + 8) * AK_ST + lc + 4];
        }
#pragma unroll
        for (int nj = 0; nj < 8; nj++) {
            int col = wn * 64 + nj * 8 + lr;
            uint32_t b0h = BsH[col * AK_ST + lc];
            uint32_t b1h = BsH[col * AK_ST + lc + 4];
            uint32_t b0l = BsL[col * AK_ST + lc];
            uint32_t b1l = BsL[col * AK_ST + lc + 4];
#pragma unroll
            for (int mi = 0; mi < 2; mi++) {
                mma_f16(acc[mi][nj], aH[mi], b0h, b1h);
                mma_f16(acc[mi][nj], aH[mi], b0l, b1l);
                mma_f16(acc[mi][nj], aL[mi], b0h, b1h);
            }
        }
        __syncthreads();
    }

#pragma unroll
    for (int mi = 0; mi < 2; mi++) {
        int row = row0 + wm * 32 + mi * 16 + lr;
#pragma unroll
        for (int nj = 0; nj < 8; nj++) {
            int col = col0 + wn * 64 + nj * 8 + 2 * lc;
            float* cp0 = C + (size_t)row * ldc + col;
            cp0[0] = acc[mi][nj][0];
            cp0[1] = acc[mi][nj][1];
            float* cp1 = C + (size_t)(row + 8) * ldc + col;
            cp1[0] = acc[mi][nj][2];
            cp1[1] = acc[mi][nj][3];
        }
    }
}

// ---------------- prep kernels ---------------------------------------------
__global__ void split_h2(const float* __restrict__ a, __half* __restrict__ h,
                         __half* __restrict__ l, int n4) {
    int i = blockIdx.x * 256 + threadIdx.x;
    if (i >= n4) return;
    float4 v = ((const float4*)a)[i];
    __half hx = __float2half_rn(v.x), hy = __float2half_rn(v.y);
    __half hz = __float2half_rn(v.z), hw = __float2half_rn(v.w);
    __half2 h0 = __halves2half2(hx, hy);
    __half2 h1 = __halves2half2(hz, hw);
    ((uint2*)h)[i] = make_uint2(*(uint32_t*)&h0, *(uint32_t*)&h1);
    __half2 l0 = __halves2half2(__float2half_rn(v.x - __half2float(hx)),
                                __float2half_rn(v.y - __half2float(hy)));
    __half2 l1 = __halves2half2(__float2half_rn(v.z - __half2float(hz)),
                                __float2half_rn(v.w - __half2float(hw)));
    ((uint2*)l)[i] = make_uint2(*(uint32_t*)&l0, *(uint32_t*)&l1);
}

// transpose fp32 [DIM][ncols] -> fp16 hi/lo [ncols][DIM]
__global__ void transp_split_g(const float* __restrict__ w, __half* __restrict__ th,
                               __half* __restrict__ tl, int ncols) {
    __shared__ float tile[32][33];
    int bx = blockIdx.x * 32;  // n
    int by = blockIdx.y * 32;  // k
    int tx = threadIdx.x, ty = threadIdx.y;
    for (int i = 0; i < 32; i += 8)
        tile[ty + i][tx] = w[(size_t)(by + ty + i) * ncols + bx + tx];
    __syncthreads();
    for (int i = 0; i < 32; i += 8) {
        float v = tile[tx][ty + i];
        __half h = __float2half_rn(v);
        th[(size_t)(bx + ty + i) * DIM + by + tx] = h;
        tl[(size_t)(bx + ty + i) * DIM + by + tx] = __float2half_rn(v - __half2float(h));
    }
}

// transpose fp32 [DIM][ncols] -> fp16 [ncols][DIM]
__global__ void transp_half_g(const float* __restrict__ w, __half* __restrict__ t, int ncols) {
    __shared__ float tile[32][33];
    int bx = blockIdx.x * 32;
    int by = blockIdx.y * 32;
    int tx = threadIdx.x, ty = threadIdx.y;
    for (int i = 0; i < 32; i += 8)
        tile[ty + i][tx] = w[(size_t)(by + ty + i) * ncols + bx + tx];
    __syncthreads();
    for (int i = 0; i < 32; i += 8)
        t[(size_t)(bx + ty + i) * DIM + by + tx] = __float2half_rn(tile[tx][ty + i]);
}

// ---------------- exact fp32 q rows 0..63: split-K ---------------------------
__global__ __launch_bounds__(128) void qproj_part(const float* __restrict__ x,
                                                  const float* __restrict__ wq,
                                                  float* __restrict__ part) {
    __shared__ float xs[8][256];
    int tid = threadIdx.x;
    int col = blockIdx.x * 128 + tid;
    int r0 = blockIdx.y * 8;
    int k0 = blockIdx.z * 256;
    float acc[8];
#pragma unroll
    for (int rr = 0; rr < 8; rr++) acc[rr] = 0.f;

    for (int i = tid; i < 8 * 256; i += 128) {
        int rr = i >> 8, kk = i & 255;
        xs[rr][kk] = x[(size_t)(r0 + rr) * DIM + k0 + kk];
    }
    __syncthreads();
    for (int kk = 0; kk < 256; kk++) {
        float w = wq[(size_t)(k0 + kk) * DIM + col];
#pragma unroll
        for (int rr = 0; rr < 8; rr++) acc[rr] += xs[rr][kk] * w;
    }
#pragma unroll
    for (int rr = 0; rr < 8; rr++)
        part[(size_t)blockIdx.z * ESTQ * DIM + (size_t)(r0 + rr) * DIM + col] = acc[rr];
}

__global__ void qproj_red(const float* __restrict__ part, float* __restrict__ q64) {
    int idx = blockIdx.x * 256 + threadIdx.x;
    if (idx >= ESTQ * DIM) return;
    float s = 0.f;
#pragma unroll
    for (int ks = 0; ks < 8; ks++) s += part[(size_t)ks * ESTQ * DIM + idx];
    q64[idx] = s;
}

// ---------------- RoPE -------------------------------------------------------
__global__ void rope_kernel(float* t, const float* __restrict__ cosb,
                            const float* __restrict__ sinb, int H, int stride, int total) {
    int idx = blockIdx.x * blockDim.x + threadIdx.x;
    if (idx >= total) return;
    int d2 = idx & 31;
    int h = (idx >> 5) % H;
    int s = idx / (32 * H);
    float c = cosb[s * 32 + d2];
    float sn = sinb[s * 32 + d2];
    float* p = t + (size_t)s * stride + h * 64 + 2 * d2;
    float xr = p[0], xi = p[1];
    p[0] = xr * c - xi * sn;
    p[1] = xr * sn + xi * c;
}

// ---------------- est phase A: TC scores (fp16 hi/lo 3-term) ------------------
#define ES_ST 36

__global__ __launch_bounds__(256) void est_score(const float* __restrict__ q64,
                                                 const float* __restrict__ kv,
                                                 float* __restrict__ probs) {
    __shared__ uint32_t qh[64 * ES_ST];
    __shared__ uint32_t ql[64 * ES_ST];
    __shared__ uint32_t kh[64 * ES_ST];
    __shared__ uint32_t kl[64 * ES_ST];
    int tid = threadIdx.x;
    int lane = tid & 31;
    int warp = tid >> 5;
    int lr = lane >> 2;
    int lc = lane & 3;
    int wm = warp & 3;
    int wn = warp >> 2;
    int h = blockIdx.y;
    int c0 = blockIdx.x * 64;
    int kvh = h >> 2;

    for (int l = tid; l < 64 * 16; l += 256) {
        int r = l >> 4, c4 = (l & 15) * 4;
        float4 v = *(const float4*)&q64[(size_t)r * DIM + h * HD + c4];
        __half hx = __float2half_rn(v.x), hy = __float2half_rn(v.y);
        __half hz = __float2half_rn(v.z), hw = __float2half_rn(v.w);
        __half2 p0 = __halves2half2(hx, hy);
        __half2 p1 = __halves2half2(hz, hw);
        qh[r * ES_ST + c4 / 2] = *(uint32_t*)&p0;
        qh[r * ES_ST + c4 / 2 + 1] = *(uint32_t*)&p1;
        __half2 q0 = __halves2half2(__float2half_rn(v.x - __half2float(hx)),
                                    __float2half_rn(v.y - __half2float(hy)));
        __half2 q1 = __halves2half2(__float2half_rn(v.z - __half2float(hz)),
                                    __float2half_rn(v.w - __half2float(hw)));
        ql[r * ES_ST + c4 / 2] = *(uint32_t*)&q0;
        ql[r * ES_ST + c4 / 2 + 1] = *(uint32_t*)&q1;

        float4 kvv = *(const float4*)&kv[(size_t)(c0 + r) * KVW + kvh * HD + c4];
        __half kx = __float2half_rn(kvv.x), ky = __float2half_rn(kvv.y);
        __half kz = __float2half_rn(kvv.z), kw = __float2half_rn(kvv.w);
        __half2 r0 = __halves2half2(kx, ky);
        __half2 r1 = __halves2half2(kz, kw);
        kh[r * ES_ST + c4 / 2] = *(uint32_t*)&r0;
        kh[r * ES_ST + c4 / 2 + 1] = *(uint32_t*)&r1;
        __half2 s0 = __halves2half2(__float2half_rn(kvv.x - __half2float(kx)),
                                    __float2half_rn(kvv.y - __half2float(ky)));
        __half2 s1 = __halves2half2(__float2half_rn(kvv.z - __half2float(kz)),
                                    __float2half_rn(kvv.w - __half2float(kw)));
        kl[r * ES_ST + c4 / 2] = *(uint32_t*)&s0;
        kl[r * ES_ST + c4 / 2 + 1] = *(uint32_t*)&s1;
    }
    __syncthreads();

    float acc[4][4];
#pragma unroll
    for (int nt = 0; nt < 4; nt++)
#pragma unroll
        for (int e = 0; e < 4; e++) acc[nt][e] = 0.f;

#pragma unroll
    for (int kc = 0; kc < 4; kc++) {
        int kw = kc * 8;
        int ra = wm * 16 + lr;
        uint32_t aH[4], aL[4];
        aH[0] = qh[ra * ES_ST + kw + lc];
        aH[1] = qh[(ra + 8) * ES_ST + kw + lc];
        aH[2] = qh[ra * ES_ST + kw + lc + 4];
        aH[3] = qh[(ra + 8) * ES_ST + kw + lc + 4];
        aL[0] = ql[ra * ES_ST + kw + lc];
        aL[1] = ql[(ra + 8) * ES_ST + kw + lc];
        aL[2] = ql[ra * ES_ST + kw + lc + 4];
        aL[3] = ql[(ra + 8) * ES_ST + kw + lc + 4];
#pragma unroll
        for (int nt = 0; nt < 4; nt++) {
            int n0 = wn * 32 + nt * 8;
            uint32_t b0h = kh[(n0 + lr) * ES_ST + kw + lc];
            uint32_t b1h = kh[(n0 + lr) * ES_ST + kw + lc + 4];
            uint32_t b0l = kl[(n0 + lr) * ES_ST + kw + lc];
            uint32_t b1l = kl[(n0 + lr) * ES_ST + kw + lc + 4];
            mma_f16(acc[nt], aH, b0h, b1h);
            mma_f16(acc[nt], aH, b0l, b1l);
            mma_f16(acc[nt], aL, b0h, b1h);
        }
    }

#pragma unroll
    for (int nt = 0; nt < 4; nt++) {
        int row = wm * 16 + lr;
        int col = wn * 32 + nt * 8 + 2 * lc;
#pragma unroll
        for (int e = 0; e < 4; e++) {
            int rr = row + (e >> 1) * 8;
            int cc = col + (e & 1);
            int kk = c0 + cc;
            float val = acc[nt][e] * SCALE;
            if (kk >= SEQ - ESTQ && rr < kk - (SEQ - ESTQ)) val = -INFINITY;
            probs[((size_t)h * ESTQ + rr) * SEQ + kk] = val;
        }
    }
}

// ---------------- est phase B -------------------------------------------------
__global__ __launch_bounds__(256) void est_norm(float* __restrict__ probs) {
    int qi = blockIdx.x;
    int h = blockIdx.y;
    __shared__ float sc[SEQ];
    __shared__ float red[8];
    int tid = threadIdx.x;
    float* pr = probs + ((size_t)h * ESTQ + qi) * SEQ;

    for (int l = tid; l < SEQ / 4; l += 256)
        *(float4*)&sc[l * 4] = *(const float4*)&pr[l * 4];
    __syncthreads();

    float m = -INFINITY;
    for (int kk = tid; kk < SEQ; kk += 256) m = fmaxf(m, sc[kk]);
#pragma unroll
    for (int o = 16; o; o >>= 1) m = fmaxf(m, __shfl_xor_sync(0xFFFFFFFFu, m, o));
    if ((tid & 31) == 0) red[tid >> 5] = m;
    __syncthreads();
    if (tid == 0) {
        float mm = red[0];
#pragma unroll
        for (int i = 1; i < 8; i++) mm = fmaxf(mm, red[i]);
        red[0] = mm;
    }
    __syncthreads();
    m = red[0];
    __syncthreads();

    float s = 0.f;
    for (int kk = tid; kk < SEQ; kk += 256) {
        float e = expf(sc[kk] - m);
        sc[kk] = e;
        s += e;
    }
#pragma unroll
    for (int o = 16; o; o >>= 1) s += __shfl_xor_sync(0xFFFFFFFFu, s, o);
    if ((tid & 31) == 0) red[tid >> 5] = s;
    __syncthreads();
    if (tid == 0) {
        float ss = 0.f;
#pragma unroll
        for (int i = 0; i < 8; i++) ss += red[i];
        red[0] = ss;
    }
    __syncthreads();
    float inv = 1.f / red[0];
    for (int kk = tid; kk < SEQ; kk += 256) pr[kk] = sc[kk] * inv;
}

// ---------------- vertical / diagonal ------------------------------------------
__global__ void vertical_kernel(const float* __restrict__ probs, float* __restrict__ vert) {
    int idx = blockIdx.x * 256 + threadIdx.x;
    int h = idx >> 12;
    int kk = idx & (SEQ - 1);
    float s = 0.f;
    const float* base = probs + (size_t)h * ESTQ * SEQ + kk;
    for (int i = 0; i < ESTQ; i++) s += base[(size_t)i * SEQ];
    vert[idx] = s;
}

__global__ void diag_kernel(const float* __restrict__ probs, float* __restrict__ dg) {
    int idx = blockIdx.x * 256 + threadIdx.x;
    int h = idx >> 12;
    int jp = idx & (SEQ - 1);
    float s = 0.f;
    const float* base = probs + (size_t)h * ESTQ * SEQ;
    for (int i = 0; i < ESTQ; i++) {
        int col = i + jp - 63;
        if (col >= 0 && col < SEQ) s += base[(size_t)i * SEQ + col];
    }
    dg[idx] = s;
}

// ---------------- merged top-k ---------------------------------------------------
__global__ void topk2_kernel(const float* __restrict__ vert, const float* __restrict__ dg,
                             int* __restrict__ keys) {
    int b = blockIdx.x;
    int mode = b >> 5;
    int h = b & 31;
    const float* vals = mode ? dg : vert;
    int kcount = mode ? SSZ : VSZ;
    __shared__ unsigned long long a[SEQ];
    int tid = threadIdx.x;
    for (int i = tid; i < SEQ; i += 512) {
        unsigned u = __float_as_uint(vals[h * SEQ + i]);
        u = (u & 0x80000000u) ? ~u : (u | 0x80000000u);
        a[i] = ((unsigned long long)(~u) << 32) | (unsigned)i;
    }
    __syncthreads();
    for (int k = 2; k <= SEQ; k <<= 1) {
        for (int j = k >> 1; j > 0; j >>= 1) {
            for (int i = tid; i < SEQ; i += 512) {
                int ixj = i ^ j;
                if (ixj > i) {
                    bool up = ((i & k) == 0);
                    unsigned long long x = a[i], y = a[ixj];
                    if (up ? (x > y) : (x < y)) { a[i] = y; a[ixj] = x; }
                }
            }
            __syncthreads();
        }
    }
    if (mode == 0) {
        for (int t = tid; t < kcount; t += 512)
            keys[h * NKEYP + t] = (int)(a[t] & 0xFFFFFFFFull);
    } else {
        for (int t = tid; t < kcount; t += 512)
            keys[h * NKEYP + VSZ + t] = (SEQ - 1) - (int)(a[t] & 0xFFFFFFFFull);
        for (int t = NKEY + tid; t < NKEYP; t += 512) keys[h * NKEYP + t] = PADKEY;
    }
}

// ---------------- sort keys ascending per head ----------------------------------
__global__ __launch_bounds__(256) void sortkeys_kernel(int* __restrict__ keys) {
    int h = blockIdx.x;
    __shared__ int a[2048];
    int tid = threadIdx.x;
    for (int i = tid; i < 2048; i += 256)
        a[i] = (i < NKEYP) ? keys[h * NKEYP + i] : PADKEY;
    __syncthreads();
    for (int k = 2; k <= 2048; k <<= 1) {
        for (int j = k >> 1; j > 0; j >>= 1) {
            for (int i = tid; i < 2048; i += 256) {
                int ixj = i ^ j;
                if (ixj > i) {
                    bool up = ((i & k) == 0);
                    int x = a[i], y = a[ixj];
                    if (up ? (x > y) : (x < y)) { a[i] = y; a[ixj] = x; }
                }
            }
            __syncthreads();
        }
    }
    for (int i = tid; i < NKEYP; i += 256) keys[h * NKEYP + i] = a[i];
}

// ---------------- gather ----------------------------------------------------------
__global__ void gather_kernel(const float* __restrict__ kv,
                              const int* __restrict__ keys,
                              float* __restrict__ ksp, float* __restrict__ vsp) {
    int j = blockIdx.x;
    int h = j / NKEYP;
    int d = threadIdx.x;
    int key = keys[j];
    int kvh = h >> 2;
    float kvv = 0.f, vvv = 0.f;
    if (key < SEQ) {
        kvv = kv[(size_t)key * KVW + kvh * HD + d];
        vvv = kv[(size_t)key * KVW + 512 + kvh * HD + d];
    }
    ksp[(size_t)j * HD + d] = kvv;
    vsp[(size_t)j * HD + d] = vvv;
}

// ---------------- sparse attention v4: TC QK (3xTF32) + TC PV (fp16) -------------
#define QHL_ST 132
#define SS_ST 36
#define PH_W 20
#define SPV_WORDS (64*132 + 32*132 + 64*36 + 64*20 + 64*20 + 1152 + 4*64 + 4*64 + 8)

__global__ __launch_bounds__(256) void spattn_kernel(const float* __restrict__ q,
                                                     const float* __restrict__ ksp,
                                                     const float* __restrict__ vsp,
                                                     const int* __restrict__ keys,
                                                     __half* __restrict__ attout) {
    extern __shared__ uint32_t smem[];
    uint32_t* qhl = smem;
    uint32_t* khl = qhl + 64 * 132;
    float* ss = (float*)(khl + 32 * 132);
    uint32_t* psh = (uint32_t*)(ss + 64 * 36);
    uint32_t* vst = psh + 64 * PH_W;
    int* keys_all = (int*)(vst + 64 * PH_W);
    float* m_arr = (float*)(keys_all + 1152);
    float* l_arr = m_arr + 64;
    float* crow = l_arr + 64;
    float* vbar = crow + 64;
    float* vbar4 = vbar + 64;
    int* anyflag = (int*)(vbar4 + 4 * 64);

    int qb = blockIdx.x;
    int h = blockIdx.y;
    int tid = threadIdx.x;
    int lane = tid & 31;
    int warp = tid >> 5;
    int lr = lane >> 2;
    int lc = lane & 3;
    int wm = warp & 3;
    int wn = warp >> 2;
    int qp = tid >> 3;
    int g = tid & 7;
    int qbmax = qb * 64 + 63;

    for (int i = tid; i < NKEYP; i += 256) keys_all[i] = keys[h * NKEYP + i];
    if (tid < 64) { m_arr[tid] = -INFINITY; l_arr[tid] = 0.f; }
    if (tid == 0) *anyflag = 0;
    for (int l = tid; l < 64 * 16; l += 256) {
        int r = l >> 4, c4 = (l & 15) * 4;
        float4 v = *(const float4*)&q[(size_t)(qb * 64 + r) * DIM + h * HD + c4];
        uint32_t* dh = &qhl[r * QHL_ST + c4];
        uint32_t h0 = f2tf32(v.x), h1 = f2tf32(v.y), h2 = f2tf32(v.z), h3 = f2tf32(v.w);
        dh[0] = h0; dh[1] = h1; dh[2] = h2; dh[3] = h3;
        dh[64] = f2tf32(v.x - __uint_as_float(h0));
        dh[65] = f2tf32(v.y - __uint_as_float(h1));
        dh[66] = f2tf32(v.z - __uint_as_float(h2));
        dh[67] = f2tf32(v.w - __uint_as_float(h3));
    }
    __syncthreads();

    float pacc[4][4];
#pragma unroll
    for (int nt = 0; nt < 4; nt++)
#pragma unroll
        for (int e = 0; e < 4; e++) pacc[nt][e] = 0.f;

    for (int t = 0; t < NKEYP / 32; t++) {
        if (keys_all[t * 32] > qbmax) continue;
        __syncthreads();

        for (int l = tid; l < 32 * 16; l += 256) {
            int r = l >> 4, c4 = (l & 15) * 4;
            float4 kv = *(const float4*)&ksp[((size_t)h * NKEYP + t * 32 + r) * HD + c4];
            uint32_t* dh = &khl[r * QHL_ST + c4];
            uint32_t h0 = f2tf32(kv.x), h1 = f2tf32(kv.y), h2 = f2tf32(kv.z), h3 = f2tf32(kv.w);
            dh[0] = h0; dh[1] = h1; dh[2] = h2; dh[3] = h3;
            dh[64] = f2tf32(kv.x - __uint_as_float(h0));
            dh[65] = f2tf32(kv.y - __uint_as_float(h1));
            dh[66] = f2tf32(kv.z - __uint_as_float(h2));
            dh[67] = f2tf32(kv.w - __uint_as_float(h3));
        }
        {
            int j = tid >> 3;
            int d8 = (tid & 7) * 8;
            const float* vr = &vsp[((size_t)h * NKEYP + t * 32 + j) * HD + d8];
            float4 v0 = *(const float4*)vr;
            float4 v1 = *(const float4*)(vr + 4);
            __half* vh = (__half*)vst;
#pragma unroll
            for (int i = 0; i < 4; i++)
                vh[(d8 + i) * (PH_W * 2) + j] = __float2half_rn(((const float*)&v0)[i]);
#pragma unroll
            for (int i = 0; i < 4; i++)
                vh[(d8 + 4 + i) * (PH_W * 2) + j] = __float2half_rn(((const float*)&v1)[i]);
        }
        __syncthreads();

        {
            float acc[2][4];
#pragma unroll
            for (int nt = 0; nt < 2; nt++)
#pragma unroll
                for (int e = 0; e < 4; e++) acc[nt][e] = 0.f;
#pragma unroll
            for (int ksI = 0; ksI < 8; ksI++) {
                int kb = ksI * 8;
                int ra = wm * 16 + lr;
                uint32_t aH[4], aL[4];
                aH[0] = qhl[ra * QHL_ST + kb + lc];
                aH[1] = qhl[(ra + 8) * QHL_ST + kb + lc];
                aH[2] = qhl[ra * QHL_ST + kb + lc + 4];
                aH[3] = qhl[(ra + 8) * QHL_ST + kb + lc + 4];
                aL[0] = qhl[ra * QHL_ST + 64 + kb + lc];
                aL[1] = qhl[(ra + 8) * QHL_ST + 64 + kb + lc];
                aL[2] = qhl[ra * QHL_ST + 64 + kb + lc + 4];
                aL[3] = qhl[(ra + 8) * QHL_ST + 64 + kb + lc + 4];
#pragma unroll
                for (int nt = 0; nt < 2; nt++) {
                    int n0 = wn * 16 + nt * 8;
                    uint32_t b0h = khl[(n0 + lr) * QHL_ST + kb + lc];
                    uint32_t b1h = khl[(n0 + lr) * QHL_ST + kb + lc + 4];
                    uint32_t b0l = khl[(n0 + lr) * QHL_ST + 64 + kb + lc];
                    uint32_t b1l = khl[(n0 + lr) * QHL_ST + 64 + kb + lc + 4];
                    mma_tf32(acc[nt], aH, b0h, b1h);
                    mma_tf32(acc[nt], aH, b0l, b1l);
                    mma_tf32(acc[nt], aL, b0h, b1h);
                }
            }
#pragma unroll
            for (int nt = 0; nt < 2; nt++) {
                int row = wm * 16 + lr;
                int col = wn * 16 + nt * 8 + 2 * lc;
#pragma unroll
                for (int e = 0; e < 4; e++) {
                    int rr = row + (e >> 1) * 8;
                    int cc = col + (e & 1);
                    int key = keys_all[t * 32 + cc];
                    int sg = qb * 64 + rr;
                    float val;
                    if (key >= SEQ) val = -INFINITY;
                    else val = (key <= sg) ? acc[nt][e] * SCALE : -1e30f;
                    ss[rr * SS_ST + cc] = val;
                }
            }
        }
        __syncthreads();

        if (tid < 64) {
            int r = tid;
            float tm = m_arr[r];
#pragma unroll
            for (int j = 0; j < 32; j++) tm = fmaxf(tm, ss[r * SS_ST + j]);
            float c = expf(m_arr[r] - tm);
            crow[r] = c;
            m_arr[r] = tm;
            l_arr[r] *= c;
        }
        __syncthreads();

        {
            int r0 = qp, r1 = qp + 32;
            float m0 = m_arr[r0], m1 = m_arr[r1];
            float ps0 = 0.f, ps1 = 0.f;
            __half* ph = (__half*)psh;
#pragma unroll
            for (int j = 0; j < 4; j++) {
                int cc = g * 4 + j;
                float e0 = expf(ss[r0 * SS_ST + cc] - m0);
                float e1 = expf(ss[r1 * SS_ST + cc] - m1);
                ph[r0 * (PH_W * 2) + cc] = __float2half_rn(e0);
                ph[r1 * (PH_W * 2) + cc] = __float2half_rn(e1);
                ps0 += e0; ps1 += e1;
            }
#pragma unroll
            for (int o = 4; o; o >>= 1) {
                ps0 += __shfl_down_sync(0xFFFFFFFFu, ps0, o, 8);
                ps1 += __shfl_down_sync(0xFFFFFFFFu, ps1, o, 8);
            }
            if (g == 0) { l_arr[r0] += ps0; l_arr[r1] += ps1; }
            float c0 = crow[wm * 16 + lr];
            float c1 = crow[wm * 16 + lr + 8];
#pragma unroll
            for (int nt = 0; nt < 4; nt++) {
                pacc[nt][0] *= c0; pacc[nt][1] *= c0;
                pacc[nt][2] *= c1; pacc[nt][3] *= c1;
            }
        }
        __syncthreads();

        {
#pragma unroll
            for (int kb = 0; kb < 2; kb++) {
                int kw = kb * 8;
                int ra = wm * 16 + lr;
                uint32_t a[4];
                a[0] = psh[ra * PH_W + kw + lc];
                a[1] = psh[(ra + 8) * PH_W + kw + lc];
                a[2] = psh[ra * PH_W + kw + lc + 4];
                a[3] = psh[(ra + 8) * PH_W + kw + lc + 4];
#pragma unroll
                for (int nt = 0; nt < 4; nt++) {
                    int n0 = wn * 32 + nt * 8;
                    uint32_t b0 = vst[(n0 + lr) * PH_W + kw + lc];
                    uint32_t b1 = vst[(n0 + lr) * PH_W + kw + lc + 4];
                    mma_f16(pacc[nt], a, b0, b1);
                }
            }
        }
    }
    __syncthreads();

    if (tid < 64 && m_arr[tid] < -5e29f) *anyflag = 1;
    __syncthreads();
    if (*anyflag) {
        int d = tid & 63, part = tid >> 6;
        float s = 0.f;
        for (int j = part; j < NKEYP; j += 4)
            if (keys_all[j] < SEQ) s += vsp[((size_t)h * NKEYP + j) * HD + d];
        vbar4[part * 64 + d] = s;
        __syncthreads();
        if (tid < 64)
            vbar[tid] = (vbar4[tid] + vbar4[64 + tid] + vbar4[128 + tid] + vbar4[192 + tid])
                        * (1.f / NKEY);
        __syncthreads();
    }

    {
        int r0 = wm * 16 + lr, r1 = r0 + 8;
        float i0 = 1.f / l_arr[r0], i1 = 1.f / l_arr[r1];
        bool f0 = m_arr[r0] < -5e29f, f1 = m_arr[r1] < -5e29f;
        __half* o0 = &attout[(size_t)(qb * 64 + r0) * DIM + h * HD];
        __half* o1 = &attout[(size_t)(qb * 64 + r1) * DIM + h * HD];
#pragma unroll
        for (int nt = 0; nt < 4; nt++) {
            int col = wn * 32 + nt * 8 + 2 * lc;
            o0[col]     = __float2half_rn(f0 ? vbar[col]     : pacc[nt][0] * i0);
            o0[col + 1] = __float2half_rn(f0 ? vbar[col + 1] : pacc[nt][1] * i0);
            o1[col]     = __float2half_rn(f1 ? vbar[col]     : pacc[nt][2] * i1);
            o1[col + 1] = __float2half_rn(f1 ? vbar[col + 1] : pacc[nt][3] * i1);
        }
    }
}

// --------------------------------- launch --------------------------------
extern "C" void kernel_launch(void* const* d_in, const int* in_sizes, int n_in,
                              void* d_out, int out_size) {
    const float* x    = (const float*)d_in[0];
    const float* fcos = (const float*)d_in[1];
    const float* fsin = (const float*)d_in[2];
    const float* wq   = (const float*)d_in[3];
    const float* wk   = (const float*)d_in[4];
    const float* wv   = (const float*)d_in[5];
    const float* wo   = (const float*)d_in[6];
    float* out = (float*)d_out;

    float *q, *q64, *q64p, *kv, *probs, *vert, *dgp, *ksp, *vsp;
    int* keys;
    __half *xh, *xl, *atth, *wqt, *wot, *wkth, *wktl, *wvt;
    cudaGetSymbolAddress((void**)&q, g_q);
    cudaGetSymbolAddress((void**)&q64, g_q64);
    cudaGetSymbolAddress((void**)&q64p, g_q64p);
    cudaGetSymbolAddress((void**)&kv, g_kv);
    cudaGetSymbolAddress((void**)&probs, g_probs);
    cudaGetSymbolAddress((void**)&vert, g_vert);
    cudaGetSymbolAddress((void**)&dgp, g_diag);
    cudaGetSymbolAddress((void**)&keys, g_keys);
    cudaGetSymbolAddress((void**)&ksp, g_ksp);
    cudaGetSymbolAddress((void**)&vsp, g_vsp);
    cudaGetSymbolAddress((void**)&xh, g_xh);
    cudaGetSymbolAddress((void**)&xl, g_xl);
    cudaGetSymbolAddress((void**)&atth, g_atth);
    cudaGetSymbolAddress((void**)&wqt, g_wqt);
    cudaGetSymbolAddress((void**)&wot, g_wot);
    cudaGetSymbolAddress((void**)&wkth, g_wkt_h);
    cudaGetSymbolAddress((void**)&wktl, g_wkt_l);
    cudaGetSymbolAddress((void**)&wvt, g_wvt);

    // prep
    split_h2<<<(SEQ * DIM / 4 + 255) / 256, 256>>>(x, xh, xl, SEQ * DIM / 4);
    transp_split_g<<<dim3(512 / 32, DIM / 32), dim3(32, 8)>>>(wk, wkth, wktl, 512);
    transp_half_g<<<dim3(512 / 32, DIM / 32), dim3(32, 8)>>>(wv, wvt, 512);
    transp_half_g<<<dim3(DIM / 32, DIM / 32), dim3(32, 8)>>>(wq, wqt, DIM);
    transp_half_g<<<dim3(DIM / 32, DIM / 32), dim3(32, 8)>>>(wo, wot, DIM);

    // projections: q 1x fp16; k 3-term fp16 (selection accuracy); v 1x fp16
    gemm_f16<<<dim3(DIM / 128, SEQ / 128), 256>>>(xh, wqt, q, SEQ, DIM, DIM, DIM);
    {
        size_t smb = (size_t)(2 * STG2W) * 4;
        cudaFuncSetAttribute(gemm_f16x3, cudaFuncAttributeMaxDynamicSharedMemorySize,
                             (int)smb);
        gemm_f16x3<<<dim3(512 / 128, SEQ / 128), 256, smb>>>(
            xh, xl, wkth, wktl, kv, SEQ, 512, DIM, KVW);
    }
    gemm_f16<<<dim3(512 / 128, SEQ / 128), 256>>>(xh, wvt, kv + 512, SEQ, 512, DIM, KVW);

    // exact fp32 q rows 0..63
    qproj_part<<<dim3(16, 8, 8), 128>>>(x, wq, q64p);
    qproj_red<<<(ESTQ * DIM + 255) / 256, 256>>>(q64p, q64);

    // RoPE
    {
        int tq = SEQ * NH * 32;
        rope_kernel<<<(tq + 255) / 256, 256>>>(q, fcos, fsin, NH, DIM, tq);
        int tk = SEQ * NKV * 32;
        rope_kernel<<<(tk + 255) / 256, 256>>>(kv, fcos, fsin, NKV, KVW, tk);
        int tq64 = ESTQ * NH * 32;
        rope_kernel<<<(tq64 + 255) / 256, 256>>>(q64, fcos, fsin, NH, DIM, tq64);
    }

    // estimation (TC scores)
    est_score<<<dim3(SEQ / 64, NH), 256>>>(q64, kv, probs);
    est_norm<<<dim3(ESTQ, NH), 256>>>(probs);

    vertical_kernel<<<(NH * SEQ) / 256, 256>>>(probs, vert);
    diag_kernel<<<(NH * SEQ) / 256, 256>>>(probs, dgp);

    topk2_kernel<<<64, 512>>>(vert, dgp, keys);
    sortkeys_kernel<<<NH, 256>>>(keys);

    gather_kernel<<<NH * NKEYP, 64>>>(kv, keys, ksp, vsp);

    {
        size_t spbytes = (size_t)SPV_WORDS * 4;
        cudaFuncSetAttribute(spattn_kernel,
                             cudaFuncAttributeMaxDynamicSharedMemorySize, (int)spbytes);
        spattn_kernel<<<dim3(SEQ / 64, NH), 256, spbytes>>>(q, ksp, vsp, keys, atth);
    }

    // output projection
    gemm_f16<<<dim3(DIM / 128, SEQ / 128), 256>>>(atth, wot, out, SEQ, DIM, DIM, DIM);
}

// round 17
// speedup vs baseline: 2.7146x; 1.1226x over previous
#include <cuda_runtime.h>
#include <cuda_fp16.h>
#include <math.h>
#include <stdint.h>

#define SEQ   4096
#define DIM   2048
#define NH    32
#define NKV   8
#define HD    64
#define ESTQ  64
#define VSZ   300
#define SSZ   800
#define NKEY  1100
#define NKEYP 1152
#define SCALE 0.125f
#define PADKEY 0x3FFFFFFF
#define KVW   1024

// ---------------- device scratch ----------------
__device__ float g_q[SEQ * DIM];
__device__ float g_q64[ESTQ * DIM];
__device__ float g_q64p[8 * ESTQ * DIM];
__device__ float g_kv[SEQ * KVW];
__device__ float g_probs[NH * ESTQ * SEQ];
__device__ float g_vert[NH * SEQ];
__device__ float g_diag[NH * SEQ];
__device__ int   g_keys[NH * NKEYP];
__device__ __half g_xh[SEQ * DIM];
__device__ __half g_xl[SEQ * DIM];
__device__ __half g_atth[SEQ * DIM];
__device__ __half g_wqt[DIM * DIM];
__device__ __half g_wot[DIM * DIM];
__device__ __half g_wkt_h[512 * DIM];
__device__ __half g_wkt_l[512 * DIM];
__device__ __half g_wvt[512 * DIM];

// ---------------- helpers ------------------------------------------------
__device__ __forceinline__ void mma_f16(float c[4], const uint32_t a[4],
                                        uint32_t b0, uint32_t b1) {
    asm volatile(
        "mma.sync.aligned.m16n8k16.row.col.f32.f16.f16.f32 "
        "{%0,%1,%2,%3}, {%4,%5,%6,%7}, {%8,%9}, {%0,%1,%2,%3};\n"
        : "+f"(c[0]), "+f"(c[1]), "+f"(c[2]), "+f"(c[3])
        : "r"(a[0]), "r"(a[1]), "r"(a[2]), "r"(a[3]), "r"(b0), "r"(b1));
}

__device__ __forceinline__ uint32_t smem_u32(const void* p) {
    uint32_t a;
    asm("{ .reg .u64 t; cvta.to.shared.u64 t, %1; cvt.u32.u64 %0, t; }" : "=r"(a) : "l"(p));
    return a;
}

// ================= fp16 k16 GEMM with cp.async double buffering ===========
#define AF_ST 20

__global__ __launch_bounds__(256) void gemm_f16(const __half* __restrict__ A,
                                                const __half* __restrict__ Bt,
                                                float* __restrict__ C,
                                                int M, int N, int K, int ldc) {
    __shared__ uint32_t As[2][128 * AF_ST];
    __shared__ uint32_t Bs[2][128 * AF_ST];
    int tid = threadIdx.x;
    int lane = tid & 31;
    int warp = tid >> 5;
    int wm = warp & 3;
    int wn = warp >> 2;
    int row0 = blockIdx.y * 128;
    int col0 = blockIdx.x * 128;
    int lr = lane >> 2;
    int lc = lane & 3;

    uint32_t asb[2], bsb[2];
    asb[0] = smem_u32(&As[0][0]);
    asb[1] = smem_u32(&As[1][0]);
    bsb[0] = smem_u32(&Bs[0][0]);
    bsb[1] = smem_u32(&Bs[1][0]);

    float acc[2][8][4];
#pragma unroll
    for (int mi = 0; mi < 2; mi++)
#pragma unroll
        for (int nj = 0; nj < 8; nj++)
#pragma unroll
            for (int e = 0; e < 4; e++) acc[mi][nj][e] = 0.f;

    int r_ld = tid >> 2;
    int j_ld = tid & 3;

    {
#pragma unroll
        for (int i = 0; i < 2; i++) {
            int r = r_ld + i * 64;
            uint32_t da = asb[0] + (uint32_t)(r * AF_ST + j_ld * 4) * 4;
            const __half* sa = A + (size_t)(row0 + r) * K + j_ld * 8;
            asm volatile("cp.async.ca.shared.global [%0], [%1], 16;" :: "r"(da), "l"(sa));
            uint32_t db = bsb[0] + (uint32_t)(r * AF_ST + j_ld * 4) * 4;
            const __half* sb = Bt + (size_t)(col0 + r) * K + j_ld * 8;
            asm volatile("cp.async.ca.shared.global [%0], [%1], 16;" :: "r"(db), "l"(sb));
        }
        asm volatile("cp.async.commit_group;");
    }

    int KC = K >> 5;
    for (int c = 0; c < KC; c++) {
        int buf = c & 1;
        if (c + 1 < KC) {
            int k0 = (c + 1) << 5;
            int nb = buf ^ 1;
#pragma unroll
            for (int i = 0; i < 2; i++) {
                int r = r_ld + i * 64;
                uint32_t da = asb[nb] + (uint32_t)(r * AF_ST + j_ld * 4) * 4;
                const __half* sa = A + (size_t)(row0 + r) * K + k0 + j_ld * 8;
                asm volatile("cp.async.ca.shared.global [%0], [%1], 16;" :: "r"(da), "l"(sa));
                uint32_t db = bsb[nb] + (uint32_t)(r * AF_ST + j_ld * 4) * 4;
                const __half* sb = Bt + (size_t)(col0 + r) * K + k0 + j_ld * 8;
                asm volatile("cp.async.ca.shared.global [%0], [%1], 16;" :: "r"(db), "l"(sb));
            }
            asm volatile("cp.async.commit_group;");
            asm volatile("cp.async.wait_group 1;");
        } else {
            asm volatile("cp.async.wait_group 0;");
        }
        __syncthreads();

        const uint32_t* Ab = As[buf];
        const uint32_t* Bb = Bs[buf];
#pragma unroll
        for (int ks = 0; ks < 2; ks++) {
            int kb = ks * 8;
            uint32_t a[2][4];
#pragma unroll
            for (int mi = 0; mi < 2; mi++) {
                int ra = wm * 32 + mi * 16 + lr;
                a[mi][0] = Ab[ra * AF_ST + kb + lc];
                a[mi][1] = Ab[(ra + 8) * AF_ST + kb + lc];
                a[mi][2] = Ab[ra * AF_ST + kb + lc + 4];
                a[mi][3] = Ab[(ra + 8) * AF_ST + kb + lc + 4];
            }
#pragma unroll
            for (int nj = 0; nj < 8; nj++) {
                int col = wn * 64 + nj * 8 + lr;
                uint32_t b0 = Bb[col * AF_ST + kb + lc];
                uint32_t b1 = Bb[col * AF_ST + kb + lc + 4];
                mma_f16(acc[0][nj], a[0], b0, b1);
                mma_f16(acc[1][nj], a[1], b0, b1);
            }
        }
        __syncthreads();
    }

#pragma unroll
    for (int mi = 0; mi < 2; mi++) {
        int row = row0 + wm * 32 + mi * 16 + lr;
#pragma unroll
        for (int nj = 0; nj < 8; nj++) {
            int col = col0 + wn * 64 + nj * 8 + 2 * lc;
            float* cp0 = C + (size_t)row * ldc + col;
            cp0[0] = acc[mi][nj][0];
            cp0[1] = acc[mi][nj][1];
            float* cp1 = C + (size_t)(row + 8) * ldc + col;
            cp1[0] = acc[mi][nj][2];
            cp1[1] = acc[mi][nj][3];
        }
    }
}

// ===== fp16 hi/lo 3-term GEMM, BK=16 (k projection) =====
#define AK_ST 12
#define STG2W (4 * 128 * AK_ST)

__global__ __launch_bounds__(256) void gemm_f16x3(const __half* __restrict__ AH,
                                                  const __half* __restrict__ AL,
                                                  const __half* __restrict__ BH,
                                                  const __half* __restrict__ BL,
                                                  float* __restrict__ C,
                                                  int M, int N, int K, int ldc) {
    extern __shared__ uint32_t sm[];
    uint32_t base = smem_u32(sm);
    int tid = threadIdx.x;
    int lane = tid & 31;
    int warp = tid >> 5;
    int wm = warp & 3;
    int wn = warp >> 2;
    int row0 = blockIdx.y * 128;
    int col0 = blockIdx.x * 128;
    int lr = lane >> 2;
    int lc = lane & 3;

    float acc[2][8][4];
#pragma unroll
    for (int mi = 0; mi < 2; mi++)
#pragma unroll
        for (int nj = 0; nj < 8; nj++)
#pragma unroll
            for (int e = 0; e < 4; e++) acc[mi][nj][e] = 0.f;

    int r_ld = tid >> 1;
    int j_ld = tid & 1;

    auto issue = [&](int stage, int k0) {
        uint32_t sb = base + (uint32_t)stage * STG2W * 4;
        uint32_t off = (uint32_t)(r_ld * AK_ST + j_ld * 4) * 4;
        const __half* pa = AH + (size_t)(row0 + r_ld) * K + k0 + j_ld * 8;
        asm volatile("cp.async.ca.shared.global [%0], [%1], 16;" :: "r"(sb + off), "l"(pa));
        const __half* pl = AL + (size_t)(row0 + r_ld) * K + k0 + j_ld * 8;
        asm volatile("cp.async.ca.shared.global [%0], [%1], 16;"
                     :: "r"(sb + (uint32_t)(128 * AK_ST) * 4 + off), "l"(pl));
        const __half* pb = BH + (size_t)(col0 + r_ld) * K + k0 + j_ld * 8;
        asm volatile("cp.async.ca.shared.global [%0], [%1], 16;"
                     :: "r"(sb + (uint32_t)(2 * 128 * AK_ST) * 4 + off), "l"(pb));
        const __half* pc = BL + (size_t)(col0 + r_ld) * K + k0 + j_ld * 8;
        asm volatile("cp.async.ca.shared.global [%0], [%1], 16;"
                     :: "r"(sb + (uint32_t)(3 * 128 * AK_ST) * 4 + off), "l"(pc));
        asm volatile("cp.async.commit_group;");
    };

    issue(0, 0);

    int KC = K >> 4;
    for (int c = 0; c < KC; c++) {
        int buf = c & 1;
        if (c + 1 < KC) {
            issue(buf ^ 1, (c + 1) << 4);
            asm volatile("cp.async.wait_group 1;");
        } else {
            asm volatile("cp.async.wait_group 0;");
        }
        __syncthreads();

        const uint32_t* AsH = sm + (size_t)buf * STG2W;
        const uint32_t* AsL = AsH + 128 * AK_ST;
        const uint32_t* BsH = AsH + 2 * 128 * AK_ST;
        const uint32_t* BsL = AsH + 3 * 128 * AK_ST;
        uint32_t aH[2][4], aL[2][4];
#pragma unroll
        for (int mi = 0; mi < 2; mi++) {
            int ra = wm * 32 + mi * 16 + lr;
            aH[mi][0] = AsH[ra * AK_ST + lc];
            aH[mi][1] = AsH[(ra + 8) * AK_ST + lc];
            aH[mi][2] = AsH[ra * AK_ST + lc + 4];
            aH[mi][3] = AsH[(ra + 8) * AK_ST + lc + 4];
            aL[mi][0] = AsL[ra * AK_ST + lc];
            aL[mi][1] = AsL[(ra + 8) * AK_ST + lc];
            aL[mi][2] = AsL[ra * AK_ST + lc + 4];
            aL[mi][3] = AsL[(ra + 8) * AK_ST + lc + 4];
        }
#pragma unroll
        for (int nj = 0; nj < 8; nj++) {
            int col = wn * 64 + nj * 8 + lr;
            uint32_t b0h = BsH[col * AK_ST + lc];
            uint32_t b1h = BsH[col * AK_ST + lc + 4];
            uint32_t b0l = BsL[col * AK_ST + lc];
            uint32_t b1l = BsL[col * AK_ST + lc + 4];
#pragma unroll
            for (int mi = 0; mi < 2; mi++) {
                mma_f16(acc[mi][nj], aH[mi], b0h, b1h);
                mma_f16(acc[mi][nj], aH[mi], b0l, b1l);
                mma_f16(acc[mi][nj], aL[mi], b0h, b1h);
            }
        }
        __syncthreads();
    }

#pragma unroll
    for (int mi = 0; mi < 2; mi++) {
        int row = row0 + wm * 32 + mi * 16 + lr;
#pragma unroll
        for (int nj = 0; nj < 8; nj++) {
            int col = col0 + wn * 64 + nj * 8 + 2 * lc;
            float* cp0 = C + (size_t)row * ldc + col;
            cp0[0] = acc[mi][nj][0];
            cp0[1] = acc[mi][nj][1];
            float* cp1 = C + (size_t)(row + 8) * ldc + col;
            cp1[0] = acc[mi][nj][2];
            cp1[1] = acc[mi][nj][3];
        }
    }
}

// ---------------- prep kernels ---------------------------------------------
__global__ void split_h2(const float* __restrict__ a, __half* __restrict__ h,
                         __half* __restrict__ l, int n4) {
    int i = blockIdx.x * 256 + threadIdx.x;
    if (i >= n4) return;
    float4 v = ((const float4*)a)[i];
    __half hx = __float2half_rn(v.x), hy = __float2half_rn(v.y);
    __half hz = __float2half_rn(v.z), hw = __float2half_rn(v.w);
    __half2 h0 = __halves2half2(hx, hy);
    __half2 h1 = __halves2half2(hz, hw);
    ((uint2*)h)[i] = make_uint2(*(uint32_t*)&h0, *(uint32_t*)&h1);
    __half2 l0 = __halves2half2(__float2half_rn(v.x - __half2float(hx)),
                                __float2half_rn(v.y - __half2float(hy)));
    __half2 l1 = __halves2half2(__float2half_rn(v.z - __half2float(hz)),
                                __float2half_rn(v.w - __half2float(hw)));
    ((uint2*)l)[i] = make_uint2(*(uint32_t*)&l0, *(uint32_t*)&l1);
}

__global__ void transp_split_g(const float* __restrict__ w, __half* __restrict__ th,
                               __half* __restrict__ tl, int ncols) {
    __shared__ float tile[32][33];
    int bx = blockIdx.x * 32;
    int by = blockIdx.y * 32;
    int tx = threadIdx.x, ty = threadIdx.y;
    for (int i = 0; i < 32; i += 8)
        tile[ty + i][tx] = w[(size_t)(by + ty + i) * ncols + bx + tx];
    __syncthreads();
    for (int i = 0; i < 32; i += 8) {
        float v = tile[tx][ty + i];
        __half h = __float2half_rn(v);
        th[(size_t)(bx + ty + i) * DIM + by + tx] = h;
        tl[(size_t)(bx + ty + i) * DIM + by + tx] = __float2half_rn(v - __half2float(h));
    }
}

__global__ void transp_half_g(const float* __restrict__ w, __half* __restrict__ t, int ncols) {
    __shared__ float tile[32][33];
    int bx = blockIdx.x * 32;
    int by = blockIdx.y * 32;
    int tx = threadIdx.x, ty = threadIdx.y;
    for (int i = 0; i < 32; i += 8)
        tile[ty + i][tx] = w[(size_t)(by + ty + i) * ncols + bx + tx];
    __syncthreads();
    for (int i = 0; i < 32; i += 8)
        t[(size_t)(bx + ty + i) * DIM + by + tx] = __float2half_rn(tile[tx][ty + i]);
}

// ---------------- exact fp32 q rows 0..63: split-K ---------------------------
__global__ __launch_bounds__(128) void qproj_part(const float* __restrict__ x,
                                                  const float* __restrict__ wq,
                                                  float* __restrict__ part) {
    __shared__ float xs[8][256];
    int tid = threadIdx.x;
    int col = blockIdx.x * 128 + tid;
    int r0 = blockIdx.y * 8;
    int k0 = blockIdx.z * 256;
    float acc[8];
#pragma unroll
    for (int rr = 0; rr < 8; rr++) acc[rr] = 0.f;

    for (int i = tid; i < 8 * 256; i += 128) {
        int rr = i >> 8, kk = i & 255;
        xs[rr][kk] = x[(size_t)(r0 + rr) * DIM + k0 + kk];
    }
    __syncthreads();
    for (int kk = 0; kk < 256; kk++) {
        float w = wq[(size_t)(k0 + kk) * DIM + col];
#pragma unroll
        for (int rr = 0; rr < 8; rr++) acc[rr] += xs[rr][kk] * w;
    }
#pragma unroll
    for (int rr = 0; rr < 8; rr++)
        part[(size_t)blockIdx.z * ESTQ * DIM + (size_t)(r0 + rr) * DIM + col] = acc[rr];
}

__global__ void qproj_red(const float* __restrict__ part, float* __restrict__ q64) {
    int idx = blockIdx.x * 256 + threadIdx.x;
    if (idx >= ESTQ * DIM) return;
    float s = 0.f;
#pragma unroll
    for (int ks = 0; ks < 8; ks++) s += part[(size_t)ks * ESTQ * DIM + idx];
    q64[idx] = s;
}

// ---------------- RoPE -------------------------------------------------------
__global__ void rope_kernel(float* t, const float* __restrict__ cosb,
                            const float* __restrict__ sinb, int H, int stride, int total) {
    int idx = blockIdx.x * blockDim.x + threadIdx.x;
    if (idx >= total) return;
    int d2 = idx & 31;
    int h = (idx >> 5) % H;
    int s = idx / (32 * H);
    float c = cosb[s * 32 + d2];
    float sn = sinb[s * 32 + d2];
    float* p = t + (size_t)s * stride + h * 64 + 2 * d2;
    float xr = p[0], xi = p[1];
    p[0] = xr * c - xi * sn;
    p[1] = xr * sn + xi * c;
}

// ---------------- est phase A: TC scores (fp16 hi/lo 3-term) ------------------
#define ES_ST 36

__global__ __launch_bounds__(256) void est_score(const float* __restrict__ q64,
                                                 const float* __restrict__ kv,
                                                 float* __restrict__ probs) {
    __shared__ uint32_t qh[64 * ES_ST];
    __shared__ uint32_t ql[64 * ES_ST];
    __shared__ uint32_t kh[64 * ES_ST];
    __shared__ uint32_t kl[64 * ES_ST];
    int tid = threadIdx.x;
    int lane = tid & 31;
    int warp = tid >> 5;
    int lr = lane >> 2;
    int lc = lane & 3;
    int wm = warp & 3;
    int wn = warp >> 2;
    int h = blockIdx.y;
    int c0 = blockIdx.x * 64;
    int kvh = h >> 2;

    for (int l = tid; l < 64 * 16; l += 256) {
        int r = l >> 4, c4 = (l & 15) * 4;
        float4 v = *(const float4*)&q64[(size_t)r * DIM + h * HD + c4];
        __half hx = __float2half_rn(v.x), hy = __float2half_rn(v.y);
        __half hz = __float2half_rn(v.z), hw = __float2half_rn(v.w);
        __half2 p0 = __halves2half2(hx, hy);
        __half2 p1 = __halves2half2(hz, hw);
        qh[r * ES_ST + c4 / 2] = *(uint32_t*)&p0;
        qh[r * ES_ST + c4 / 2 + 1] = *(uint32_t*)&p1;
        __half2 q0 = __halves2half2(__float2half_rn(v.x - __half2float(hx)),
                                    __float2half_rn(v.y - __half2float(hy)));
        __half2 q1 = __halves2half2(__float2half_rn(v.z - __half2float(hz)),
                                    __float2half_rn(v.w - __half2float(hw)));
        ql[r * ES_ST + c4 / 2] = *(uint32_t*)&q0;
        ql[r * ES_ST + c4 / 2 + 1] = *(uint32_t*)&q1;

        float4 kvv = *(const float4*)&kv[(size_t)(c0 + r) * KVW + kvh * HD + c4];
        __half kx = __float2half_rn(kvv.x), ky = __float2half_rn(kvv.y);
        __half kz = __float2half_rn(kvv.z), kw = __float2half_rn(kvv.w);
        __half2 r0 = __halves2half2(kx, ky);
        __half2 r1 = __halves2half2(kz, kw);
        kh[r * ES_ST + c4 / 2] = *(uint32_t*)&r0;
        kh[r * ES_ST + c4 / 2 + 1] = *(uint32_t*)&r1;
        __half2 s0 = __halves2half2(__float2half_rn(kvv.x - __half2float(kx)),
                                    __float2half_rn(kvv.y - __half2float(ky)));
        __half2 s1 = __halves2half2(__float2half_rn(kvv.z - __half2float(kz)),
                                    __float2half_rn(kvv.w - __half2float(kw)));
        kl[r * ES_ST + c4 / 2] = *(uint32_t*)&s0;
        kl[r * ES_ST + c4 / 2 + 1] = *(uint32_t*)&s1;
    }
    __syncthreads();

    float acc[4][4];
#pragma unroll
    for (int nt = 0; nt < 4; nt++)
#pragma unroll
        for (int e = 0; e < 4; e++) acc[nt][e] = 0.f;

#pragma unroll
    for (int kc = 0; kc < 4; kc++) {
        int kw = kc * 8;
        int ra = wm * 16 + lr;
        uint32_t aH[4], aL[4];
        aH[0] = qh[ra * ES_ST + kw + lc];
        aH[1] = qh[(ra + 8) * ES_ST + kw + lc];
        aH[2] = qh[ra * ES_ST + kw + lc + 4];
        aH[3] = qh[(ra + 8) * ES_ST + kw + lc + 4];
        aL[0] = ql[ra * ES_ST + kw + lc];
        aL[1] = ql[(ra + 8) * ES_ST + kw + lc];
        aL[2] = ql[ra * ES_ST + kw + lc + 4];
        aL[3] = ql[(ra + 8) * ES_ST + kw + lc + 4];
#pragma unroll
        for (int nt = 0; nt < 4; nt++) {
            int n0 = wn * 32 + nt * 8;
            uint32_t b0h = kh[(n0 + lr) * ES_ST + kw + lc];
            uint32_t b1h = kh[(n0 + lr) * ES_ST + kw + lc + 4];
            uint32_t b0l = kl[(n0 + lr) * ES_ST + kw + lc];
            uint32_t b1l = kl[(n0 + lr) * ES_ST + kw + lc + 4];
            mma_f16(acc[nt], aH, b0h, b1h);
            mma_f16(acc[nt], aH, b0l, b1l);
            mma_f16(acc[nt], aL, b0h, b1h);
        }
    }

#pragma unroll
    for (int nt = 0; nt < 4; nt++) {
        int row = wm * 16 + lr;
        int col = wn * 32 + nt * 8 + 2 * lc;
#pragma unroll
        for (int e = 0; e < 4; e++) {
            int rr = row + (e >> 1) * 8;
            int cc = col + (e & 1);
            int kk = c0 + cc;
            float val = acc[nt][e] * SCALE;
            if (kk >= SEQ - ESTQ && rr < kk - (SEQ - ESTQ)) val = -INFINITY;
            probs[((size_t)h * ESTQ + rr) * SEQ + kk] = val;
        }
    }
}

// ---------------- est phase B -------------------------------------------------
__global__ __launch_bounds__(256) void est_norm(float* __restrict__ probs) {
    int qi = blockIdx.x;
    int h = blockIdx.y;
    __shared__ float sc[SEQ];
    __shared__ float red[8];
    int tid = threadIdx.x;
    float* pr = probs + ((size_t)h * ESTQ + qi) * SEQ;

    for (int l = tid; l < SEQ / 4; l += 256)
        *(float4*)&sc[l * 4] = *(const float4*)&pr[l * 4];
    __syncthreads();

    float m = -INFINITY;
    for (int kk = tid; kk < SEQ; kk += 256) m = fmaxf(m, sc[kk]);
#pragma unroll
    for (int o = 16; o; o >>= 1) m = fmaxf(m, __shfl_xor_sync(0xFFFFFFFFu, m, o));
    if ((tid & 31) == 0) red[tid >> 5] = m;
    __syncthreads();
    if (tid == 0) {
        float mm = red[0];
#pragma unroll
        for (int i = 1; i < 8; i++) mm = fmaxf(mm, red[i]);
        red[0] = mm;
    }
    __syncthreads();
    m = red[0];
    __syncthreads();

    float s = 0.f;
    for (int kk = tid; kk < SEQ; kk += 256) {
        float e = expf(sc[kk] - m);
        sc[kk] = e;
        s += e;
    }
#pragma unroll
    for (int o = 16; o; o >>= 1) s += __shfl_xor_sync(0xFFFFFFFFu, s, o);
    if ((tid & 31) == 0) red[tid >> 5] = s;
    __syncthreads();
    if (tid == 0) {
        float ss = 0.f;
#pragma unroll
        for (int i = 0; i < 8; i++) ss += red[i];
        red[0] = ss;
    }
    __syncthreads();
    float inv = 1.f / red[0];
    for (int kk = tid; kk < SEQ; kk += 256) pr[kk] = sc[kk] * inv;
}

// ---------------- vertical / diagonal ------------------------------------------
__global__ void vertical_kernel(const float* __restrict__ probs, float* __restrict__ vert) {
    int idx = blockIdx.x * 256 + threadIdx.x;
    int h = idx >> 12;
    int kk = idx & (SEQ - 1);
    float s = 0.f;
    const float* base = probs + (size_t)h * ESTQ * SEQ + kk;
    for (int i = 0; i < ESTQ; i++) s += base[(size_t)i * SEQ];
    vert[idx] = s;
}

__global__ void diag_kernel(const float* __restrict__ probs, float* __restrict__ dg) {
    int idx = blockIdx.x * 256 + threadIdx.x;
    int h = idx >> 12;
    int jp = idx & (SEQ - 1);
    float s = 0.f;
    const float* base = probs + (size_t)h * ESTQ * SEQ;
    for (int i = 0; i < ESTQ; i++) {
        int col = i + jp - 63;
        if (col >= 0 && col < SEQ) s += base[(size_t)i * SEQ + col];
    }
    dg[idx] = s;
}

// ---------------- merged top-k ---------------------------------------------------
__global__ void topk2_kernel(const float* __restrict__ vert, const float* __restrict__ dg,
                             int* __restrict__ keys) {
    int b = blockIdx.x;
    int mode = b >> 5;
    int h = b & 31;
    const float* vals = mode ? dg : vert;
    int kcount = mode ? SSZ : VSZ;
    __shared__ unsigned long long a[SEQ];
    int tid = threadIdx.x;
    for (int i = tid; i < SEQ; i += 512) {
        unsigned u = __float_as_uint(vals[h * SEQ + i]);
        u = (u & 0x80000000u) ? ~u : (u | 0x80000000u);
        a[i] = ((unsigned long long)(~u) << 32) | (unsigned)i;
    }
    __syncthreads();
    for (int k = 2; k <= SEQ; k <<= 1) {
        for (int j = k >> 1; j > 0; j >>= 1) {
            for (int i = tid; i < SEQ; i += 512) {
                int ixj = i ^ j;
                if (ixj > i) {
                    bool up = ((i & k) == 0);
                    unsigned long long x = a[i], y = a[ixj];
                    if (up ? (x > y) : (x < y)) { a[i] = y; a[ixj] = x; }
                }
            }
            __syncthreads();
        }
    }
    if (mode == 0) {
        for (int t = tid; t < kcount; t += 512)
            keys[h * NKEYP + t] = (int)(a[t] & 0xFFFFFFFFull);
    } else {
        for (int t = tid; t < kcount; t += 512)
            keys[h * NKEYP + VSZ + t] = (SEQ - 1) - (int)(a[t] & 0xFFFFFFFFull);
        for (int t = NKEY + tid; t < NKEYP; t += 512) keys[h * NKEYP + t] = PADKEY;
    }
}

// ---------------- sort keys ascending per head ----------------------------------
__global__ __launch_bounds__(256) void sortkeys_kernel(int* __restrict__ keys) {
    int h = blockIdx.x;
    __shared__ int a[2048];
    int tid = threadIdx.x;
    for (int i = tid; i < 2048; i += 256)
        a[i] = (i < NKEYP) ? keys[h * NKEYP + i] : PADKEY;
    __syncthreads();
    for (int k = 2; k <= 2048; k <<= 1) {
        for (int j = k >> 1; j > 0; j >>= 1) {
            for (int i = tid; i < 2048; i += 256) {
                int ixj = i ^ j;
                if (ixj > i) {
                    bool up = ((i & k) == 0);
                    int x = a[i], y = a[ixj];
                    if (up ? (x > y) : (x < y)) { a[i] = y; a[ixj] = x; }
                }
            }
            __syncthreads();
        }
    }
    for (int i = tid; i < NKEYP; i += 256) keys[h * NKEYP + i] = a[i];
}

// -------- sparse attention v5: fp16x3 QK + fp16 PV, direct kv gather ----------
// smem (u32 words): qh/ql 64*36 ea, kh/kl 32*36 ea, ss 64*36 f32,
// psh 64*20, vst 64*20, keys 1152, m/l/crow/vbar 64 ea, vbar4 256, flag 8
#define QS_ST 36
#define SS_ST 36
#define PH_W 20
#define SPV_WORDS (2*64*36 + 2*32*36 + 64*36 + 64*20 + 64*20 + 1152 + 4*64 + 4*64 + 8)

__global__ __launch_bounds__(256) void spattn_kernel(const float* __restrict__ q,
                                                     const float* __restrict__ kv,
                                                     const int* __restrict__ keys,
                                                     __half* __restrict__ attout) {
    extern __shared__ uint32_t smem[];
    uint32_t* qh = smem;                       // 64*36
    uint32_t* ql = qh + 64 * QS_ST;            // 64*36
    uint32_t* kh = ql + 64 * QS_ST;            // 32*36
    uint32_t* kl = kh + 32 * QS_ST;            // 32*36
    float* ss = (float*)(kl + 32 * QS_ST);     // 64*36
    uint32_t* psh = (uint32_t*)(ss + 64 * SS_ST);
    uint32_t* vst = psh + 64 * PH_W;
    int* keys_all = (int*)(vst + 64 * PH_W);
    float* m_arr = (float*)(keys_all + 1152);
    float* l_arr = m_arr + 64;
    float* crow = l_arr + 64;
    float* vbar = crow + 64;
    float* vbar4 = vbar + 64;
    int* anyflag = (int*)(vbar4 + 4 * 64);

    int qb = blockIdx.x;
    int h = blockIdx.y;
    int tid = threadIdx.x;
    int lane = tid & 31;
    int warp = tid >> 5;
    int lr = lane >> 2;
    int lc = lane & 3;
    int wm = warp & 3;
    int wn = warp >> 2;
    int qp = tid >> 3;
    int g = tid & 7;
    int kvh = h >> 2;
    int qbmax = qb * 64 + 63;

    for (int i = tid; i < NKEYP; i += 256) keys_all[i] = keys[h * NKEYP + i];
    if (tid < 64) { m_arr[tid] = -INFINITY; l_arr[tid] = 0.f; }
    if (tid == 0) *anyflag = 0;
    // q tile -> fp16 hi/lo
    for (int l = tid; l < 64 * 16; l += 256) {
        int r = l >> 4, c4 = (l & 15) * 4;
        float4 v = *(const float4*)&q[(size_t)(qb * 64 + r) * DIM + h * HD + c4];
        __half hx = __float2half_rn(v.x), hy = __float2half_rn(v.y);
        __half hz = __float2half_rn(v.z), hw = __float2half_rn(v.w);
        __half2 p0 = __halves2half2(hx, hy);
        __half2 p1 = __halves2half2(hz, hw);
        qh[r * QS_ST + c4 / 2] = *(uint32_t*)&p0;
        qh[r * QS_ST + c4 / 2 + 1] = *(uint32_t*)&p1;
        __half2 q0 = __halves2half2(__float2half_rn(v.x - __half2float(hx)),
                                    __float2half_rn(v.y - __half2float(hy)));
        __half2 q1 = __halves2half2(__float2half_rn(v.z - __half2float(hz)),
                                    __float2half_rn(v.w - __half2float(hw)));
        ql[r * QS_ST + c4 / 2] = *(uint32_t*)&q0;
        ql[r * QS_ST + c4 / 2 + 1] = *(uint32_t*)&q1;
    }
    __syncthreads();

    float pacc[4][4];
#pragma unroll
    for (int nt = 0; nt < 4; nt++)
#pragma unroll
        for (int e = 0; e < 4; e++) pacc[nt][e] = 0.f;

    for (int t = 0; t < NKEYP / 32; t++) {
        if (keys_all[t * 32] > qbmax) continue;
        __syncthreads();

        // k tile: gather from kv, convert to fp16 hi/lo
        for (int l = tid; l < 32 * 16; l += 256) {
            int r = l >> 4, c4 = (l & 15) * 4;
            int key = keys_all[t * 32 + r];
            float4 kvv = (key < SEQ)
                ? *(const float4*)&kv[(size_t)key * KVW + kvh * HD + c4]
                : make_float4(0.f, 0.f, 0.f, 0.f);
            __half kx = __float2half_rn(kvv.x), ky = __float2half_rn(kvv.y);
            __half kz = __float2half_rn(kvv.z), kw = __float2half_rn(kvv.w);
            __half2 r0 = __halves2half2(kx, ky);
            __half2 r1 = __halves2half2(kz, kw);
            kh[r * QS_ST + c4 / 2] = *(uint32_t*)&r0;
            kh[r * QS_ST + c4 / 2 + 1] = *(uint32_t*)&r1;
            __half2 s0 = __halves2half2(__float2half_rn(kvv.x - __half2float(kx)),
                                        __float2half_rn(kvv.y - __half2float(ky)));
            __half2 s1 = __halves2half2(__float2half_rn(kvv.z - __half2float(kz)),
                                        __float2half_rn(kvv.w - __half2float(kw)));
            kl[r * QS_ST + c4 / 2] = *(uint32_t*)&s0;
            kl[r * QS_ST + c4 / 2 + 1] = *(uint32_t*)&s1;
        }
        // V^T tile: gather from kv, fp16
        {
            int j = tid >> 3;
            int d8 = (tid & 7) * 8;
            int key = keys_all[t * 32 + j];
            float4 v0, v1;
            if (key < SEQ) {
                const float* vr = &kv[(size_t)key * KVW + 512 + kvh * HD + d8];
                v0 = *(const float4*)vr;
                v1 = *(const float4*)(vr + 4);
            } else {
                v0 = make_float4(0.f, 0.f, 0.f, 0.f);
                v1 = v0;
            }
            __half* vh = (__half*)vst;
#pragma unroll
            for (int i = 0; i < 4; i++)
                vh[(d8 + i) * (PH_W * 2) + j] = __float2half_rn(((const float*)&v0)[i]);
#pragma unroll
            for (int i = 0; i < 4; i++)
                vh[(d8 + 4 + i) * (PH_W * 2) + j] = __float2half_rn(((const float*)&v1)[i]);
        }
        __syncthreads();

        // QK MMA (fp16 hi/lo 3-term, K=64 = 4 k16 chunks)
        {
            float acc[2][4];
#pragma unroll
            for (int nt = 0; nt < 2; nt++)
#pragma unroll
                for (int e = 0; e < 4; e++) acc[nt][e] = 0.f;
#pragma unroll
            for (int kc = 0; kc < 4; kc++) {
                int kw = kc * 8;
                int ra = wm * 16 + lr;
                uint32_t aH[4], aL[4];
                aH[0] = qh[ra * QS_ST + kw + lc];
                aH[1] = qh[(ra + 8) * QS_ST + kw + lc];
                aH[2] = qh[ra * QS_ST + kw + lc + 4];
                aH[3] = qh[(ra + 8) * QS_ST + kw + lc + 4];
                aL[0] = ql[ra * QS_ST + kw + lc];
                aL[1] = ql[(ra + 8) * QS_ST + kw + lc];
                aL[2] = ql[ra * QS_ST + kw + lc + 4];
                aL[3] = ql[(ra + 8) * QS_ST + kw + lc + 4];
#pragma unroll
                for (int nt = 0; nt < 2; nt++) {
                    int n0 = wn * 16 + nt * 8;
                    uint32_t b0h = kh[(n0 + lr) * QS_ST + kw + lc];
                    uint32_t b1h = kh[(n0 + lr) * QS_ST + kw + lc + 4];
                    uint32_t b0l = kl[(n0 + lr) * QS_ST + kw + lc];
                    uint32_t b1l = kl[(n0 + lr) * QS_ST + kw + lc + 4];
                    mma_f16(acc[nt], aH, b0h, b1h);
                    mma_f16(acc[nt], aH, b0l, b1l);
                    mma_f16(acc[nt], aL, b0h, b1h);
                }
            }
#pragma unroll
            for (int nt = 0; nt < 2; nt++) {
                int row = wm * 16 + lr;
                int col = wn * 16 + nt * 8 + 2 * lc;
#pragma unroll
                for (int e = 0; e < 4; e++) {
                    int rr = row + (e >> 1) * 8;
                    int cc = col + (e & 1);
                    int key = keys_all[t * 32 + cc];
                    int sg = qb * 64 + rr;
                    float val;
                    if (key >= SEQ) val = -INFINITY;
                    else val = (key <= sg) ? acc[nt][e] * SCALE : -1e30f;
                    ss[rr * SS_ST + cc] = val;
                }
            }
        }
        __syncthreads();

        if (tid < 64) {
            int r = tid;
            float tm = m_arr[r];
#pragma unroll
            for (int j = 0; j < 32; j++) tm = fmaxf(tm, ss[r * SS_ST + j]);
            float c = expf(m_arr[r] - tm);
            crow[r] = c;
            m_arr[r] = tm;
            l_arr[r] *= c;
        }
        __syncthreads();

        {
            int r0 = qp, r1 = qp + 32;
            float m0 = m_arr[r0], m1 = m_arr[r1];
            float ps0 = 0.f, ps1 = 0.f;
            __half* ph = (__half*)psh;
#pragma unroll
            for (int j = 0; j < 4; j++) {
                int cc = g * 4 + j;
                float e0 = expf(ss[r0 * SS_ST + cc] - m0);
                float e1 = expf(ss[r1 * SS_ST + cc] - m1);
                ph[r0 * (PH_W * 2) + cc] = __float2half_rn(e0);
                ph[r1 * (PH_W * 2) + cc] = __float2half_rn(e1);
                ps0 += e0; ps1 += e1;
            }
#pragma unroll
            for (int o = 4; o; o >>= 1) {
                ps0 += __shfl_down_sync(0xFFFFFFFFu, ps0, o, 8);
                ps1 += __shfl_down_sync(0xFFFFFFFFu, ps1, o, 8);
            }
            if (g == 0) { l_arr[r0] += ps0; l_arr[r1] += ps1; }
            float c0 = crow[wm * 16 + lr];
            float c1 = crow[wm * 16 + lr + 8];
#pragma unroll
            for (int nt = 0; nt < 4; nt++) {
                pacc[nt][0] *= c0; pacc[nt][1] *= c0;
                pacc[nt][2] *= c1; pacc[nt][3] *= c1;
            }
        }
        __syncthreads();

        {
#pragma unroll
            for (int kb = 0; kb < 2; kb++) {
                int kw = kb * 8;
                int ra = wm * 16 + lr;
                uint32_t a[4];
                a[0] = psh[ra * PH_W + kw + lc];
                a[1] = psh[(ra + 8) * PH_W + kw + lc];
                a[2] = psh[ra * PH_W + kw + lc + 4];
                a[3] = psh[(ra + 8) * PH_W + kw + lc + 4];
#pragma unroll
                for (int nt = 0; nt < 4; nt++) {
                    int n0 = wn * 32 + nt * 8;
                    uint32_t b0 = vst[(n0 + lr) * PH_W + kw + lc];
                    uint32_t b1 = vst[(n0 + lr) * PH_W + kw + lc + 4];
                    mma_f16(pacc[nt], a, b0, b1);
                }
            }
        }
    }
    __syncthreads();

    if (tid < 64 && m_arr[tid] < -5e29f) *anyflag = 1;
    __syncthreads();
    if (*anyflag) {
        int d = tid & 63, part = tid >> 6;
        float s = 0.f;
        for (int j = part; j < NKEYP; j += 4) {
            int key = keys_all[j];
            if (key < SEQ) s += kv[(size_t)key * KVW + 512 + kvh * HD + d];
        }
        vbar4[part * 64 + d] = s;
        __syncthreads();
        if (tid < 64)
            vbar[tid] = (vbar4[tid] + vbar4[64 + tid] + vbar4[128 + tid] + vbar4[192 + tid])
                        * (1.f / NKEY);
        __syncthreads();
    }

    {
        int r0 = wm * 16 + lr, r1 = r0 + 8;
        float i0 = 1.f / l_arr[r0], i1 = 1.f / l_arr[r1];
        bool f0 = m_arr[r0] < -5e29f, f1 = m_arr[r1] < -5e29f;
        __half* o0 = &attout[(size_t)(qb * 64 + r0) * DIM + h * HD];
        __half* o1 = &attout[(size_t)(qb * 64 + r1) * DIM + h * HD];
#pragma unroll
        for (int nt = 0; nt < 4; nt++) {
            int col = wn * 32 + nt * 8 + 2 * lc;
            o0[col]     = __float2half_rn(f0 ? vbar[col]     : pacc[nt][0] * i0);
            o0[col + 1] = __float2half_rn(f0 ? vbar[col + 1] : pacc[nt][1] * i0);
            o1[col]     = __float2half_rn(f1 ? vbar[col]     : pacc[nt][2] * i1);
            o1[col + 1] = __float2half_rn(f1 ? vbar[col + 1] : pacc[nt][3] * i1);
        }
    }
}

// --------------------------------- launch --------------------------------
extern "C" void kernel_launch(void* const* d_in, const int* in_sizes, int n_in,
                              void* d_out, int out_size) {
    const float* x    = (const float*)d_in[0];
    const float* fcos = (const float*)d_in[1];
    const float* fsin = (const float*)d_in[2];
    const float* wq   = (const float*)d_in[3];
    const float* wk   = (const float*)d_in[4];
    const float* wv   = (const float*)d_in[5];
    const float* wo   = (const float*)d_in[6];
    float* out = (float*)d_out;

    float *q, *q64, *q64p, *kv, *probs, *vert, *dgp;
    int* keys;
    __half *xh, *xl, *atth, *wqt, *wot, *wkth, *wktl, *wvt;
    cudaGetSymbolAddress((void**)&q, g_q);
    cudaGetSymbolAddress((void**)&q64, g_q64);
    cudaGetSymbolAddress((void**)&q64p, g_q64p);
    cudaGetSymbolAddress((void**)&kv, g_kv);
    cudaGetSymbolAddress((void**)&probs, g_probs);
    cudaGetSymbolAddress((void**)&vert, g_vert);
    cudaGetSymbolAddress((void**)&dgp, g_diag);
    cudaGetSymbolAddress((void**)&keys, g_keys);
    cudaGetSymbolAddress((void**)&xh, g_xh);
    cudaGetSymbolAddress((void**)&xl, g_xl);
    cudaGetSymbolAddress((void**)&atth, g_atth);
    cudaGetSymbolAddress((void**)&wqt, g_wqt);
    cudaGetSymbolAddress((void**)&wot, g_wot);
    cudaGetSymbolAddress((void**)&wkth, g_wkt_h);
    cudaGetSymbolAddress((void**)&wktl, g_wkt_l);
    cudaGetSymbolAddress((void**)&wvt, g_wvt);

    // prep
    split_h2<<<(SEQ * DIM / 4 + 255) / 256, 256>>>(x, xh, xl, SEQ * DIM / 4);
    transp_split_g<<<dim3(512 / 32, DIM / 32), dim3(32, 8)>>>(wk, wkth, wktl, 512);
    transp_half_g<<<dim3(512 / 32, DIM / 32), dim3(32, 8)>>>(wv, wvt, 512);
    transp_half_g<<<dim3(DIM / 32, DIM / 32), dim3(32, 8)>>>(wq, wqt, DIM);
    transp_half_g<<<dim3(DIM / 32, DIM / 32), dim3(32, 8)>>>(wo, wot, DIM);

    // projections: q 1x fp16; k 3-term fp16; v 1x fp16
    gemm_f16<<<dim3(DIM / 128, SEQ / 128), 256>>>(xh, wqt, q, SEQ, DIM, DIM, DIM);
    {
        size_t smb = (size_t)(2 * STG2W) * 4;
        cudaFuncSetAttribute(gemm_f16x3, cudaFuncAttributeMaxDynamicSharedMemorySize,
                             (int)smb);
        gemm_f16x3<<<dim3(512 / 128, SEQ / 128), 256, smb>>>(
            xh, xl, wkth, wktl, kv, SEQ, 512, DIM, KVW);
    }
    gemm_f16<<<dim3(512 / 128, SEQ / 128), 256>>>(xh, wvt, kv + 512, SEQ, 512, DIM, KVW);

    // exact fp32 q rows 0..63
    qproj_part<<<dim3(16, 8, 8), 128>>>(x, wq, q64p);
    qproj_red<<<(ESTQ * DIM + 255) / 256, 256>>>(q64p, q64);

    // RoPE
    {
        int tq = SEQ * NH * 32;
        rope_kernel<<<(tq + 255) / 256, 256>>>(q, fcos, fsin, NH, DIM, tq);
        int tk = SEQ * NKV * 32;
        rope_kernel<<<(tk + 255) / 256, 256>>>(kv, fcos, fsin, NKV, KVW, tk);
        int tq64 = ESTQ * NH * 32;
        rope_kernel<<<(tq64 + 255) / 256, 256>>>(q64, fcos, fsin, NH, DIM, tq64);
    }

    // estimation
    est_score<<<dim3(SEQ / 64, NH), 256>>>(q64, kv, probs);
    est_norm<<<dim3(ESTQ, NH), 256>>>(probs);

    vertical_kernel<<<(NH * SEQ) / 256, 256>>>(probs, vert);
    diag_kernel<<<(NH * SEQ) / 256, 256>>>(probs, dgp);

    topk2_kernel<<<64, 512>>>(vert, dgp, keys);
    sortkeys_kernel<<<NH, 256>>>(keys);

    // sparse attention (direct kv gather)
    {
        size_t spbytes = (size_t)SPV_WORDS * 4;
        cudaFuncSetAttribute(spattn_kernel,
                             cudaFuncAttributeMaxDynamicSharedMemorySize, (int)spbytes);
        spattn_kernel<<<dim3(SEQ / 64, NH), 256, spbytes>>>(q, kv, keys, atth);
    }

    // output projection
    gemm_f16<<<dim3(DIM / 128, SEQ / 128), 256>>>(atth, wot, out, SEQ, DIM, DIM, DIM);
}